// round 1
// baseline (speedup 1.0000x reference)
#include <cuda_runtime.h>
#include <cuda_bf16.h>
#include <math.h>

// ---------------------------------------------------------------------------
// Problem constants
// ---------------------------------------------------------------------------
#define BB 4
#define SS 4096
#define DD 1024
#define HH 16
#define DH 64
#define FF 64
#define DFF 4096
#define NTOK (BB * SS)            // 16384 tokens
#define NROWS64 (NTOK * HH)       // 262144 rows of 64 (token-major, head-minor)

// ---------------------------------------------------------------------------
// Scratch (static device globals; allocation at module load, allowed)
// ---------------------------------------------------------------------------
__device__ float g_h[(size_t)NTOK * DD];        // LN1 out, later LN2 out
__device__ float g_q[(size_t)NTOK * DD];        // q -> qf -> attn (in place)
__device__ float g_k[(size_t)NTOK * DD];        // k -> kf (in place)
__device__ float g_v[(size_t)NTOK * DD];        // v
__device__ float g_kvp[8 * 64 * FF * DH];       // kv partials per chunk
__device__ float g_ksp[8 * 64 * FF];            // ksum partials per chunk
__device__ float g_kv[64 * FF * DH];            // [bh][f][d]
__device__ float g_ksum[64 * FF];               // [bh][f]
__device__ float g_ffn[(size_t)NTOK * DFF];     // gelu(h2@w1+b1)

// ---------------------------------------------------------------------------
// LayerNorm: one block (256 thr) per row of 1024
// ---------------------------------------------------------------------------
__global__ __launch_bounds__(256) void ln_kernel(const float* __restrict__ x,
                                                 const float* __restrict__ g,
                                                 const float* __restrict__ b,
                                                 float* __restrict__ out)
{
    int row = blockIdx.x;
    int t = threadIdx.x;
    const float4* xr = reinterpret_cast<const float4*>(x + (size_t)row * DD);
    float4 xv = xr[t];

    float s  = xv.x + xv.y + xv.z + xv.w;
    float s2 = xv.x*xv.x + xv.y*xv.y + xv.z*xv.z + xv.w*xv.w;

    __shared__ float red[2][8];
    #pragma unroll
    for (int off = 16; off > 0; off >>= 1) {
        s  += __shfl_xor_sync(0xffffffffu, s,  off);
        s2 += __shfl_xor_sync(0xffffffffu, s2, off);
    }
    int w = t >> 5, l = t & 31;
    if (l == 0) { red[0][w] = s; red[1][w] = s2; }
    __syncthreads();
    __shared__ float smu, srstd;
    if (t == 0) {
        float ts = 0.f, ts2 = 0.f;
        #pragma unroll
        for (int i = 0; i < 8; i++) { ts += red[0][i]; ts2 += red[1][i]; }
        float mu = ts * (1.0f / DD);
        float var = ts2 * (1.0f / DD) - mu * mu;
        smu = mu;
        srstd = rsqrtf(var + 1e-5f);
    }
    __syncthreads();
    float mu = smu, rstd = srstd;

    const float4 gv = reinterpret_cast<const float4*>(g)[t];
    const float4 bv = reinterpret_cast<const float4*>(b)[t];
    float4 ov;
    ov.x = (xv.x - mu) * rstd * gv.x + bv.x;
    ov.y = (xv.y - mu) * rstd * gv.y + bv.y;
    ov.z = (xv.z - mu) * rstd * gv.z + bv.z;
    ov.w = (xv.w - mu) * rstd * gv.w + bv.w;
    reinterpret_cast<float4*>(out + (size_t)row * DD)[t] = ov;
}

// ---------------------------------------------------------------------------
// SGEMM: C[M,N] = A[M,K] @ B[K,N] (+bias)(gelu)(+residual)
// BM=BN=128, BK=8, TM=TN=8, 256 threads. All dims multiples of tile sizes.
// ---------------------------------------------------------------------------
__global__ __launch_bounds__(256) void sgemm_kernel(
    const float* __restrict__ A, const float* __restrict__ B,
    float* __restrict__ C, int M, int N, int K,
    const float* __restrict__ bias,
    const float* __restrict__ residual,
    int act /*0 none, 1 gelu*/)
{
    const int BM = 128, BN = 128, BK = 8, TM = 8, TN = 8;
    __shared__ float As[BK][BM];
    __shared__ float Bs[BK][BN];

    int tid = threadIdx.x;
    int tx = tid & 15;        // 0..15  (col group)
    int ty = tid >> 4;        // 0..15  (row group)
    int row0 = blockIdx.y * BM;
    int col0 = blockIdx.x * BN;

    int a_r = tid >> 1;             // 0..127
    int a_c = (tid & 1) * 4;        // 0 or 4
    int b_r = tid >> 5;             // 0..7
    int b_c = (tid & 31) * 4;       // 0..124

    float acc[TM][TN];
    #pragma unroll
    for (int i = 0; i < TM; i++)
        #pragma unroll
        for (int j = 0; j < TN; j++) acc[i][j] = 0.f;

    const float* Aptr = A + (size_t)(row0 + a_r) * K + a_c;
    const float* Bptr = B + (size_t)b_r * N + col0 + b_c;

    for (int k0 = 0; k0 < K; k0 += BK) {
        float4 av = *reinterpret_cast<const float4*>(Aptr + k0);
        As[a_c + 0][a_r] = av.x;
        As[a_c + 1][a_r] = av.y;
        As[a_c + 2][a_r] = av.z;
        As[a_c + 3][a_r] = av.w;
        float4 bv = *reinterpret_cast<const float4*>(Bptr + (size_t)k0 * N);
        *reinterpret_cast<float4*>(&Bs[b_r][b_c]) = bv;
        __syncthreads();

        #pragma unroll
        for (int kk = 0; kk < BK; kk++) {
            float ra[TM], rb[TN];
            float4 a0 = *reinterpret_cast<const float4*>(&As[kk][ty * TM]);
            float4 a1 = *reinterpret_cast<const float4*>(&As[kk][ty * TM + 4]);
            ra[0]=a0.x; ra[1]=a0.y; ra[2]=a0.z; ra[3]=a0.w;
            ra[4]=a1.x; ra[5]=a1.y; ra[6]=a1.z; ra[7]=a1.w;
            float4 b0 = *reinterpret_cast<const float4*>(&Bs[kk][tx * TN]);
            float4 b1 = *reinterpret_cast<const float4*>(&Bs[kk][tx * TN + 4]);
            rb[0]=b0.x; rb[1]=b0.y; rb[2]=b0.z; rb[3]=b0.w;
            rb[4]=b1.x; rb[5]=b1.y; rb[6]=b1.z; rb[7]=b1.w;
            #pragma unroll
            for (int i = 0; i < TM; i++)
                #pragma unroll
                for (int j = 0; j < TN; j++)
                    acc[i][j] = fmaf(ra[i], rb[j], acc[i][j]);
        }
        __syncthreads();
    }

    #pragma unroll
    for (int i = 0; i < TM; i++) {
        int r = row0 + ty * TM + i;
        #pragma unroll
        for (int j = 0; j < TN; j++) {
            int c = col0 + tx * TN + j;
            float val = acc[i][j];
            if (bias) val += bias[c];
            if (act == 1) val = 0.5f * val * (1.0f + erff(val * 0.70710678118654752f));
            if (residual) val += residual[(size_t)r * N + c];
            C[(size_t)r * N + c] = val;
        }
    }
}

// ---------------------------------------------------------------------------
// Feature map (in place): row of 64 -> relu(row @ proj) + eps
// Rows are 64-float contiguous chunks; NROWS64 of them. 8 warps/block,
// 32 rows/warp -> 256 rows/block, 1024 blocks.
// ---------------------------------------------------------------------------
__global__ __launch_bounds__(256) void fmap_kernel(float* __restrict__ t,
                                                   const float* __restrict__ proj)
{
    __shared__ float projS[64 * 64];
    __shared__ float rowbuf[8][64];
    int tid = threadIdx.x, w = tid >> 5, l = tid & 31;
    for (int i = tid; i < 64 * 64; i += 256) projS[i] = proj[i];
    __syncthreads();

    size_t base_row = (size_t)blockIdx.x * 256 + (size_t)w * 32;
    for (int r = 0; r < 32; r++) {
        float* p = t + (base_row + r) * 64;
        rowbuf[w][l]      = p[l];
        rowbuf[w][l + 32] = p[l + 32];
        __syncwarp();
        float a0 = 0.f, a1 = 0.f;
        #pragma unroll
        for (int d = 0; d < 64; d++) {
            float rv = rowbuf[w][d];
            a0 = fmaf(rv, projS[d * 64 + l],      a0);
            a1 = fmaf(rv, projS[d * 64 + l + 32], a1);
        }
        __syncwarp();
        p[l]      = fmaxf(a0, 0.f) + 1e-6f;
        p[l + 32] = fmaxf(a1, 0.f) + 1e-6f;
    }
}

// ---------------------------------------------------------------------------
// kv partials: for (bh, chunk): kvp[chunk][bh][f][d] = sum_{n in chunk} kf*v
// plus ksum partials. grid (64, 8), block 256. Chunk = 512 tokens.
// ---------------------------------------------------------------------------
__global__ __launch_bounds__(256) void kv_kernel(const float* __restrict__ kf,
                                                 const float* __restrict__ vv,
                                                 float* __restrict__ kvp,
                                                 float* __restrict__ ksp)
{
    int bh = blockIdx.x;
    int b = bh >> 4, h = bh & 15;
    int chunk = blockIdx.y;

    __shared__ float ks[16][64];
    __shared__ float vs[16][64];
    int tid = threadIdx.x;
    int fq = tid >> 4, dq = tid & 15;
    int ln = tid >> 4, lc = (tid & 15) * 4;

    float acc[4][4];
    #pragma unroll
    for (int i = 0; i < 4; i++)
        #pragma unroll
        for (int j = 0; j < 4; j++) acc[i][j] = 0.f;
    float ksacc = 0.f;

    size_t base = (size_t)b * SS * DD + (size_t)h * 64;
    int nstart = chunk * 512;
    for (int n0 = nstart; n0 < nstart + 512; n0 += 16) {
        const float* kp = kf + base + (size_t)(n0 + ln) * DD + lc;
        const float* vp = vv + base + (size_t)(n0 + ln) * DD + lc;
        *reinterpret_cast<float4*>(&ks[ln][lc]) = *reinterpret_cast<const float4*>(kp);
        *reinterpret_cast<float4*>(&vs[ln][lc]) = *reinterpret_cast<const float4*>(vp);
        __syncthreads();
        #pragma unroll
        for (int nn = 0; nn < 16; nn++) {
            float rk[4], rv[4];
            #pragma unroll
            for (int i = 0; i < 4; i++) rk[i] = ks[nn][fq * 4 + i];
            #pragma unroll
            for (int j = 0; j < 4; j++) rv[j] = vs[nn][dq * 4 + j];
            #pragma unroll
            for (int i = 0; i < 4; i++)
                #pragma unroll
                for (int j = 0; j < 4; j++)
                    acc[i][j] = fmaf(rk[i], rv[j], acc[i][j]);
        }
        if (tid < 64) {
            #pragma unroll
            for (int nn = 0; nn < 16; nn++) ksacc += ks[nn][tid];
        }
        __syncthreads();
    }

    float* dst = kvp + (size_t)chunk * 64 * 4096 + (size_t)bh * 4096;
    #pragma unroll
    for (int i = 0; i < 4; i++)
        #pragma unroll
        for (int j = 0; j < 4; j++)
            dst[(fq * 4 + i) * 64 + dq * 4 + j] = acc[i][j];
    if (tid < 64)
        ksp[(size_t)chunk * 64 * 64 + bh * 64 + tid] = ksacc;
}

__global__ __launch_bounds__(256) void kv_reduce_kernel(const float* __restrict__ kvp,
                                                        const float* __restrict__ ksp,
                                                        float* __restrict__ kv,
                                                        float* __restrict__ ksum)
{
    int i = blockIdx.x * 256 + threadIdx.x;
    if (i < 64 * 4096) {
        float s = 0.f;
        #pragma unroll
        for (int c = 0; c < 8; c++) s += kvp[(size_t)c * 64 * 4096 + i];
        kv[i] = s;
    }
    if (i < 64 * 64) {
        float s = 0.f;
        #pragma unroll
        for (int c = 0; c < 8; c++) s += ksp[(size_t)c * 64 * 64 + i];
        ksum[i] = s;
    }
}

// ---------------------------------------------------------------------------
// attn (in place on qf): row -> (row @ kv[bh]) / (row . ksum[bh] + eps)
// grid (64 bh, 64), block 256. 64 rows/block (8 per warp).
// ---------------------------------------------------------------------------
__global__ __launch_bounds__(256) void attn_kernel(float* __restrict__ qf,
                                                   const float* __restrict__ kv,
                                                   const float* __restrict__ ksum)
{
    __shared__ float kvS[64 * 64];
    __shared__ float ks[64];
    __shared__ float rowbuf[8][64];

    int bh = blockIdx.x;
    int b = bh >> 4, h = bh & 15;
    int tid = threadIdx.x, w = tid >> 5, l = tid & 31;

    for (int i = tid; i < 64 * 64; i += 256) kvS[i] = kv[(size_t)bh * 4096 + i];
    if (tid < 64) ks[tid] = ksum[bh * 64 + tid];
    __syncthreads();

    size_t base = (size_t)b * SS * DD + (size_t)h * 64;
    int n0 = blockIdx.y * 64 + w * 8;
    for (int r = 0; r < 8; r++) {
        float* p = qf + base + (size_t)(n0 + r) * DD;
        rowbuf[w][l]      = p[l];
        rowbuf[w][l + 32] = p[l + 32];
        __syncwarp();
        float dsum = rowbuf[w][l] * ks[l] + rowbuf[w][l + 32] * ks[l + 32];
        #pragma unroll
        for (int off = 16; off > 0; off >>= 1)
            dsum += __shfl_xor_sync(0xffffffffu, dsum, off);
        float inv = 1.0f / (dsum + 1e-6f);
        float a0 = 0.f, a1 = 0.f;
        #pragma unroll
        for (int f = 0; f < 64; f++) {
            float qv = rowbuf[w][f];
            a0 = fmaf(qv, kvS[f * 64 + l],      a0);
            a1 = fmaf(qv, kvS[f * 64 + l + 32], a1);
        }
        __syncwarp();
        p[l]      = a0 * inv;
        p[l + 32] = a1 * inv;
    }
}

// ---------------------------------------------------------------------------
// Launch
// ---------------------------------------------------------------------------
extern "C" void kernel_launch(void* const* d_in, const int* in_sizes, int n_in,
                              void* d_out, int out_size)
{
    const float* x     = (const float*)d_in[0];
    const float* ln1_g = (const float*)d_in[1];
    const float* ln1_b = (const float*)d_in[2];
    const float* wq    = (const float*)d_in[3];
    const float* wk    = (const float*)d_in[4];
    const float* wv    = (const float*)d_in[5];
    const float* proj  = (const float*)d_in[6];
    const float* wo    = (const float*)d_in[7];
    const float* bo    = (const float*)d_in[8];
    const float* ln2_g = (const float*)d_in[9];
    const float* ln2_b = (const float*)d_in[10];
    const float* w1    = (const float*)d_in[11];
    const float* b1    = (const float*)d_in[12];
    const float* w2    = (const float*)d_in[13];
    const float* b2    = (const float*)d_in[14];
    float* out = (float*)d_out;

    float *h, *q, *k, *v, *kvp, *ksp, *kv, *ksum, *ffn;
    cudaGetSymbolAddress((void**)&h,    g_h);
    cudaGetSymbolAddress((void**)&q,    g_q);
    cudaGetSymbolAddress((void**)&k,    g_k);
    cudaGetSymbolAddress((void**)&v,    g_v);
    cudaGetSymbolAddress((void**)&kvp,  g_kvp);
    cudaGetSymbolAddress((void**)&ksp,  g_ksp);
    cudaGetSymbolAddress((void**)&kv,   g_kv);
    cudaGetSymbolAddress((void**)&ksum, g_ksum);
    cudaGetSymbolAddress((void**)&ffn,  g_ffn);

    // LN1
    ln_kernel<<<NTOK, 256>>>(x, ln1_g, ln1_b, h);

    // QKV GEMMs: [16384,1024] @ [1024,1024]
    dim3 g1024(DD / 128, NTOK / 128);
    sgemm_kernel<<<g1024, 256>>>(h, wq, q, NTOK, DD, DD, nullptr, nullptr, 0);
    sgemm_kernel<<<g1024, 256>>>(h, wk, k, NTOK, DD, DD, nullptr, nullptr, 0);
    sgemm_kernel<<<g1024, 256>>>(h, wv, v, NTOK, DD, DD, nullptr, nullptr, 0);

    // Feature maps in place on q, k
    fmap_kernel<<<NROWS64 / 256, 256>>>(q, proj);
    fmap_kernel<<<NROWS64 / 256, 256>>>(k, proj);

    // kv = sum_n k (x) v  per head, ksum = sum_n k (two-stage, deterministic)
    kv_kernel<<<dim3(64, 8), 256>>>(k, v, kvp, ksp);
    kv_reduce_kernel<<<(64 * 4096 + 255) / 256, 256>>>(kvp, ksp, kv, ksum);

    // attn in place on q (layout already [B,S,H*DH])
    attn_kernel<<<dim3(64, 64), 256>>>(q, kv, ksum);

    // x2 = x + attn @ wo + bo  -> d_out
    sgemm_kernel<<<g1024, 256>>>(q, wo, out, NTOK, DD, DD, bo, x, 0);

    // LN2
    ln_kernel<<<NTOK, 256>>>(out, ln2_g, ln2_b, h);

    // ffn = gelu(h2 @ w1 + b1)
    dim3 g4096(DFF / 128, NTOK / 128);
    sgemm_kernel<<<g4096, 256>>>(h, w1, ffn, NTOK, DFF, DD, b1, nullptr, 1);

    // out = x2 + ffn @ w2 + b2   (residual read from d_out in place)
    sgemm_kernel<<<g1024, 256>>>(ffn, w2, out, NTOK, DD, DFF, b2, out, 0);
}

// round 3
// speedup vs baseline: 2.3894x; 2.3894x over previous
#include <cuda_runtime.h>
#include <cuda_bf16.h>
#include <math.h>
#include <stdint.h>

// ---------------------------------------------------------------------------
// Problem constants
// ---------------------------------------------------------------------------
#define BB 4
#define SS 4096
#define DD 1024
#define HH 16
#define DH 64
#define FF 64
#define DFF 4096
#define NTOK (BB * SS)            // 16384 tokens
#define NROWS64 (NTOK * HH)       // 262144 rows of 64

// ---------------------------------------------------------------------------
// Scratch (static device globals)
// ---------------------------------------------------------------------------
__device__ float g_q[(size_t)NTOK * DD];
__device__ float g_k[(size_t)NTOK * DD];
__device__ float g_v[(size_t)NTOK * DD];
__device__ __nv_bfloat16 g_h_hi[(size_t)NTOK * DD];
__device__ __nv_bfloat16 g_h_lo[(size_t)NTOK * DD];
__device__ __nv_bfloat16 g_at_hi[(size_t)NTOK * DD];
__device__ __nv_bfloat16 g_at_lo[(size_t)NTOK * DD];
__device__ __nv_bfloat16 g_ffn_hi[(size_t)NTOK * DFF];
__device__ __nv_bfloat16 g_ffn_lo[(size_t)NTOK * DFF];
// Transposed+split weights: [N, K] bf16 hi/lo
__device__ __nv_bfloat16 g_wqT_hi[DD * DD], g_wqT_lo[DD * DD];
__device__ __nv_bfloat16 g_wkT_hi[DD * DD], g_wkT_lo[DD * DD];
__device__ __nv_bfloat16 g_wvT_hi[DD * DD], g_wvT_lo[DD * DD];
__device__ __nv_bfloat16 g_woT_hi[DD * DD], g_woT_lo[DD * DD];
__device__ __nv_bfloat16 g_w1T_hi[(size_t)DFF * DD], g_w1T_lo[(size_t)DFF * DD];
__device__ __nv_bfloat16 g_w2T_hi[(size_t)DD * DFF], g_w2T_lo[(size_t)DD * DFF];
// linear-attention small tensors
__device__ float g_kvp[8 * 64 * FF * DH];
__device__ float g_ksp[8 * 64 * FF];
__device__ float g_kv[64 * FF * DH];
__device__ float g_ksum[64 * FF];

// ---------------------------------------------------------------------------
// PTX helpers (baseline PTX only — no 'a'-suffix features)
// ---------------------------------------------------------------------------
__device__ __forceinline__ uint32_t smem_u32(const void* p) {
    uint32_t a;
    asm("{ .reg .u64 t; cvta.to.shared.u64 t, %1; cvt.u32.u64 %0, t; }"
        : "=r"(a) : "l"(p));
    return a;
}
__device__ __forceinline__ void cp_async16(uint32_t dst, const void* src) {
    asm volatile("cp.async.cg.shared.global [%0], [%1], 16;\n" :: "r"(dst), "l"(src));
}
__device__ __forceinline__ void cp_commit() {
    asm volatile("cp.async.commit_group;\n" ::: "memory");
}
template <int N>
__device__ __forceinline__ void cp_wait() {
    asm volatile("cp.async.wait_group %0;\n" :: "n"(N) : "memory");
}
__device__ __forceinline__ void ldsm4(uint32_t& r0, uint32_t& r1, uint32_t& r2,
                                      uint32_t& r3, uint32_t addr) {
    asm volatile("ldmatrix.sync.aligned.m8n8.x4.shared.b16 {%0,%1,%2,%3}, [%4];"
                 : "=r"(r0), "=r"(r1), "=r"(r2), "=r"(r3) : "r"(addr));
}
__device__ __forceinline__ void mma16816(float* c, const uint32_t* a,
                                         uint32_t b0, uint32_t b1) {
    asm volatile(
        "mma.sync.aligned.m16n8k16.row.col.f32.bf16.bf16.f32 "
        "{%0,%1,%2,%3}, {%4,%5,%6,%7}, {%8,%9}, {%0,%1,%2,%3};"
        : "+f"(c[0]), "+f"(c[1]), "+f"(c[2]), "+f"(c[3])
        : "r"(a[0]), "r"(a[1]), "r"(a[2]), "r"(a[3]), "r"(b0), "r"(b1));
}

// ---------------------------------------------------------------------------
// Weight transpose + bf16 hi/lo split:  W[K,N] -> Wt_hi/lo[N,K]
// ---------------------------------------------------------------------------
__global__ __launch_bounds__(256) void ts_kernel(const float* __restrict__ W,
                                                 __nv_bfloat16* __restrict__ hi,
                                                 __nv_bfloat16* __restrict__ lo,
                                                 int K, int N)
{
    __shared__ float t[32][33];
    int n0 = blockIdx.x * 32, k0 = blockIdx.y * 32;
    int tx = threadIdx.x & 31, ty = threadIdx.x >> 5;
    for (int r = ty; r < 32; r += 8)
        t[r][tx] = W[(size_t)(k0 + r) * N + n0 + tx];
    __syncthreads();
    for (int r = ty; r < 32; r += 8) {
        float v = t[tx][r];
        __nv_bfloat16 h = __float2bfloat16(v);
        hi[(size_t)(n0 + r) * K + k0 + tx] = h;
        lo[(size_t)(n0 + r) * K + k0 + tx] = __float2bfloat16(v - __bfloat162float(h));
    }
}

// ---------------------------------------------------------------------------
// split-store helper (2 consecutive elements)
// ---------------------------------------------------------------------------
__device__ __forceinline__ void split_store2(__nv_bfloat16* hi, __nv_bfloat16* lo,
                                             size_t idx, float a, float b)
{
    __nv_bfloat16 ha = __float2bfloat16(a);
    __nv_bfloat16 hb = __float2bfloat16(b);
    __nv_bfloat16 la = __float2bfloat16(a - __bfloat162float(ha));
    __nv_bfloat16 lb = __float2bfloat16(b - __bfloat162float(hb));
    *reinterpret_cast<__nv_bfloat162*>(hi + idx) = __halves2bfloat162(ha, hb);
    *reinterpret_cast<__nv_bfloat162*>(lo + idx) = __halves2bfloat162(la, lb);
}

// ---------------------------------------------------------------------------
// LayerNorm -> bf16 hi/lo. One block (256 thr) per row of 1024.
// ---------------------------------------------------------------------------
__global__ __launch_bounds__(256) void ln_kernel(const float* __restrict__ x,
                                                 const float* __restrict__ g,
                                                 const float* __restrict__ b,
                                                 __nv_bfloat16* __restrict__ ohi,
                                                 __nv_bfloat16* __restrict__ olo)
{
    int row = blockIdx.x;
    int t = threadIdx.x;
    const float4* xr = reinterpret_cast<const float4*>(x + (size_t)row * DD);
    float4 xv = xr[t];

    float s  = xv.x + xv.y + xv.z + xv.w;
    float s2 = xv.x*xv.x + xv.y*xv.y + xv.z*xv.z + xv.w*xv.w;

    __shared__ float red[2][8];
    #pragma unroll
    for (int off = 16; off > 0; off >>= 1) {
        s  += __shfl_xor_sync(0xffffffffu, s,  off);
        s2 += __shfl_xor_sync(0xffffffffu, s2, off);
    }
    int w = t >> 5, l = t & 31;
    if (l == 0) { red[0][w] = s; red[1][w] = s2; }
    __syncthreads();
    __shared__ float smu, srstd;
    if (t == 0) {
        float ts = 0.f, ts2 = 0.f;
        #pragma unroll
        for (int i = 0; i < 8; i++) { ts += red[0][i]; ts2 += red[1][i]; }
        float mu = ts * (1.0f / DD);
        float var = ts2 * (1.0f / DD) - mu * mu;
        smu = mu;
        srstd = rsqrtf(var + 1e-5f);
    }
    __syncthreads();
    float mu = smu, rstd = srstd;

    const float4 gv = reinterpret_cast<const float4*>(g)[t];
    const float4 bv = reinterpret_cast<const float4*>(b)[t];
    float o0 = (xv.x - mu) * rstd * gv.x + bv.x;
    float o1 = (xv.y - mu) * rstd * gv.y + bv.y;
    float o2 = (xv.z - mu) * rstd * gv.z + bv.z;
    float o3 = (xv.w - mu) * rstd * gv.w + bv.w;
    size_t idx = (size_t)row * DD + t * 4;
    split_store2(ohi, olo, idx,     o0, o1);
    split_store2(ohi, olo, idx + 2, o2, o3);
}

// ---------------------------------------------------------------------------
// HMMA GEMM: C[M,N] = Ahi@BhiT + Ahi@BloT + Alo@BhiT  (B given as [N,K])
// Tile 128x128, BK=32, 3-stage cp.async pipeline, mma.sync m16n8k16 bf16.
// mode 0: Cf = val
// mode 1: Cf = val + bias + residual
// mode 2: Chi/Clo = split(gelu(val + bias))
// ---------------------------------------------------------------------------
#define STAGE_BYTES 32768
#define GEMM_SMEM (3 * STAGE_BYTES)

// swizzled 16B-chunk offset within a 128x32 bf16 tile (64B rows)
__device__ __forceinline__ uint32_t tile_off(int row, int chunk) {
    int sw = chunk ^ (row & 3) ^ ((row >> 2) & 1);
    return (uint32_t)(row * 64 + (sw << 4));
}

__device__ __forceinline__ void load_stage(
    uint32_t st, const char* Ahi, const char* Alo, const char* Bhi, const char* Blo,
    int K, int row0, int col0, int kc, int tid)
{
    int row = tid >> 1;
    int jb = (tid & 1) * 2;
    size_t kb = (size_t)kc * 64;  // byte offset of 32-elem chunk within a row
    size_t ga = (size_t)(row0 + row) * K * 2 + kb;
    size_t gb = (size_t)(col0 + row) * K * 2 + kb;
    #pragma unroll
    for (int j = 0; j < 2; j++) {
        uint32_t so = tile_off(row, jb + j);
        cp_async16(st + so,                 Ahi + ga + (jb + j) * 16);
        cp_async16(st + 8192 + so,          Alo + ga + (jb + j) * 16);
        cp_async16(st + 16384 + so,         Bhi + gb + (jb + j) * 16);
        cp_async16(st + 24576 + so,         Blo + gb + (jb + j) * 16);
    }
}

__global__ __launch_bounds__(256, 1) void mma_gemm_kernel(
    const __nv_bfloat16* __restrict__ Ahi, const __nv_bfloat16* __restrict__ Alo,
    const __nv_bfloat16* __restrict__ Bhi, const __nv_bfloat16* __restrict__ Blo,
    int M, int N, int K,
    float* __restrict__ Cf, const float* __restrict__ bias,
    const float* __restrict__ residual,
    __nv_bfloat16* __restrict__ Chi, __nv_bfloat16* __restrict__ Clo, int mode)
{
    extern __shared__ char smem[];
    uint32_t sbase = smem_u32(smem);

    int tid = threadIdx.x;
    int wid = tid >> 5, l = tid & 31;
    int wr = wid >> 2, wc = wid & 3;   // 2x4 warp grid: 64x32 per warp
    int row0 = blockIdx.y * 128;
    int col0 = blockIdx.x * 128;
    int CH = K >> 5;

    const char* pAhi = (const char*)Ahi;
    const char* pAlo = (const char*)Alo;
    const char* pBhi = (const char*)Bhi;
    const char* pBlo = (const char*)Blo;

    float acc[4][4][4];
    #pragma unroll
    for (int i = 0; i < 4; i++)
        #pragma unroll
        for (int j = 0; j < 4; j++)
            #pragma unroll
            for (int t = 0; t < 4; t++) acc[i][j][t] = 0.f;

    // per-lane ldmatrix geometry
    int aRow = wr * 64 + (l & 15);
    int aHalf = (l >> 4) & 1;
    int bRowL = (l & 7) + ((l >> 4) & 1) * 8;   // row within 16-row pair block
    int bHalf = (l >> 3) & 1;

    // prologue: chunks 0,1
    load_stage(sbase, pAhi, pAlo, pBhi, pBlo, K, row0, col0, 0, tid);
    cp_commit();
    load_stage(sbase + STAGE_BYTES, pAhi, pAlo, pBhi, pBlo, K, row0, col0, 1, tid);
    cp_commit();

    for (int c = 0; c < CH; c++) {
        if (c == CH - 1) cp_wait<0>(); else cp_wait<1>();
        __syncthreads();
        if (c + 2 < CH) {
            load_stage(sbase + ((c + 2) % 3) * STAGE_BYTES,
                       pAhi, pAlo, pBhi, pBlo, K, row0, col0, c + 2, tid);
            cp_commit();
        }
        uint32_t st = sbase + (c % 3) * STAGE_BYTES;
        #pragma unroll
        for (int ks = 0; ks < 2; ks++) {
            uint32_t ahi[4][4], alo[4][4];
            #pragma unroll
            for (int mt = 0; mt < 4; mt++) {
                uint32_t off = tile_off(aRow + mt * 16, ks * 2 + aHalf);
                ldsm4(ahi[mt][0], ahi[mt][1], ahi[mt][2], ahi[mt][3], st + off);
                ldsm4(alo[mt][0], alo[mt][1], alo[mt][2], alo[mt][3], st + 8192 + off);
            }
            uint32_t bhi[4][2], blo[4][2];
            #pragma unroll
            for (int p = 0; p < 2; p++) {
                uint32_t off = tile_off(wc * 32 + p * 16 + bRowL, ks * 2 + bHalf);
                ldsm4(bhi[2*p][0], bhi[2*p][1], bhi[2*p+1][0], bhi[2*p+1][1],
                      st + 16384 + off);
                ldsm4(blo[2*p][0], blo[2*p][1], blo[2*p+1][0], blo[2*p+1][1],
                      st + 24576 + off);
            }
            #pragma unroll
            for (int mt = 0; mt < 4; mt++)
                #pragma unroll
                for (int nt = 0; nt < 4; nt++) {
                    mma16816(acc[mt][nt], ahi[mt], bhi[nt][0], bhi[nt][1]);
                    mma16816(acc[mt][nt], ahi[mt], blo[nt][0], blo[nt][1]);
                    mma16816(acc[mt][nt], alo[mt], bhi[nt][0], bhi[nt][1]);
                }
        }
    }

    // epilogue
    int rb = row0 + wr * 64 + (l >> 2);
    int cb = col0 + wc * 32 + (l & 3) * 2;
    #pragma unroll
    for (int mt = 0; mt < 4; mt++) {
        #pragma unroll
        for (int half = 0; half < 2; half++) {
            int r = rb + mt * 16 + half * 8;
            #pragma unroll
            for (int nt = 0; nt < 4; nt++) {
                int ccol = cb + nt * 8;
                float v0 = acc[mt][nt][half * 2];
                float v1 = acc[mt][nt][half * 2 + 1];
                if (mode == 2) {
                    v0 += bias[ccol];
                    v1 += bias[ccol + 1];
                    v0 = 0.5f * v0 * (1.0f + erff(v0 * 0.70710678118654752f));
                    v1 = 0.5f * v1 * (1.0f + erff(v1 * 0.70710678118654752f));
                    split_store2(Chi, Clo, (size_t)r * N + ccol, v0, v1);
                } else {
                    if (mode == 1) {
                        v0 += bias[ccol];
                        v1 += bias[ccol + 1];
                        const float2 rr = *reinterpret_cast<const float2*>(
                            residual + (size_t)r * N + ccol);
                        v0 += rr.x; v1 += rr.y;
                    }
                    float2 o; o.x = v0; o.y = v1;
                    *reinterpret_cast<float2*>(Cf + (size_t)r * N + ccol) = o;
                }
            }
        }
    }
}

// ---------------------------------------------------------------------------
// Feature map (in place, fp32): row of 64 -> relu(row @ proj) + eps
// ---------------------------------------------------------------------------
__global__ __launch_bounds__(256) void fmap_kernel(float* __restrict__ t,
                                                   const float* __restrict__ proj)
{
    __shared__ float projS[64 * 64];
    __shared__ float rowbuf[8][64];
    int tid = threadIdx.x, w = tid >> 5, l = tid & 31;
    for (int i = tid; i < 64 * 64; i += 256) projS[i] = proj[i];
    __syncthreads();

    size_t base_row = (size_t)blockIdx.x * 256 + (size_t)w * 32;
    for (int r = 0; r < 32; r++) {
        float* p = t + (base_row + r) * 64;
        rowbuf[w][l]      = p[l];
        rowbuf[w][l + 32] = p[l + 32];
        __syncwarp();
        float a0 = 0.f, a1 = 0.f;
        #pragma unroll
        for (int d = 0; d < 64; d++) {
            float rv = rowbuf[w][d];
            a0 = fmaf(rv, projS[d * 64 + l],      a0);
            a1 = fmaf(rv, projS[d * 64 + l + 32], a1);
        }
        __syncwarp();
        p[l]      = fmaxf(a0, 0.f) + 1e-6f;
        p[l + 32] = fmaxf(a1, 0.f) + 1e-6f;
    }
}

// ---------------------------------------------------------------------------
// kv partials + reduce
// ---------------------------------------------------------------------------
__global__ __launch_bounds__(256) void kv_kernel(const float* __restrict__ kf,
                                                 const float* __restrict__ vv,
                                                 float* __restrict__ kvp,
                                                 float* __restrict__ ksp)
{
    int bh = blockIdx.x;
    int b = bh >> 4, h = bh & 15;
    int chunk = blockIdx.y;

    __shared__ float ks[16][64];
    __shared__ float vs[16][64];
    int tid = threadIdx.x;
    int fq = tid >> 4, dq = tid & 15;
    int ln = tid >> 4, lc = (tid & 15) * 4;

    float acc[4][4];
    #pragma unroll
    for (int i = 0; i < 4; i++)
        #pragma unroll
        for (int j = 0; j < 4; j++) acc[i][j] = 0.f;
    float ksacc = 0.f;

    size_t base = (size_t)b * SS * DD + (size_t)h * 64;
    int nstart = chunk * 512;
    for (int n0 = nstart; n0 < nstart + 512; n0 += 16) {
        const float* kp = kf + base + (size_t)(n0 + ln) * DD + lc;
        const float* vp = vv + base + (size_t)(n0 + ln) * DD + lc;
        *reinterpret_cast<float4*>(&ks[ln][lc]) = *reinterpret_cast<const float4*>(kp);
        *reinterpret_cast<float4*>(&vs[ln][lc]) = *reinterpret_cast<const float4*>(vp);
        __syncthreads();
        #pragma unroll
        for (int nn = 0; nn < 16; nn++) {
            float rk[4], rv[4];
            #pragma unroll
            for (int i = 0; i < 4; i++) rk[i] = ks[nn][fq * 4 + i];
            #pragma unroll
            for (int j = 0; j < 4; j++) rv[j] = vs[nn][dq * 4 + j];
            #pragma unroll
            for (int i = 0; i < 4; i++)
                #pragma unroll
                for (int j = 0; j < 4; j++)
                    acc[i][j] = fmaf(rk[i], rv[j], acc[i][j]);
        }
        if (tid < 64) {
            #pragma unroll
            for (int nn = 0; nn < 16; nn++) ksacc += ks[nn][tid];
        }
        __syncthreads();
    }

    float* dst = kvp + (size_t)chunk * 64 * 4096 + (size_t)bh * 4096;
    #pragma unroll
    for (int i = 0; i < 4; i++)
        #pragma unroll
        for (int j = 0; j < 4; j++)
            dst[(fq * 4 + i) * 64 + dq * 4 + j] = acc[i][j];
    if (tid < 64)
        ksp[(size_t)chunk * 64 * 64 + bh * 64 + tid] = ksacc;
}

__global__ __launch_bounds__(256) void kv_reduce_kernel(const float* __restrict__ kvp,
                                                        const float* __restrict__ ksp,
                                                        float* __restrict__ kv,
                                                        float* __restrict__ ksum)
{
    int i = blockIdx.x * 256 + threadIdx.x;
    if (i < 64 * 4096) {
        float s = 0.f;
        #pragma unroll
        for (int c = 0; c < 8; c++) s += kvp[(size_t)c * 64 * 4096 + i];
        kv[i] = s;
    }
    if (i < 64 * 64) {
        float s = 0.f;
        #pragma unroll
        for (int c = 0; c < 8; c++) s += ksp[(size_t)c * 64 * 64 + i];
        ksum[i] = s;
    }
}

// ---------------------------------------------------------------------------
// attn: row -> (row @ kv[bh]) / (row . ksum[bh] + eps), written as bf16 hi/lo
// ---------------------------------------------------------------------------
__global__ __launch_bounds__(256) void attn_kernel(const float* __restrict__ qf,
                                                   const float* __restrict__ kv,
                                                   const float* __restrict__ ksum,
                                                   __nv_bfloat16* __restrict__ ohi,
                                                   __nv_bfloat16* __restrict__ olo)
{
    __shared__ float kvS[64 * 64];
    __shared__ float ks[64];
    __shared__ float rowbuf[8][64];

    int bh = blockIdx.x;
    int b = bh >> 4, h = bh & 15;
    int tid = threadIdx.x, w = tid >> 5, l = tid & 31;

    for (int i = tid; i < 64 * 64; i += 256) kvS[i] = kv[(size_t)bh * 4096 + i];
    if (tid < 64) ks[tid] = ksum[bh * 64 + tid];
    __syncthreads();

    size_t base = (size_t)b * SS * DD + (size_t)h * 64;
    int n0 = blockIdx.y * 64 + w * 8;
    for (int r = 0; r < 8; r++) {
        const float* p = qf + base + (size_t)(n0 + r) * DD;
        rowbuf[w][l]      = p[l];
        rowbuf[w][l + 32] = p[l + 32];
        __syncwarp();
        float dsum = rowbuf[w][l] * ks[l] + rowbuf[w][l + 32] * ks[l + 32];
        #pragma unroll
        for (int off = 16; off > 0; off >>= 1)
            dsum += __shfl_xor_sync(0xffffffffu, dsum, off);
        float inv = 1.0f / (dsum + 1e-6f);
        float a0 = 0.f, a1 = 0.f;
        #pragma unroll
        for (int f = 0; f < 64; f++) {
            float qv = rowbuf[w][f];
            a0 = fmaf(qv, kvS[f * 64 + l],      a0);
            a1 = fmaf(qv, kvS[f * 64 + l + 32], a1);
        }
        __syncwarp();
        a0 *= inv; a1 *= inv;
        size_t i0 = base + (size_t)(n0 + r) * DD;
        __nv_bfloat16 h0 = __float2bfloat16(a0);
        __nv_bfloat16 h1 = __float2bfloat16(a1);
        ohi[i0 + l]      = h0;
        ohi[i0 + l + 32] = h1;
        olo[i0 + l]      = __float2bfloat16(a0 - __bfloat162float(h0));
        olo[i0 + l + 32] = __float2bfloat16(a1 - __bfloat162float(h1));
    }
}

// ---------------------------------------------------------------------------
// Launch
// ---------------------------------------------------------------------------
extern "C" void kernel_launch(void* const* d_in, const int* in_sizes, int n_in,
                              void* d_out, int out_size)
{
    const float* x     = (const float*)d_in[0];
    const float* ln1_g = (const float*)d_in[1];
    const float* ln1_b = (const float*)d_in[2];
    const float* wq    = (const float*)d_in[3];
    const float* wk    = (const float*)d_in[4];
    const float* wv    = (const float*)d_in[5];
    const float* proj  = (const float*)d_in[6];
    const float* wo    = (const float*)d_in[7];
    const float* bo    = (const float*)d_in[8];
    const float* ln2_g = (const float*)d_in[9];
    const float* ln2_b = (const float*)d_in[10];
    const float* w1    = (const float*)d_in[11];
    const float* b1    = (const float*)d_in[12];
    const float* w2    = (const float*)d_in[13];
    const float* b2    = (const float*)d_in[14];
    float* out = (float*)d_out;

    float *q, *k, *v, *kvp, *ksp, *kv, *ksum;
    __nv_bfloat16 *h_hi, *h_lo, *at_hi, *at_lo, *ffn_hi, *ffn_lo;
    __nv_bfloat16 *wqT_hi, *wqT_lo, *wkT_hi, *wkT_lo, *wvT_hi, *wvT_lo;
    __nv_bfloat16 *woT_hi, *woT_lo, *w1T_hi, *w1T_lo, *w2T_hi, *w2T_lo;
    cudaGetSymbolAddress((void**)&q, g_q);
    cudaGetSymbolAddress((void**)&k, g_k);
    cudaGetSymbolAddress((void**)&v, g_v);
    cudaGetSymbolAddress((void**)&kvp, g_kvp);
    cudaGetSymbolAddress((void**)&ksp, g_ksp);
    cudaGetSymbolAddress((void**)&kv, g_kv);
    cudaGetSymbolAddress((void**)&ksum, g_ksum);
    cudaGetSymbolAddress((void**)&h_hi, g_h_hi);
    cudaGetSymbolAddress((void**)&h_lo, g_h_lo);
    cudaGetSymbolAddress((void**)&at_hi, g_at_hi);
    cudaGetSymbolAddress((void**)&at_lo, g_at_lo);
    cudaGetSymbolAddress((void**)&ffn_hi, g_ffn_hi);
    cudaGetSymbolAddress((void**)&ffn_lo, g_ffn_lo);
    cudaGetSymbolAddress((void**)&wqT_hi, g_wqT_hi);
    cudaGetSymbolAddress((void**)&wqT_lo, g_wqT_lo);
    cudaGetSymbolAddress((void**)&wkT_hi, g_wkT_hi);
    cudaGetSymbolAddress((void**)&wkT_lo, g_wkT_lo);
    cudaGetSymbolAddress((void**)&wvT_hi, g_wvT_hi);
    cudaGetSymbolAddress((void**)&wvT_lo, g_wvT_lo);
    cudaGetSymbolAddress((void**)&woT_hi, g_woT_hi);
    cudaGetSymbolAddress((void**)&woT_lo, g_woT_lo);
    cudaGetSymbolAddress((void**)&w1T_hi, g_w1T_hi);
    cudaGetSymbolAddress((void**)&w1T_lo, g_w1T_lo);
    cudaGetSymbolAddress((void**)&w2T_hi, g_w2T_hi);
    cudaGetSymbolAddress((void**)&w2T_lo, g_w2T_lo);

    cudaFuncSetAttribute(mma_gemm_kernel,
                         cudaFuncAttributeMaxDynamicSharedMemorySize, GEMM_SMEM);

    // Weight prep: transpose + split
    ts_kernel<<<dim3(DD / 32, DD / 32), 256>>>(wq, wqT_hi, wqT_lo, DD, DD);
    ts_kernel<<<dim3(DD / 32, DD / 32), 256>>>(wk, wkT_hi, wkT_lo, DD, DD);
    ts_kernel<<<dim3(DD / 32, DD / 32), 256>>>(wv, wvT_hi, wvT_lo, DD, DD);
    ts_kernel<<<dim3(DD / 32, DD / 32), 256>>>(wo, woT_hi, woT_lo, DD, DD);
    ts_kernel<<<dim3(DFF / 32, DD / 32), 256>>>(w1, w1T_hi, w1T_lo, DD, DFF);
    ts_kernel<<<dim3(DD / 32, DFF / 32), 256>>>(w2, w2T_hi, w2T_lo, DFF, DD);

    // LN1 -> h (bf16 hi/lo)
    ln_kernel<<<NTOK, 256>>>(x, ln1_g, ln1_b, h_hi, h_lo);

    // QKV GEMMs (fp32 out)
    dim3 gQ(DD / 128, NTOK / 128);
    mma_gemm_kernel<<<gQ, 256, GEMM_SMEM>>>(h_hi, h_lo, wqT_hi, wqT_lo,
        NTOK, DD, DD, q, nullptr, nullptr, nullptr, nullptr, 0);
    mma_gemm_kernel<<<gQ, 256, GEMM_SMEM>>>(h_hi, h_lo, wkT_hi, wkT_lo,
        NTOK, DD, DD, k, nullptr, nullptr, nullptr, nullptr, 0);
    mma_gemm_kernel<<<gQ, 256, GEMM_SMEM>>>(h_hi, h_lo, wvT_hi, wvT_lo,
        NTOK, DD, DD, v, nullptr, nullptr, nullptr, nullptr, 0);

    // feature maps (in place, fp32)
    fmap_kernel<<<NROWS64 / 256, 256>>>(q, proj);
    fmap_kernel<<<NROWS64 / 256, 256>>>(k, proj);

    // kv / ksum
    kv_kernel<<<dim3(64, 8), 256>>>(k, v, kvp, ksp);
    kv_reduce_kernel<<<(64 * 4096 + 255) / 256, 256>>>(kvp, ksp, kv, ksum);

    // attn -> bf16 hi/lo
    attn_kernel<<<dim3(64, 64), 256>>>(q, kv, ksum, at_hi, at_lo);

    // x2 = x + attn @ wo + bo -> out (fp32)
    mma_gemm_kernel<<<gQ, 256, GEMM_SMEM>>>(at_hi, at_lo, woT_hi, woT_lo,
        NTOK, DD, DD, out, bo, x, nullptr, nullptr, 1);

    // LN2 -> h (bf16 hi/lo)
    ln_kernel<<<NTOK, 256>>>(out, ln2_g, ln2_b, h_hi, h_lo);

    // ffn = gelu(h2 @ w1 + b1) -> bf16 hi/lo
    dim3 gF1(DFF / 128, NTOK / 128);
    mma_gemm_kernel<<<gF1, 256, GEMM_SMEM>>>(h_hi, h_lo, w1T_hi, w1T_lo,
        NTOK, DFF, DD, nullptr, b1, nullptr, ffn_hi, ffn_lo, 2);

    // out = x2 + ffn @ w2 + b2 (in-place residual)
    mma_gemm_kernel<<<gQ, 256, GEMM_SMEM>>>(ffn_hi, ffn_lo, w2T_hi, w2T_lo,
        NTOK, DD, DFF, out, b2, out, nullptr, nullptr, 1);
}

// round 4
// speedup vs baseline: 2.9613x; 1.2393x over previous
#include <cuda_runtime.h>
#include <cuda_bf16.h>
#include <math.h>
#include <stdint.h>

// ---------------------------------------------------------------------------
// Problem constants
// ---------------------------------------------------------------------------
#define BB 4
#define SS 4096
#define DD 1024
#define HH 16
#define DH 64
#define FF 64
#define DFF 4096
#define NTOK (BB * SS)            // 16384 tokens

// ---------------------------------------------------------------------------
// Scratch (static device globals)
// ---------------------------------------------------------------------------
__device__ float g_q[(size_t)NTOK * DD];   // also reused as fp32 temp for folded weights
__device__ float g_k[(size_t)NTOK * DD];
__device__ float g_v[(size_t)NTOK * DD];
__device__ __nv_bfloat16 g_h_hi[(size_t)NTOK * DD];
__device__ __nv_bfloat16 g_h_lo[(size_t)NTOK * DD];
__device__ __nv_bfloat16 g_at_hi[(size_t)NTOK * DD];
__device__ __nv_bfloat16 g_at_lo[(size_t)NTOK * DD];
__device__ __nv_bfloat16 g_ffn_hi[(size_t)NTOK * DFF];
__device__ __nv_bfloat16 g_ffn_lo[(size_t)NTOK * DFF];
// Transposed+split weights, [N, K] bf16 hi/lo
__device__ __nv_bfloat16 g_wqkvT_hi[3 * DD * DD], g_wqkvT_lo[3 * DD * DD]; // folded q,k + v
__device__ __nv_bfloat16 g_woT_hi[DD * DD], g_woT_lo[DD * DD];
__device__ __nv_bfloat16 g_w1T_hi[(size_t)DFF * DD], g_w1T_lo[(size_t)DFF * DD];
__device__ __nv_bfloat16 g_w2T_hi[(size_t)DD * DFF], g_w2T_lo[(size_t)DD * DFF];
// linear-attention small tensors
__device__ float g_kvp[8 * 64 * FF * DH];
__device__ float g_ksp[8 * 64 * FF];
__device__ float g_kv[64 * FF * DH];
__device__ float g_ksum[64 * FF];

// ---------------------------------------------------------------------------
// PTX helpers (baseline PTX only — no 'a'-suffix features)
// ---------------------------------------------------------------------------
__device__ __forceinline__ uint32_t smem_u32(const void* p) {
    uint32_t a;
    asm("{ .reg .u64 t; cvta.to.shared.u64 t, %1; cvt.u32.u64 %0, t; }"
        : "=r"(a) : "l"(p));
    return a;
}
__device__ __forceinline__ void cp_async16(uint32_t dst, const void* src) {
    asm volatile("cp.async.cg.shared.global [%0], [%1], 16;\n" :: "r"(dst), "l"(src));
}
__device__ __forceinline__ void cp_commit() {
    asm volatile("cp.async.commit_group;\n" ::: "memory");
}
template <int N>
__device__ __forceinline__ void cp_wait() {
    asm volatile("cp.async.wait_group %0;\n" :: "n"(N) : "memory");
}
__device__ __forceinline__ void ldsm4(uint32_t& r0, uint32_t& r1, uint32_t& r2,
                                      uint32_t& r3, uint32_t addr) {
    asm volatile("ldmatrix.sync.aligned.m8n8.x4.shared.b16 {%0,%1,%2,%3}, [%4];"
                 : "=r"(r0), "=r"(r1), "=r"(r2), "=r"(r3) : "r"(addr));
}
__device__ __forceinline__ void mma16816(float* c, const uint32_t* a,
                                         uint32_t b0, uint32_t b1) {
    asm volatile(
        "mma.sync.aligned.m16n8k16.row.col.f32.bf16.bf16.f32 "
        "{%0,%1,%2,%3}, {%4,%5,%6,%7}, {%8,%9}, {%0,%1,%2,%3};"
        : "+f"(c[0]), "+f"(c[1]), "+f"(c[2]), "+f"(c[3])
        : "r"(a[0]), "r"(a[1]), "r"(a[2]), "r"(a[3]), "r"(b0), "r"(b1));
}

// ---------------------------------------------------------------------------
// Fold proj into a QK weight: out[d, h*64+f] = sum_dh W[d, h*64+dh]*proj[dh,f]
// grid (D/64, H), block 256
// ---------------------------------------------------------------------------
__global__ __launch_bounds__(256) void fold_kernel(const float* __restrict__ W,
                                                   const float* __restrict__ proj,
                                                   float* __restrict__ outW)
{
    __shared__ float projS[64][64];
    __shared__ float wS[64][65];
    int d0 = blockIdx.x * 64, h = blockIdx.y;
    int tid = threadIdx.x;
    for (int i = tid; i < 64 * 64; i += 256)
        projS[i >> 6][i & 63] = proj[i];
    for (int i = tid; i < 64 * 64; i += 256)
        wS[i >> 6][i & 63] = W[(size_t)(d0 + (i >> 6)) * (HH * DH) + h * 64 + (i & 63)];
    __syncthreads();
    int r = tid >> 2;
    int fb = (tid & 3) * 16;
    float acc[16];
    #pragma unroll
    for (int i = 0; i < 16; i++) acc[i] = 0.f;
    #pragma unroll 8
    for (int c = 0; c < 64; c++) {
        float w = wS[r][c];
        #pragma unroll
        for (int i = 0; i < 16; i++)
            acc[i] = fmaf(w, projS[c][fb + i], acc[i]);
    }
    for (int i = 0; i < 16; i++)
        outW[(size_t)(d0 + r) * (HH * FF) + h * 64 + fb + i] = acc[i];
}

// ---------------------------------------------------------------------------
// Weight transpose + bf16 hi/lo split:  W[K,N] -> Wt_hi/lo[N,K]
// ---------------------------------------------------------------------------
__global__ __launch_bounds__(256) void ts_kernel(const float* __restrict__ W,
                                                 __nv_bfloat16* __restrict__ hi,
                                                 __nv_bfloat16* __restrict__ lo,
                                                 int K, int N)
{
    __shared__ float t[32][33];
    int n0 = blockIdx.x * 32, k0 = blockIdx.y * 32;
    int tx = threadIdx.x & 31, ty = threadIdx.x >> 5;
    for (int r = ty; r < 32; r += 8)
        t[r][tx] = W[(size_t)(k0 + r) * N + n0 + tx];
    __syncthreads();
    for (int r = ty; r < 32; r += 8) {
        float v = t[tx][r];
        __nv_bfloat16 h = __float2bfloat16(v);
        hi[(size_t)(n0 + r) * K + k0 + tx] = h;
        lo[(size_t)(n0 + r) * K + k0 + tx] = __float2bfloat16(v - __bfloat162float(h));
    }
}

// ---------------------------------------------------------------------------
// split-store helper (2 consecutive elements)
// ---------------------------------------------------------------------------
__device__ __forceinline__ void split_store2(__nv_bfloat16* hi, __nv_bfloat16* lo,
                                             size_t idx, float a, float b)
{
    __nv_bfloat16 ha = __float2bfloat16(a);
    __nv_bfloat16 hb = __float2bfloat16(b);
    __nv_bfloat16 la = __float2bfloat16(a - __bfloat162float(ha));
    __nv_bfloat16 lb = __float2bfloat16(b - __bfloat162float(hb));
    *reinterpret_cast<__nv_bfloat162*>(hi + idx) = __halves2bfloat162(ha, hb);
    *reinterpret_cast<__nv_bfloat162*>(lo + idx) = __halves2bfloat162(la, lb);
}

// ---------------------------------------------------------------------------
// LayerNorm -> bf16 hi/lo. One block (256 thr) per row of 1024.
// ---------------------------------------------------------------------------
__global__ __launch_bounds__(256) void ln_kernel(const float* __restrict__ x,
                                                 const float* __restrict__ g,
                                                 const float* __restrict__ b,
                                                 __nv_bfloat16* __restrict__ ohi,
                                                 __nv_bfloat16* __restrict__ olo)
{
    int row = blockIdx.x;
    int t = threadIdx.x;
    const float4* xr = reinterpret_cast<const float4*>(x + (size_t)row * DD);
    float4 xv = xr[t];

    float s  = xv.x + xv.y + xv.z + xv.w;
    float s2 = xv.x*xv.x + xv.y*xv.y + xv.z*xv.z + xv.w*xv.w;

    __shared__ float red[2][8];
    #pragma unroll
    for (int off = 16; off > 0; off >>= 1) {
        s  += __shfl_xor_sync(0xffffffffu, s,  off);
        s2 += __shfl_xor_sync(0xffffffffu, s2, off);
    }
    int w = t >> 5, l = t & 31;
    if (l == 0) { red[0][w] = s; red[1][w] = s2; }
    __syncthreads();
    __shared__ float smu, srstd;
    if (t == 0) {
        float ts = 0.f, ts2 = 0.f;
        #pragma unroll
        for (int i = 0; i < 8; i++) { ts += red[0][i]; ts2 += red[1][i]; }
        float mu = ts * (1.0f / DD);
        float var = ts2 * (1.0f / DD) - mu * mu;
        smu = mu;
        srstd = rsqrtf(var + 1e-5f);
    }
    __syncthreads();
    float mu = smu, rstd = srstd;

    const float4 gv = reinterpret_cast<const float4*>(g)[t];
    const float4 bv = reinterpret_cast<const float4*>(b)[t];
    float o0 = (xv.x - mu) * rstd * gv.x + bv.x;
    float o1 = (xv.y - mu) * rstd * gv.y + bv.y;
    float o2 = (xv.z - mu) * rstd * gv.z + bv.z;
    float o3 = (xv.w - mu) * rstd * gv.w + bv.w;
    size_t idx = (size_t)row * DD + t * 4;
    split_store2(ohi, olo, idx,     o0, o1);
    split_store2(ohi, olo, idx + 2, o2, o3);
}

// ---------------------------------------------------------------------------
// HMMA GEMM: C[M,N] = Ahi@BhiT + Ahi@BloT + Alo@BhiT  (B given as [N,K])
// Tile 128x256, BK=32, 3-stage cp.async pipeline, warp tile 64x64.
// mode 0: Cf = val
// mode 1: Cf = val + bias + residual
// mode 2: Chi/Clo = split(gelu(val + bias))
// mode 3: fused qkv: seg 0 -> relu+eps -> Cf(q), seg 1 -> relu+eps -> kOut,
//                    seg 2 -> plain -> vOut  (out stride 1024)
// ---------------------------------------------------------------------------
#define STAGE_BYTES 49152
#define GEMM_SMEM (3 * STAGE_BYTES)

// swizzled 16B-chunk offset within an Rx32 bf16 tile (64B rows)
__device__ __forceinline__ uint32_t tile_off(int row, int chunk) {
    int sw = chunk ^ (row & 3) ^ ((row >> 2) & 1);
    return (uint32_t)(row * 64 + (sw << 4));
}

__device__ __forceinline__ void load_stage(
    uint32_t st, const char* Ahi, const char* Alo, const char* Bhi, const char* Blo,
    int K, int row0, int col0, int kc, int tid)
{
    size_t kb = (size_t)kc * 64;  // byte offset of 32-elem chunk within a row
    // A: 128 rows x 4 chunks, hi+lo
    #pragma unroll
    for (int i = 0; i < 2; i++) {
        int id = tid + 256 * i;
        int row = id >> 2, ch = id & 3;
        size_t ga = (size_t)(row0 + row) * K * 2 + kb + ch * 16;
        uint32_t so = tile_off(row, ch);
        cp_async16(st + so,        Ahi + ga);
        cp_async16(st + 8192 + so, Alo + ga);
    }
    // B: 256 rows x 4 chunks, hi+lo
    #pragma unroll
    for (int i = 0; i < 4; i++) {
        int id = tid + 256 * i;
        int row = id >> 2, ch = id & 3;
        size_t gb = (size_t)(col0 + row) * K * 2 + kb + ch * 16;
        uint32_t so = tile_off(row, ch);
        cp_async16(st + 16384 + so, Bhi + gb);
        cp_async16(st + 32768 + so, Blo + gb);
    }
}

__global__ __launch_bounds__(256, 1) void mma_gemm_kernel(
    const __nv_bfloat16* __restrict__ Ahi, const __nv_bfloat16* __restrict__ Alo,
    const __nv_bfloat16* __restrict__ Bhi, const __nv_bfloat16* __restrict__ Blo,
    int M, int N, int K,
    float* __restrict__ Cf, const float* __restrict__ bias,
    const float* __restrict__ residual,
    __nv_bfloat16* __restrict__ Chi, __nv_bfloat16* __restrict__ Clo,
    float* __restrict__ kOut, float* __restrict__ vOut, int mode)
{
    extern __shared__ char smem[];
    uint32_t sbase = smem_u32(smem);

    int tid = threadIdx.x;
    int wid = tid >> 5, l = tid & 31;
    int wr = wid >> 2, wc = wid & 3;   // 2x4 warp grid: 64x64 per warp
    int row0 = blockIdx.y * 128;
    int col0 = blockIdx.x * 256;
    int CH = K >> 5;

    const char* pAhi = (const char*)Ahi;
    const char* pAlo = (const char*)Alo;
    const char* pBhi = (const char*)Bhi;
    const char* pBlo = (const char*)Blo;

    float acc[4][8][4];
    #pragma unroll
    for (int i = 0; i < 4; i++)
        #pragma unroll
        for (int j = 0; j < 8; j++)
            #pragma unroll
            for (int t = 0; t < 4; t++) acc[i][j][t] = 0.f;

    // per-lane ldmatrix geometry
    int aRow = wr * 64 + (l & 15);
    int aHalf = (l >> 4) & 1;
    int bRowL = (l & 7) + ((l >> 4) & 1) * 8;
    int bHalf = (l >> 3) & 1;

    load_stage(sbase, pAhi, pAlo, pBhi, pBlo, K, row0, col0, 0, tid);
    cp_commit();
    load_stage(sbase + STAGE_BYTES, pAhi, pAlo, pBhi, pBlo, K, row0, col0, 1, tid);
    cp_commit();

    for (int c = 0; c < CH; c++) {
        if (c == CH - 1) cp_wait<0>(); else cp_wait<1>();
        __syncthreads();
        if (c + 2 < CH) {
            load_stage(sbase + ((c + 2) % 3) * STAGE_BYTES,
                       pAhi, pAlo, pBhi, pBlo, K, row0, col0, c + 2, tid);
            cp_commit();
        }
        uint32_t st = sbase + (c % 3) * STAGE_BYTES;
        #pragma unroll
        for (int ks = 0; ks < 2; ks++) {
            uint32_t ahi[4][4], alo[4][4];
            #pragma unroll
            for (int mt = 0; mt < 4; mt++) {
                uint32_t off = tile_off(aRow + mt * 16, ks * 2 + aHalf);
                ldsm4(ahi[mt][0], ahi[mt][1], ahi[mt][2], ahi[mt][3], st + off);
                ldsm4(alo[mt][0], alo[mt][1], alo[mt][2], alo[mt][3], st + 8192 + off);
            }
            uint32_t bhi[8][2], blo[8][2];
            #pragma unroll
            for (int p = 0; p < 4; p++) {
                uint32_t off = tile_off(wc * 64 + p * 16 + bRowL, ks * 2 + bHalf);
                ldsm4(bhi[2*p][0], bhi[2*p][1], bhi[2*p+1][0], bhi[2*p+1][1],
                      st + 16384 + off);
                ldsm4(blo[2*p][0], blo[2*p][1], blo[2*p+1][0], blo[2*p+1][1],
                      st + 32768 + off);
            }
            #pragma unroll
            for (int mt = 0; mt < 4; mt++)
                #pragma unroll
                for (int nt = 0; nt < 8; nt++) {
                    mma16816(acc[mt][nt], ahi[mt], bhi[nt][0], bhi[nt][1]);
                    mma16816(acc[mt][nt], ahi[mt], blo[nt][0], blo[nt][1]);
                    mma16816(acc[mt][nt], alo[mt], bhi[nt][0], bhi[nt][1]);
                }
        }
    }

    // epilogue
    int rb = row0 + wr * 64 + (l >> 2);
    int cb = col0 + wc * 64 + (l & 3) * 2;

    if (mode == 3) {
        int seg = col0 >> 10;                 // tile fully inside one segment
        float* dst = (seg == 0) ? Cf : ((seg == 1) ? kOut : vOut);
        int csub = seg << 10;
        bool dorelu = (seg < 2);
        #pragma unroll
        for (int mt = 0; mt < 4; mt++)
            #pragma unroll
            for (int half = 0; half < 2; half++) {
                int r = rb + mt * 16 + half * 8;
                #pragma unroll
                for (int nt = 0; nt < 8; nt++) {
                    int ccol = cb + nt * 8 - csub;
                    float v0 = acc[mt][nt][half * 2];
                    float v1 = acc[mt][nt][half * 2 + 1];
                    if (dorelu) {
                        v0 = fmaxf(v0, 0.f) + 1e-6f;
                        v1 = fmaxf(v1, 0.f) + 1e-6f;
                    }
                    float2 o; o.x = v0; o.y = v1;
                    *reinterpret_cast<float2*>(dst + (size_t)r * 1024 + ccol) = o;
                }
            }
        return;
    }

    #pragma unroll
    for (int mt = 0; mt < 4; mt++) {
        #pragma unroll
        for (int half = 0; half < 2; half++) {
            int r = rb + mt * 16 + half * 8;
            #pragma unroll
            for (int nt = 0; nt < 8; nt++) {
                int ccol = cb + nt * 8;
                float v0 = acc[mt][nt][half * 2];
                float v1 = acc[mt][nt][half * 2 + 1];
                if (mode == 2) {
                    v0 += bias[ccol];
                    v1 += bias[ccol + 1];
                    v0 = 0.5f * v0 * (1.0f + erff(v0 * 0.70710678118654752f));
                    v1 = 0.5f * v1 * (1.0f + erff(v1 * 0.70710678118654752f));
                    split_store2(Chi, Clo, (size_t)r * N + ccol, v0, v1);
                } else {
                    if (mode == 1) {
                        v0 += bias[ccol];
                        v1 += bias[ccol + 1];
                        const float2 rr = *reinterpret_cast<const float2*>(
                            residual + (size_t)r * N + ccol);
                        v0 += rr.x; v1 += rr.y;
                    }
                    float2 o; o.x = v0; o.y = v1;
                    *reinterpret_cast<float2*>(Cf + (size_t)r * N + ccol) = o;
                }
            }
        }
    }
}

// ---------------------------------------------------------------------------
// kv partials + reduce
// ---------------------------------------------------------------------------
__global__ __launch_bounds__(256) void kv_kernel(const float* __restrict__ kf,
                                                 const float* __restrict__ vv,
                                                 float* __restrict__ kvp,
                                                 float* __restrict__ ksp)
{
    int bh = blockIdx.x;
    int b = bh >> 4, h = bh & 15;
    int chunk = blockIdx.y;

    __shared__ float ks[16][64];
    __shared__ float vs[16][64];
    int tid = threadIdx.x;
    int fq = tid >> 4, dq = tid & 15;
    int ln = tid >> 4, lc = (tid & 15) * 4;

    float acc[4][4];
    #pragma unroll
    for (int i = 0; i < 4; i++)
        #pragma unroll
        for (int j = 0; j < 4; j++) acc[i][j] = 0.f;
    float ksacc = 0.f;

    size_t base = (size_t)b * SS * DD + (size_t)h * 64;
    int nstart = chunk * 512;
    for (int n0 = nstart; n0 < nstart + 512; n0 += 16) {
        const float* kp = kf + base + (size_t)(n0 + ln) * DD + lc;
        const float* vp = vv + base + (size_t)(n0 + ln) * DD + lc;
        *reinterpret_cast<float4*>(&ks[ln][lc]) = *reinterpret_cast<const float4*>(kp);
        *reinterpret_cast<float4*>(&vs[ln][lc]) = *reinterpret_cast<const float4*>(vp);
        __syncthreads();
        #pragma unroll
        for (int nn = 0; nn < 16; nn++) {
            float rk[4], rv[4];
            #pragma unroll
            for (int i = 0; i < 4; i++) rk[i] = ks[nn][fq * 4 + i];
            #pragma unroll
            for (int j = 0; j < 4; j++) rv[j] = vs[nn][dq * 4 + j];
            #pragma unroll
            for (int i = 0; i < 4; i++)
                #pragma unroll
                for (int j = 0; j < 4; j++)
                    acc[i][j] = fmaf(rk[i], rv[j], acc[i][j]);
        }
        if (tid < 64) {
            #pragma unroll
            for (int nn = 0; nn < 16; nn++) ksacc += ks[nn][tid];
        }
        __syncthreads();
    }

    float* dst = kvp + (size_t)chunk * 64 * 4096 + (size_t)bh * 4096;
    #pragma unroll
    for (int i = 0; i < 4; i++)
        #pragma unroll
        for (int j = 0; j < 4; j++)
            dst[(fq * 4 + i) * 64 + dq * 4 + j] = acc[i][j];
    if (tid < 64)
        ksp[(size_t)chunk * 64 * 64 + bh * 64 + tid] = ksacc;
}

__global__ __launch_bounds__(256) void kv_reduce_kernel(const float* __restrict__ kvp,
                                                        const float* __restrict__ ksp,
                                                        float* __restrict__ kv,
                                                        float* __restrict__ ksum)
{
    int i = blockIdx.x * 256 + threadIdx.x;
    if (i < 64 * 4096) {
        float s = 0.f;
        #pragma unroll
        for (int c = 0; c < 8; c++) s += kvp[(size_t)c * 64 * 4096 + i];
        kv[i] = s;
    }
    if (i < 64 * 64) {
        float s = 0.f;
        #pragma unroll
        for (int c = 0; c < 8; c++) s += ksp[(size_t)c * 64 * 64 + i];
        ksum[i] = s;
    }
}

// ---------------------------------------------------------------------------
// attn: row -> (row @ kv[bh]) / (row . ksum[bh] + eps), written as bf16 hi/lo
// ---------------------------------------------------------------------------
__global__ __launch_bounds__(256) void attn_kernel(const float* __restrict__ qf,
                                                   const float* __restrict__ kv,
                                                   const float* __restrict__ ksum,
                                                   __nv_bfloat16* __restrict__ ohi,
                                                   __nv_bfloat16* __restrict__ olo)
{
    __shared__ float kvS[64 * 64];
    __shared__ float ks[64];
    __shared__ float rowbuf[8][64];

    int bh = blockIdx.x;
    int b = bh >> 4, h = bh & 15;
    int tid = threadIdx.x, w = tid >> 5, l = tid & 31;

    for (int i = tid; i < 64 * 64; i += 256) kvS[i] = kv[(size_t)bh * 4096 + i];
    if (tid < 64) ks[tid] = ksum[bh * 64 + tid];
    __syncthreads();

    size_t base = (size_t)b * SS * DD + (size_t)h * 64;
    int n0 = blockIdx.y * 64 + w * 8;
    for (int r = 0; r < 8; r++) {
        const float* p = qf + base + (size_t)(n0 + r) * DD;
        rowbuf[w][l]      = p[l];
        rowbuf[w][l + 32] = p[l + 32];
        __syncwarp();
        float dsum = rowbuf[w][l] * ks[l] + rowbuf[w][l + 32] * ks[l + 32];
        #pragma unroll
        for (int off = 16; off > 0; off >>= 1)
            dsum += __shfl_xor_sync(0xffffffffu, dsum, off);
        float inv = 1.0f / (dsum + 1e-6f);
        float a0 = 0.f, a1 = 0.f;
        #pragma unroll
        for (int f = 0; f < 64; f++) {
            float qv = rowbuf[w][f];
            a0 = fmaf(qv, kvS[f * 64 + l],      a0);
            a1 = fmaf(qv, kvS[f * 64 + l + 32], a1);
        }
        __syncwarp();
        a0 *= inv; a1 *= inv;
        size_t i0 = base + (size_t)(n0 + r) * DD;
        __nv_bfloat16 h0 = __float2bfloat16(a0);
        __nv_bfloat16 h1 = __float2bfloat16(a1);
        ohi[i0 + l]      = h0;
        ohi[i0 + l + 32] = h1;
        olo[i0 + l]      = __float2bfloat16(a0 - __bfloat162float(h0));
        olo[i0 + l + 32] = __float2bfloat16(a1 - __bfloat162float(h1));
    }
}

// ---------------------------------------------------------------------------
// Launch
// ---------------------------------------------------------------------------
extern "C" void kernel_launch(void* const* d_in, const int* in_sizes, int n_in,
                              void* d_out, int out_size)
{
    const float* x     = (const float*)d_in[0];
    const float* ln1_g = (const float*)d_in[1];
    const float* ln1_b = (const float*)d_in[2];
    const float* wq    = (const float*)d_in[3];
    const float* wk    = (const float*)d_in[4];
    const float* wv    = (const float*)d_in[5];
    const float* proj  = (const float*)d_in[6];
    const float* wo    = (const float*)d_in[7];
    const float* bo    = (const float*)d_in[8];
    const float* ln2_g = (const float*)d_in[9];
    const float* ln2_b = (const float*)d_in[10];
    const float* w1    = (const float*)d_in[11];
    const float* b1    = (const float*)d_in[12];
    const float* w2    = (const float*)d_in[13];
    const float* b2    = (const float*)d_in[14];
    float* out = (float*)d_out;

    float *q, *k, *v, *kvp, *ksp, *kv, *ksum;
    __nv_bfloat16 *h_hi, *h_lo, *at_hi, *at_lo, *ffn_hi, *ffn_lo;
    __nv_bfloat16 *wqkvT_hi, *wqkvT_lo;
    __nv_bfloat16 *woT_hi, *woT_lo, *w1T_hi, *w1T_lo, *w2T_hi, *w2T_lo;
    cudaGetSymbolAddress((void**)&q, g_q);
    cudaGetSymbolAddress((void**)&k, g_k);
    cudaGetSymbolAddress((void**)&v, g_v);
    cudaGetSymbolAddress((void**)&kvp, g_kvp);
    cudaGetSymbolAddress((void**)&ksp, g_ksp);
    cudaGetSymbolAddress((void**)&kv, g_kv);
    cudaGetSymbolAddress((void**)&ksum, g_ksum);
    cudaGetSymbolAddress((void**)&h_hi, g_h_hi);
    cudaGetSymbolAddress((void**)&h_lo, g_h_lo);
    cudaGetSymbolAddress((void**)&at_hi, g_at_hi);
    cudaGetSymbolAddress((void**)&at_lo, g_at_lo);
    cudaGetSymbolAddress((void**)&ffn_hi, g_ffn_hi);
    cudaGetSymbolAddress((void**)&ffn_lo, g_ffn_lo);
    cudaGetSymbolAddress((void**)&wqkvT_hi, g_wqkvT_hi);
    cudaGetSymbolAddress((void**)&wqkvT_lo, g_wqkvT_lo);
    cudaGetSymbolAddress((void**)&woT_hi, g_woT_hi);
    cudaGetSymbolAddress((void**)&woT_lo, g_woT_lo);
    cudaGetSymbolAddress((void**)&w1T_hi, g_w1T_hi);
    cudaGetSymbolAddress((void**)&w1T_lo, g_w1T_lo);
    cudaGetSymbolAddress((void**)&w2T_hi, g_w2T_hi);
    cudaGetSymbolAddress((void**)&w2T_lo, g_w2T_lo);

    cudaFuncSetAttribute(mma_gemm_kernel,
                         cudaFuncAttributeMaxDynamicSharedMemorySize, GEMM_SMEM);

    // --- weight prep ---
    // fold proj into wq, wk (fp32 temps live in g_q scratch; consumed before QKV)
    float* tmp0 = q;                 // [1024*1024]
    float* tmp1 = q + 1024 * 1024;   // [1024*1024]
    fold_kernel<<<dim3(DD / 64, HH), 256>>>(wq, proj, tmp0);
    fold_kernel<<<dim3(DD / 64, HH), 256>>>(wk, proj, tmp1);
    // transpose+split into concatenated [3072, 1024] buffer
    ts_kernel<<<dim3(DD / 32, DD / 32), 256>>>(tmp0, wqkvT_hi,               wqkvT_lo,               DD, DD);
    ts_kernel<<<dim3(DD / 32, DD / 32), 256>>>(tmp1, wqkvT_hi + 1024 * 1024, wqkvT_lo + 1024 * 1024, DD, DD);
    ts_kernel<<<dim3(DD / 32, DD / 32), 256>>>(wv,   wqkvT_hi + 2048 * 1024, wqkvT_lo + 2048 * 1024, DD, DD);
    ts_kernel<<<dim3(DD / 32, DD / 32), 256>>>(wo, woT_hi, woT_lo, DD, DD);
    ts_kernel<<<dim3(DFF / 32, DD / 32), 256>>>(w1, w1T_hi, w1T_lo, DD, DFF);
    ts_kernel<<<dim3(DD / 32, DFF / 32), 256>>>(w2, w2T_hi, w2T_lo, DFF, DD);

    // LN1 -> h (bf16 hi/lo)
    ln_kernel<<<NTOK, 256>>>(x, ln1_g, ln1_b, h_hi, h_lo);

    // Fused QKV GEMM: N=3072 -> q (relu+eps), k (relu+eps), v
    dim3 gQKV(3072 / 256, NTOK / 128);
    mma_gemm_kernel<<<gQKV, 256, GEMM_SMEM>>>(h_hi, h_lo, wqkvT_hi, wqkvT_lo,
        NTOK, 3072, DD, q, nullptr, nullptr, nullptr, nullptr, k, v, 3);

    // kv / ksum
    kv_kernel<<<dim3(64, 8), 256>>>(k, v, kvp, ksp);
    kv_reduce_kernel<<<(64 * 4096 + 255) / 256, 256>>>(kvp, ksp, kv, ksum);

    // attn -> bf16 hi/lo
    attn_kernel<<<dim3(64, 64), 256>>>(q, kv, ksum, at_hi, at_lo);

    // x2 = x + attn @ wo + bo -> out (fp32)
    dim3 gD(DD / 256, NTOK / 128);
    mma_gemm_kernel<<<gD, 256, GEMM_SMEM>>>(at_hi, at_lo, woT_hi, woT_lo,
        NTOK, DD, DD, out, bo, x, nullptr, nullptr, nullptr, nullptr, 1);

    // LN2 -> h (bf16 hi/lo)
    ln_kernel<<<NTOK, 256>>>(out, ln2_g, ln2_b, h_hi, h_lo);

    // ffn = gelu(h2 @ w1 + b1) -> bf16 hi/lo
    dim3 gF1(DFF / 256, NTOK / 128);
    mma_gemm_kernel<<<gF1, 256, GEMM_SMEM>>>(h_hi, h_lo, w1T_hi, w1T_lo,
        NTOK, DFF, DD, nullptr, b1, nullptr, ffn_hi, ffn_lo, nullptr, nullptr, 2);

    // out = x2 + ffn @ w2 + b2 (in-place residual)
    mma_gemm_kernel<<<gD, 256, GEMM_SMEM>>>(ffn_hi, ffn_lo, w2T_hi, w2T_lo,
        NTOK, DD, DFF, out, b2, out, nullptr, nullptr, nullptr, nullptr, 1);
}

// round 5
// speedup vs baseline: 4.2034x; 1.4195x over previous
#include <cuda_runtime.h>
#include <cuda_fp16.h>
#include <math.h>
#include <stdint.h>

// ---------------------------------------------------------------------------
// Problem constants
// ---------------------------------------------------------------------------
#define BB 4
#define SS 4096
#define DD 1024
#define HH 16
#define DH 64
#define FF 64
#define DFF 4096
#define NTOK (BB * SS)            // 16384 tokens

// ---------------------------------------------------------------------------
// Scratch (static device globals)
// ---------------------------------------------------------------------------
__device__ float g_q[(size_t)NTOK * DD];   // also fp32 temp for folded weights
__device__ float g_k[(size_t)NTOK * DD];
__device__ float g_v[(size_t)NTOK * DD];
__device__ __half g_h_hi[(size_t)NTOK * DD];
__device__ __half g_h_lo[(size_t)NTOK * DD];
__device__ __half g_at_hi[(size_t)NTOK * DD];
__device__ __half g_at_lo[(size_t)NTOK * DD];
__device__ __half g_ffn_hi[(size_t)NTOK * DFF];
__device__ __half g_ffn_lo[(size_t)NTOK * DFF];
// Transposed single-fp16 weights, [N, K]
__device__ __half g_wqkvT[3 * DD * DD];    // folded q, folded k, v
__device__ __half g_woT[DD * DD];
__device__ __half g_w1T[(size_t)DFF * DD];
__device__ __half g_w2T[(size_t)DD * DFF];
// linear-attention small tensors
__device__ float g_kvp[8 * 64 * FF * DH];
__device__ float g_ksp[8 * 64 * FF];
__device__ float g_kv[64 * FF * DH];
__device__ float g_ksum[64 * FF];

// ---------------------------------------------------------------------------
// PTX helpers (baseline PTX only — no 'a'-suffix features)
// ---------------------------------------------------------------------------
__device__ __forceinline__ uint32_t smem_u32(const void* p) {
    uint32_t a;
    asm("{ .reg .u64 t; cvta.to.shared.u64 t, %1; cvt.u32.u64 %0, t; }"
        : "=r"(a) : "l"(p));
    return a;
}
__device__ __forceinline__ void cp_async16(uint32_t dst, const void* src) {
    asm volatile("cp.async.cg.shared.global [%0], [%1], 16;\n" :: "r"(dst), "l"(src));
}
__device__ __forceinline__ void cp_commit() {
    asm volatile("cp.async.commit_group;\n" ::: "memory");
}
template <int N>
__device__ __forceinline__ void cp_wait() {
    asm volatile("cp.async.wait_group %0;\n" :: "n"(N) : "memory");
}
__device__ __forceinline__ void ldsm4(uint32_t& r0, uint32_t& r1, uint32_t& r2,
                                      uint32_t& r3, uint32_t addr) {
    asm volatile("ldmatrix.sync.aligned.m8n8.x4.shared.b16 {%0,%1,%2,%3}, [%4];"
                 : "=r"(r0), "=r"(r1), "=r"(r2), "=r"(r3) : "r"(addr));
}
__device__ __forceinline__ void mma16816(float* c, const uint32_t* a,
                                         uint32_t b0, uint32_t b1) {
    asm volatile(
        "mma.sync.aligned.m16n8k16.row.col.f32.f16.f16.f32 "
        "{%0,%1,%2,%3}, {%4,%5,%6,%7}, {%8,%9}, {%0,%1,%2,%3};"
        : "+f"(c[0]), "+f"(c[1]), "+f"(c[2]), "+f"(c[3])
        : "r"(a[0]), "r"(a[1]), "r"(a[2]), "r"(a[3]), "r"(b0), "r"(b1));
}

// ---------------------------------------------------------------------------
// Fold proj into a QK weight: out[d, h*64+f] = sum_dh W[d, h*64+dh]*proj[dh,f]
// ---------------------------------------------------------------------------
__global__ __launch_bounds__(256) void fold_kernel(const float* __restrict__ W,
                                                   const float* __restrict__ proj,
                                                   float* __restrict__ outW)
{
    __shared__ float projS[64][64];
    __shared__ float wS[64][65];
    int d0 = blockIdx.x * 64, h = blockIdx.y;
    int tid = threadIdx.x;
    for (int i = tid; i < 64 * 64; i += 256)
        projS[i >> 6][i & 63] = proj[i];
    for (int i = tid; i < 64 * 64; i += 256)
        wS[i >> 6][i & 63] = W[(size_t)(d0 + (i >> 6)) * (HH * DH) + h * 64 + (i & 63)];
    __syncthreads();
    int r = tid >> 2;
    int fb = (tid & 3) * 16;
    float acc[16];
    #pragma unroll
    for (int i = 0; i < 16; i++) acc[i] = 0.f;
    #pragma unroll 8
    for (int c = 0; c < 64; c++) {
        float w = wS[r][c];
        #pragma unroll
        for (int i = 0; i < 16; i++)
            acc[i] = fmaf(w, projS[c][fb + i], acc[i]);
    }
    for (int i = 0; i < 16; i++)
        outW[(size_t)(d0 + r) * (HH * FF) + h * 64 + fb + i] = acc[i];
}

// ---------------------------------------------------------------------------
// Weight transpose + fp16 convert:  W[K,N] -> Wt[N,K]
// ---------------------------------------------------------------------------
__global__ __launch_bounds__(256) void ts_kernel(const float* __restrict__ W,
                                                 __half* __restrict__ o,
                                                 int K, int N)
{
    __shared__ float t[32][33];
    int n0 = blockIdx.x * 32, k0 = blockIdx.y * 32;
    int tx = threadIdx.x & 31, ty = threadIdx.x >> 5;
    for (int r = ty; r < 32; r += 8)
        t[r][tx] = W[(size_t)(k0 + r) * N + n0 + tx];
    __syncthreads();
    for (int r = ty; r < 32; r += 8)
        o[(size_t)(n0 + r) * K + k0 + tx] = __float2half_rn(t[tx][r]);
}

// ---------------------------------------------------------------------------
// split-store helper (2 consecutive elements), fp16 hi + residual lo
// ---------------------------------------------------------------------------
__device__ __forceinline__ void split_store2(__half* hi, __half* lo,
                                             size_t idx, float a, float b)
{
    __half ha = __float2half_rn(a);
    __half hb = __float2half_rn(b);
    __half la = __float2half_rn(a - __half2float(ha));
    __half lb = __float2half_rn(b - __half2float(hb));
    *reinterpret_cast<__half2*>(hi + idx) = __halves2half2(ha, hb);
    *reinterpret_cast<__half2*>(lo + idx) = __halves2half2(la, lb);
}

// ---------------------------------------------------------------------------
// LayerNorm -> fp16 hi/lo. One block (256 thr) per row of 1024.
// ---------------------------------------------------------------------------
__global__ __launch_bounds__(256) void ln_kernel(const float* __restrict__ x,
                                                 const float* __restrict__ g,
                                                 const float* __restrict__ b,
                                                 __half* __restrict__ ohi,
                                                 __half* __restrict__ olo)
{
    int row = blockIdx.x;
    int t = threadIdx.x;
    const float4* xr = reinterpret_cast<const float4*>(x + (size_t)row * DD);
    float4 xv = xr[t];

    float s  = xv.x + xv.y + xv.z + xv.w;
    float s2 = xv.x*xv.x + xv.y*xv.y + xv.z*xv.z + xv.w*xv.w;

    __shared__ float red[2][8];
    #pragma unroll
    for (int off = 16; off > 0; off >>= 1) {
        s  += __shfl_xor_sync(0xffffffffu, s,  off);
        s2 += __shfl_xor_sync(0xffffffffu, s2, off);
    }
    int w = t >> 5, l = t & 31;
    if (l == 0) { red[0][w] = s; red[1][w] = s2; }
    __syncthreads();
    __shared__ float smu, srstd;
    if (t == 0) {
        float ts = 0.f, ts2 = 0.f;
        #pragma unroll
        for (int i = 0; i < 8; i++) { ts += red[0][i]; ts2 += red[1][i]; }
        float mu = ts * (1.0f / DD);
        float var = ts2 * (1.0f / DD) - mu * mu;
        smu = mu;
        srstd = rsqrtf(var + 1e-5f);
    }
    __syncthreads();
    float mu = smu, rstd = srstd;

    const float4 gv = reinterpret_cast<const float4*>(g)[t];
    const float4 bv = reinterpret_cast<const float4*>(b)[t];
    float o0 = (xv.x - mu) * rstd * gv.x + bv.x;
    float o1 = (xv.y - mu) * rstd * gv.y + bv.y;
    float o2 = (xv.z - mu) * rstd * gv.z + bv.z;
    float o3 = (xv.w - mu) * rstd * gv.w + bv.w;
    size_t idx = (size_t)row * DD + t * 4;
    split_store2(ohi, olo, idx,     o0, o1);
    split_store2(ohi, olo, idx + 2, o2, o3);
}

// ---------------------------------------------------------------------------
// HMMA GEMM: C[M,N] = (Ahi + Alo) @ B^T, fp16 inputs, fp32 accum.
// Tile 128x256, BK=32, 4-stage cp.async pipeline, warp tile 64x64.
// mode 0: Cf = val
// mode 1: Cf = val + bias + residual
// mode 2: Chi/Clo = split(gelu(val + bias))
// mode 3: fused qkv: seg0 relu+eps->Cf(q), seg1 relu+eps->kOut, seg2 ->vOut
// ---------------------------------------------------------------------------
#define STAGE_BYTES 32768
#define NSTAGE 4
#define GEMM_SMEM (NSTAGE * STAGE_BYTES)

// swizzled 16B-chunk offset within an Rx32 fp16 tile (64B rows)
__device__ __forceinline__ uint32_t tile_off(int row, int chunk) {
    int sw = chunk ^ (row & 3) ^ ((row >> 2) & 1);
    return (uint32_t)(row * 64 + (sw << 4));
}

__device__ __forceinline__ void load_stage(
    uint32_t st, const char* Ahi, const char* Alo, const char* B,
    int K, int row0, int col0, int kc, int tid)
{
    size_t kb = (size_t)kc * 64;  // byte offset of 32-elem chunk within a row
    // A: 128 rows x 4 chunks, hi+lo
    #pragma unroll
    for (int i = 0; i < 2; i++) {
        int id = tid + 256 * i;
        int row = id >> 2, ch = id & 3;
        size_t ga = (size_t)(row0 + row) * K * 2 + kb + ch * 16;
        uint32_t so = tile_off(row, ch);
        cp_async16(st + so,        Ahi + ga);
        cp_async16(st + 8192 + so, Alo + ga);
    }
    // B: 256 rows x 4 chunks
    #pragma unroll
    for (int i = 0; i < 4; i++) {
        int id = tid + 256 * i;
        int row = id >> 2, ch = id & 3;
        size_t gb = (size_t)(col0 + row) * K * 2 + kb + ch * 16;
        uint32_t so = tile_off(row, ch);
        cp_async16(st + 16384 + so, B + gb);
    }
}

__global__ __launch_bounds__(256, 1) void mma_gemm_kernel(
    const __half* __restrict__ Ahi, const __half* __restrict__ Alo,
    const __half* __restrict__ B,
    int M, int N, int K,
    float* __restrict__ Cf, const float* __restrict__ bias,
    const float* __restrict__ residual,
    __half* __restrict__ Chi, __half* __restrict__ Clo,
    float* __restrict__ kOut, float* __restrict__ vOut, int mode)
{
    extern __shared__ char smem[];
    uint32_t sbase = smem_u32(smem);

    int tid = threadIdx.x;
    int wid = tid >> 5, l = tid & 31;
    int wr = wid >> 2, wc = wid & 3;   // 2x4 warp grid: 64x64 per warp
    int row0 = blockIdx.y * 128;
    int col0 = blockIdx.x * 256;
    int CH = K >> 5;

    const char* pAhi = (const char*)Ahi;
    const char* pAlo = (const char*)Alo;
    const char* pB   = (const char*)B;

    float acc[4][8][4];
    #pragma unroll
    for (int i = 0; i < 4; i++)
        #pragma unroll
        for (int j = 0; j < 8; j++)
            #pragma unroll
            for (int t = 0; t < 4; t++) acc[i][j][t] = 0.f;

    // per-lane ldmatrix geometry
    int aRow = wr * 64 + (l & 15);
    int aHalf = (l >> 4) & 1;
    int bRowL = (l & 7) + ((l >> 4) & 1) * 8;
    int bHalf = (l >> 3) & 1;

    // prologue: stages 0..2
    load_stage(sbase,                   pAhi, pAlo, pB, K, row0, col0, 0, tid);
    cp_commit();
    load_stage(sbase + STAGE_BYTES,     pAhi, pAlo, pB, K, row0, col0, 1, tid);
    cp_commit();
    load_stage(sbase + 2 * STAGE_BYTES, pAhi, pAlo, pB, K, row0, col0, 2, tid);
    cp_commit();

    for (int c = 0; c < CH; c++) {
        cp_wait<2>();
        __syncthreads();
        // tail-clamped prefetch: always one group per iteration
        int nc = c + 3 < CH ? c + 3 : CH - 1;
        load_stage(sbase + ((c + 3) & (NSTAGE - 1)) * STAGE_BYTES,
                   pAhi, pAlo, pB, K, row0, col0, nc, tid);
        cp_commit();

        uint32_t st = sbase + (c & (NSTAGE - 1)) * STAGE_BYTES;
        #pragma unroll
        for (int ks = 0; ks < 2; ks++) {
            uint32_t ahi[4][4], alo[4][4];
            #pragma unroll
            for (int mt = 0; mt < 4; mt++) {
                uint32_t off = tile_off(aRow + mt * 16, ks * 2 + aHalf);
                ldsm4(ahi[mt][0], ahi[mt][1], ahi[mt][2], ahi[mt][3], st + off);
                ldsm4(alo[mt][0], alo[mt][1], alo[mt][2], alo[mt][3], st + 8192 + off);
            }
            uint32_t bf[8][2];
            #pragma unroll
            for (int p = 0; p < 4; p++) {
                uint32_t off = tile_off(wc * 64 + p * 16 + bRowL, ks * 2 + bHalf);
                ldsm4(bf[2*p][0], bf[2*p][1], bf[2*p+1][0], bf[2*p+1][1],
                      st + 16384 + off);
            }
            #pragma unroll
            for (int mt = 0; mt < 4; mt++)
                #pragma unroll
                for (int nt = 0; nt < 8; nt++) {
                    mma16816(acc[mt][nt], ahi[mt], bf[nt][0], bf[nt][1]);
                    mma16816(acc[mt][nt], alo[mt], bf[nt][0], bf[nt][1]);
                }
        }
    }

    // epilogue
    int rb = row0 + wr * 64 + (l >> 2);
    int cb = col0 + wc * 64 + (l & 3) * 2;

    if (mode == 3) {
        int seg = col0 >> 10;                 // tile fully inside one segment
        float* dst = (seg == 0) ? Cf : ((seg == 1) ? kOut : vOut);
        int csub = seg << 10;
        bool dorelu = (seg < 2);
        #pragma unroll
        for (int mt = 0; mt < 4; mt++)
            #pragma unroll
            for (int half = 0; half < 2; half++) {
                int r = rb + mt * 16 + half * 8;
                #pragma unroll
                for (int nt = 0; nt < 8; nt++) {
                    int ccol = cb + nt * 8 - csub;
                    float v0 = acc[mt][nt][half * 2];
                    float v1 = acc[mt][nt][half * 2 + 1];
                    if (dorelu) {
                        v0 = fmaxf(v0, 0.f) + 1e-6f;
                        v1 = fmaxf(v1, 0.f) + 1e-6f;
                    }
                    float2 o; o.x = v0; o.y = v1;
                    *reinterpret_cast<float2*>(dst + (size_t)r * 1024 + ccol) = o;
                }
            }
        return;
    }

    #pragma unroll
    for (int mt = 0; mt < 4; mt++) {
        #pragma unroll
        for (int half = 0; half < 2; half++) {
            int r = rb + mt * 16 + half * 8;
            #pragma unroll
            for (int nt = 0; nt < 8; nt++) {
                int ccol = cb + nt * 8;
                float v0 = acc[mt][nt][half * 2];
                float v1 = acc[mt][nt][half * 2 + 1];
                if (mode == 2) {
                    v0 += bias[ccol];
                    v1 += bias[ccol + 1];
                    v0 = 0.5f * v0 * (1.0f + erff(v0 * 0.70710678118654752f));
                    v1 = 0.5f * v1 * (1.0f + erff(v1 * 0.70710678118654752f));
                    split_store2(Chi, Clo, (size_t)r * N + ccol, v0, v1);
                } else {
                    if (mode == 1) {
                        v0 += bias[ccol];
                        v1 += bias[ccol + 1];
                        const float2 rr = *reinterpret_cast<const float2*>(
                            residual + (size_t)r * N + ccol);
                        v0 += rr.x; v1 += rr.y;
                    }
                    float2 o; o.x = v0; o.y = v1;
                    *reinterpret_cast<float2*>(Cf + (size_t)r * N + ccol) = o;
                }
            }
        }
    }
}

// ---------------------------------------------------------------------------
// kv partials + reduce
// ---------------------------------------------------------------------------
__global__ __launch_bounds__(256) void kv_kernel(const float* __restrict__ kf,
                                                 const float* __restrict__ vv,
                                                 float* __restrict__ kvp,
                                                 float* __restrict__ ksp)
{
    int bh = blockIdx.x;
    int b = bh >> 4, h = bh & 15;
    int chunk = blockIdx.y;

    __shared__ float ks[16][64];
    __shared__ float vs[16][64];
    int tid = threadIdx.x;
    int fq = tid >> 4, dq = tid & 15;
    int ln = tid >> 4, lc = (tid & 15) * 4;

    float acc[4][4];
    #pragma unroll
    for (int i = 0; i < 4; i++)
        #pragma unroll
        for (int j = 0; j < 4; j++) acc[i][j] = 0.f;
    float ksacc = 0.f;

    size_t base = (size_t)b * SS * DD + (size_t)h * 64;
    int nstart = chunk * 512;
    for (int n0 = nstart; n0 < nstart + 512; n0 += 16) {
        const float* kp = kf + base + (size_t)(n0 + ln) * DD + lc;
        const float* vp = vv + base + (size_t)(n0 + ln) * DD + lc;
        *reinterpret_cast<float4*>(&ks[ln][lc]) = *reinterpret_cast<const float4*>(kp);
        *reinterpret_cast<float4*>(&vs[ln][lc]) = *reinterpret_cast<const float4*>(vp);
        __syncthreads();
        #pragma unroll
        for (int nn = 0; nn < 16; nn++) {
            float rk[4], rv[4];
            #pragma unroll
            for (int i = 0; i < 4; i++) rk[i] = ks[nn][fq * 4 + i];
            #pragma unroll
            for (int j = 0; j < 4; j++) rv[j] = vs[nn][dq * 4 + j];
            #pragma unroll
            for (int i = 0; i < 4; i++)
                #pragma unroll
                for (int j = 0; j < 4; j++)
                    acc[i][j] = fmaf(rk[i], rv[j], acc[i][j]);
        }
        if (tid < 64) {
            #pragma unroll
            for (int nn = 0; nn < 16; nn++) ksacc += ks[nn][tid];
        }
        __syncthreads();
    }

    float* dst = kvp + (size_t)chunk * 64 * 4096 + (size_t)bh * 4096;
    #pragma unroll
    for (int i = 0; i < 4; i++)
        #pragma unroll
        for (int j = 0; j < 4; j++)
            dst[(fq * 4 + i) * 64 + dq * 4 + j] = acc[i][j];
    if (tid < 64)
        ksp[(size_t)chunk * 64 * 64 + bh * 64 + tid] = ksacc;
}

__global__ __launch_bounds__(256) void kv_reduce_kernel(const float* __restrict__ kvp,
                                                        const float* __restrict__ ksp,
                                                        float* __restrict__ kv,
                                                        float* __restrict__ ksum)
{
    int i = blockIdx.x * 256 + threadIdx.x;
    if (i < 64 * 4096) {
        float s = 0.f;
        #pragma unroll
        for (int c = 0; c < 8; c++) s += kvp[(size_t)c * 64 * 4096 + i];
        kv[i] = s;
    }
    if (i < 64 * 64) {
        float s = 0.f;
        #pragma unroll
        for (int c = 0; c < 8; c++) s += ksp[(size_t)c * 64 * 64 + i];
        ksum[i] = s;
    }
}

// ---------------------------------------------------------------------------
// attn: row -> (row @ kv[bh]) / (row . ksum[bh] + eps), written as fp16 hi/lo
// ---------------------------------------------------------------------------
__global__ __launch_bounds__(256) void attn_kernel(const float* __restrict__ qf,
                                                   const float* __restrict__ kv,
                                                   const float* __restrict__ ksum,
                                                   __half* __restrict__ ohi,
                                                   __half* __restrict__ olo)
{
    __shared__ float kvS[64 * 64];
    __shared__ float ks[64];
    __shared__ float rowbuf[8][64];

    int bh = blockIdx.x;
    int b = bh >> 4, h = bh & 15;
    int tid = threadIdx.x, w = tid >> 5, l = tid & 31;

    for (int i = tid; i < 64 * 64; i += 256) kvS[i] = kv[(size_t)bh * 4096 + i];
    if (tid < 64) ks[tid] = ksum[bh * 64 + tid];
    __syncthreads();

    size_t base = (size_t)b * SS * DD + (size_t)h * 64;
    int n0 = blockIdx.y * 64 + w * 8;
    for (int r = 0; r < 8; r++) {
        const float* p = qf + base + (size_t)(n0 + r) * DD;
        rowbuf[w][l]      = p[l];
        rowbuf[w][l + 32] = p[l + 32];
        __syncwarp();
        float dsum = rowbuf[w][l] * ks[l] + rowbuf[w][l + 32] * ks[l + 32];
        #pragma unroll
        for (int off = 16; off > 0; off >>= 1)
            dsum += __shfl_xor_sync(0xffffffffu, dsum, off);
        float inv = 1.0f / (dsum + 1e-6f);
        float a0 = 0.f, a1 = 0.f;
        #pragma unroll
        for (int f = 0; f < 64; f++) {
            float qv = rowbuf[w][f];
            a0 = fmaf(qv, kvS[f * 64 + l],      a0);
            a1 = fmaf(qv, kvS[f * 64 + l + 32], a1);
        }
        __syncwarp();
        a0 *= inv; a1 *= inv;
        size_t i0 = base + (size_t)(n0 + r) * DD;
        __half h0 = __float2half_rn(a0);
        __half h1 = __float2half_rn(a1);
        ohi[i0 + l]      = h0;
        ohi[i0 + l + 32] = h1;
        olo[i0 + l]      = __float2half_rn(a0 - __half2float(h0));
        olo[i0 + l + 32] = __float2half_rn(a1 - __half2float(h1));
    }
}

// ---------------------------------------------------------------------------
// Launch
// ---------------------------------------------------------------------------
extern "C" void kernel_launch(void* const* d_in, const int* in_sizes, int n_in,
                              void* d_out, int out_size)
{
    const float* x     = (const float*)d_in[0];
    const float* ln1_g = (const float*)d_in[1];
    const float* ln1_b = (const float*)d_in[2];
    const float* wq    = (const float*)d_in[3];
    const float* wk    = (const float*)d_in[4];
    const float* wv    = (const float*)d_in[5];
    const float* proj  = (const float*)d_in[6];
    const float* wo    = (const float*)d_in[7];
    const float* bo    = (const float*)d_in[8];
    const float* ln2_g = (const float*)d_in[9];
    const float* ln2_b = (const float*)d_in[10];
    const float* w1    = (const float*)d_in[11];
    const float* b1    = (const float*)d_in[12];
    const float* w2    = (const float*)d_in[13];
    const float* b2    = (const float*)d_in[14];
    float* out = (float*)d_out;

    float *q, *k, *v, *kvp, *ksp, *kv, *ksum;
    __half *h_hi, *h_lo, *at_hi, *at_lo, *ffn_hi, *ffn_lo;
    __half *wqkvT, *woT, *w1T, *w2T;
    cudaGetSymbolAddress((void**)&q, g_q);
    cudaGetSymbolAddress((void**)&k, g_k);
    cudaGetSymbolAddress((void**)&v, g_v);
    cudaGetSymbolAddress((void**)&kvp, g_kvp);
    cudaGetSymbolAddress((void**)&ksp, g_ksp);
    cudaGetSymbolAddress((void**)&kv, g_kv);
    cudaGetSymbolAddress((void**)&ksum, g_ksum);
    cudaGetSymbolAddress((void**)&h_hi, g_h_hi);
    cudaGetSymbolAddress((void**)&h_lo, g_h_lo);
    cudaGetSymbolAddress((void**)&at_hi, g_at_hi);
    cudaGetSymbolAddress((void**)&at_lo, g_at_lo);
    cudaGetSymbolAddress((void**)&ffn_hi, g_ffn_hi);
    cudaGetSymbolAddress((void**)&ffn_lo, g_ffn_lo);
    cudaGetSymbolAddress((void**)&wqkvT, g_wqkvT);
    cudaGetSymbolAddress((void**)&woT, g_woT);
    cudaGetSymbolAddress((void**)&w1T, g_w1T);
    cudaGetSymbolAddress((void**)&w2T, g_w2T);

    cudaFuncSetAttribute(mma_gemm_kernel,
                         cudaFuncAttributeMaxDynamicSharedMemorySize, GEMM_SMEM);

    // --- weight prep ---
    float* tmp0 = q;                 // [1024*1024] fp32 temps, consumed pre-QKV
    float* tmp1 = q + 1024 * 1024;
    fold_kernel<<<dim3(DD / 64, HH), 256>>>(wq, proj, tmp0);
    fold_kernel<<<dim3(DD / 64, HH), 256>>>(wk, proj, tmp1);
    ts_kernel<<<dim3(DD / 32, DD / 32), 256>>>(tmp0, wqkvT,               DD, DD);
    ts_kernel<<<dim3(DD / 32, DD / 32), 256>>>(tmp1, wqkvT + 1024 * 1024, DD, DD);
    ts_kernel<<<dim3(DD / 32, DD / 32), 256>>>(wv,   wqkvT + 2048 * 1024, DD, DD);
    ts_kernel<<<dim3(DD / 32, DD / 32), 256>>>(wo, woT, DD, DD);
    ts_kernel<<<dim3(DFF / 32, DD / 32), 256>>>(w1, w1T, DD, DFF);
    ts_kernel<<<dim3(DD / 32, DFF / 32), 256>>>(w2, w2T, DFF, DD);

    // LN1 -> h (fp16 hi/lo)
    ln_kernel<<<NTOK, 256>>>(x, ln1_g, ln1_b, h_hi, h_lo);

    // Fused QKV GEMM: N=3072 -> q (relu+eps), k (relu+eps), v
    dim3 gQKV(3072 / 256, NTOK / 128);
    mma_gemm_kernel<<<gQKV, 256, GEMM_SMEM>>>(h_hi, h_lo, wqkvT,
        NTOK, 3072, DD, q, nullptr, nullptr, nullptr, nullptr, k, v, 3);

    // kv / ksum
    kv_kernel<<<dim3(64, 8), 256>>>(k, v, kvp, ksp);
    kv_reduce_kernel<<<(64 * 4096 + 255) / 256, 256>>>(kvp, ksp, kv, ksum);

    // attn -> fp16 hi/lo
    attn_kernel<<<dim3(64, 64), 256>>>(q, kv, ksum, at_hi, at_lo);

    // x2 = x + attn @ wo + bo -> out (fp32)
    dim3 gD(DD / 256, NTOK / 128);
    mma_gemm_kernel<<<gD, 256, GEMM_SMEM>>>(at_hi, at_lo, woT,
        NTOK, DD, DD, out, bo, x, nullptr, nullptr, nullptr, nullptr, 1);

    // LN2 -> h (fp16 hi/lo)
    ln_kernel<<<NTOK, 256>>>(out, ln2_g, ln2_b, h_hi, h_lo);

    // ffn = gelu(h2 @ w1 + b1) -> fp16 hi/lo
    dim3 gF1(DFF / 256, NTOK / 128);
    mma_gemm_kernel<<<gF1, 256, GEMM_SMEM>>>(h_hi, h_lo, w1T,
        NTOK, DFF, DD, nullptr, b1, nullptr, ffn_hi, ffn_lo, nullptr, nullptr, 2);

    // out = x2 + ffn @ w2 + b2 (in-place residual)
    mma_gemm_kernel<<<gD, 256, GEMM_SMEM>>>(ffn_hi, ffn_lo, w2T,
        NTOK, DD, DFF, out, b2, out, nullptr, nullptr, nullptr, nullptr, 1);
}

// round 6
// speedup vs baseline: 6.1831x; 1.4710x over previous
#include <cuda_runtime.h>
#include <cuda_fp16.h>
#include <math.h>
#include <stdint.h>

// ---------------------------------------------------------------------------
// Problem constants
// ---------------------------------------------------------------------------
#define BB 4
#define SS 4096
#define DD 1024
#define HH 16
#define DH 64
#define FF 64
#define DFF 4096
#define NTOK (BB * SS)            // 16384 tokens

// ---------------------------------------------------------------------------
// Scratch (static device globals)
// ---------------------------------------------------------------------------
__device__ float g_q[(size_t)NTOK * DD];   // also fp32 temp for folded weights
__device__ float g_k[(size_t)NTOK * DD];
__device__ float g_v[(size_t)NTOK * DD];
__device__ __half g_h[(size_t)NTOK * DD];      // LN out (A operand), fp16
__device__ __half g_at[(size_t)NTOK * DD];     // attn out (A of wo), fp16
__device__ __half g_ffn[(size_t)NTOK * DFF];   // gelu out (A of w2), fp16
// Transposed single-fp16 weights, [N, K]
__device__ __half g_wqkvT[3 * DD * DD];    // folded q, folded k, v
__device__ __half g_woT[DD * DD];
__device__ __half g_w1T[(size_t)DFF * DD];
__device__ __half g_w2T[(size_t)DD * DFF];
// linear-attention small tensors
__device__ float g_kvp[8 * 64 * FF * DH];
__device__ float g_ksp[8 * 64 * FF];
__device__ float g_kv[64 * FF * DH];
__device__ float g_ksum[64 * FF];

// ---------------------------------------------------------------------------
// PTX helpers (baseline PTX only — no 'a'-suffix features)
// ---------------------------------------------------------------------------
__device__ __forceinline__ uint32_t smem_u32(const void* p) {
    uint32_t a;
    asm("{ .reg .u64 t; cvta.to.shared.u64 t, %1; cvt.u32.u64 %0, t; }"
        : "=r"(a) : "l"(p));
    return a;
}
__device__ __forceinline__ void cp_async16(uint32_t dst, const void* src) {
    asm volatile("cp.async.cg.shared.global [%0], [%1], 16;\n" :: "r"(dst), "l"(src));
}
__device__ __forceinline__ void cp_commit() {
    asm volatile("cp.async.commit_group;\n" ::: "memory");
}
template <int N>
__device__ __forceinline__ void cp_wait() {
    asm volatile("cp.async.wait_group %0;\n" :: "n"(N) : "memory");
}
__device__ __forceinline__ void ldsm4(uint32_t& r0, uint32_t& r1, uint32_t& r2,
                                      uint32_t& r3, uint32_t addr) {
    asm volatile("ldmatrix.sync.aligned.m8n8.x4.shared.b16 {%0,%1,%2,%3}, [%4];"
                 : "=r"(r0), "=r"(r1), "=r"(r2), "=r"(r3) : "r"(addr));
}
__device__ __forceinline__ void mma16816(float* c, const uint32_t* a,
                                         uint32_t b0, uint32_t b1) {
    asm volatile(
        "mma.sync.aligned.m16n8k16.row.col.f32.f16.f16.f32 "
        "{%0,%1,%2,%3}, {%4,%5,%6,%7}, {%8,%9}, {%0,%1,%2,%3};"
        : "+f"(c[0]), "+f"(c[1]), "+f"(c[2]), "+f"(c[3])
        : "r"(a[0]), "r"(a[1]), "r"(a[2]), "r"(a[3]), "r"(b0), "r"(b1));
}

// ---------------------------------------------------------------------------
// Fold proj into a QK weight: out[d, h*64+f] = sum_dh W[d, h*64+dh]*proj[dh,f]
// ---------------------------------------------------------------------------
__global__ __launch_bounds__(256) void fold_kernel(const float* __restrict__ W,
                                                   const float* __restrict__ proj,
                                                   float* __restrict__ outW)
{
    __shared__ float projS[64][64];
    __shared__ float wS[64][65];
    int d0 = blockIdx.x * 64, h = blockIdx.y;
    int tid = threadIdx.x;
    for (int i = tid; i < 64 * 64; i += 256)
        projS[i >> 6][i & 63] = proj[i];
    for (int i = tid; i < 64 * 64; i += 256)
        wS[i >> 6][i & 63] = W[(size_t)(d0 + (i >> 6)) * (HH * DH) + h * 64 + (i & 63)];
    __syncthreads();
    int r = tid >> 2;
    int fb = (tid & 3) * 16;
    float acc[16];
    #pragma unroll
    for (int i = 0; i < 16; i++) acc[i] = 0.f;
    #pragma unroll 8
    for (int c = 0; c < 64; c++) {
        float w = wS[r][c];
        #pragma unroll
        for (int i = 0; i < 16; i++)
            acc[i] = fmaf(w, projS[c][fb + i], acc[i]);
    }
    for (int i = 0; i < 16; i++)
        outW[(size_t)(d0 + r) * (HH * FF) + h * 64 + fb + i] = acc[i];
}

// ---------------------------------------------------------------------------
// Weight transpose + fp16 convert:  W[K,N] -> Wt[N,K]
// ---------------------------------------------------------------------------
__global__ __launch_bounds__(256) void ts_kernel(const float* __restrict__ W,
                                                 __half* __restrict__ o,
                                                 int K, int N)
{
    __shared__ float t[32][33];
    int n0 = blockIdx.x * 32, k0 = blockIdx.y * 32;
    int tx = threadIdx.x & 31, ty = threadIdx.x >> 5;
    for (int r = ty; r < 32; r += 8)
        t[r][tx] = W[(size_t)(k0 + r) * N + n0 + tx];
    __syncthreads();
    for (int r = ty; r < 32; r += 8)
        o[(size_t)(n0 + r) * K + k0 + tx] = __float2half_rn(t[tx][r]);
}

// ---------------------------------------------------------------------------
// LayerNorm -> fp16. One block (256 thr) per row of 1024.
// ---------------------------------------------------------------------------
__global__ __launch_bounds__(256) void ln_kernel(const float* __restrict__ x,
                                                 const float* __restrict__ g,
                                                 const float* __restrict__ b,
                                                 __half* __restrict__ o)
{
    int row = blockIdx.x;
    int t = threadIdx.x;
    const float4* xr = reinterpret_cast<const float4*>(x + (size_t)row * DD);
    float4 xv = xr[t];

    float s  = xv.x + xv.y + xv.z + xv.w;
    float s2 = xv.x*xv.x + xv.y*xv.y + xv.z*xv.z + xv.w*xv.w;

    __shared__ float red[2][8];
    #pragma unroll
    for (int off = 16; off > 0; off >>= 1) {
        s  += __shfl_xor_sync(0xffffffffu, s,  off);
        s2 += __shfl_xor_sync(0xffffffffu, s2, off);
    }
    int w = t >> 5, l = t & 31;
    if (l == 0) { red[0][w] = s; red[1][w] = s2; }
    __syncthreads();
    __shared__ float smu, srstd;
    if (t == 0) {
        float ts = 0.f, ts2 = 0.f;
        #pragma unroll
        for (int i = 0; i < 8; i++) { ts += red[0][i]; ts2 += red[1][i]; }
        float mu = ts * (1.0f / DD);
        float var = ts2 * (1.0f / DD) - mu * mu;
        smu = mu;
        srstd = rsqrtf(var + 1e-5f);
    }
    __syncthreads();
    float mu = smu, rstd = srstd;

    const float4 gv = reinterpret_cast<const float4*>(g)[t];
    const float4 bv = reinterpret_cast<const float4*>(b)[t];
    float o0 = (xv.x - mu) * rstd * gv.x + bv.x;
    float o1 = (xv.y - mu) * rstd * gv.y + bv.y;
    float o2 = (xv.z - mu) * rstd * gv.z + bv.z;
    float o3 = (xv.w - mu) * rstd * gv.w + bv.w;
    size_t idx = (size_t)row * DD + t * 4;
    __half2 p0 = __halves2half2(__float2half_rn(o0), __float2half_rn(o1));
    __half2 p1 = __halves2half2(__float2half_rn(o2), __float2half_rn(o3));
    *reinterpret_cast<__half2*>(o + idx)     = p0;
    *reinterpret_cast<__half2*>(o + idx + 2) = p1;
}

// ---------------------------------------------------------------------------
// HMMA GEMM: C[M,N] = A @ B^T, fp16 inputs, fp32 accum.
// Tile 128x256, BK=32, 4-stage cp.async pipeline, warp tile 64x64.
// mode 0: Cf = val
// mode 1: Cf = val + bias + residual
// mode 2: Ch = fp16(gelu(val + bias))
// mode 3: fused qkv: seg0 relu+eps->Cf(q), seg1 relu+eps->kOut, seg2 ->vOut
// ---------------------------------------------------------------------------
#define STAGE_BYTES 24576
#define NSTAGE 4
#define GEMM_SMEM (NSTAGE * STAGE_BYTES)

// swizzled 16B-chunk offset within an Rx32 fp16 tile (64B rows)
__device__ __forceinline__ uint32_t tile_off(int row, int chunk) {
    int sw = chunk ^ (row & 3) ^ ((row >> 2) & 1);
    return (uint32_t)(row * 64 + (sw << 4));
}

__device__ __forceinline__ void load_stage(
    uint32_t st, const char* A, const char* B,
    int K, int row0, int col0, int kc, int tid)
{
    size_t kb = (size_t)kc * 64;  // byte offset of 32-elem chunk within a row
    // A: 128 rows x 4 chunks
    #pragma unroll
    for (int i = 0; i < 2; i++) {
        int id = tid + 256 * i;
        int row = id >> 2, ch = id & 3;
        size_t ga = (size_t)(row0 + row) * K * 2 + kb + ch * 16;
        cp_async16(st + tile_off(row, ch), A + ga);
    }
    // B: 256 rows x 4 chunks
    #pragma unroll
    for (int i = 0; i < 4; i++) {
        int id = tid + 256 * i;
        int row = id >> 2, ch = id & 3;
        size_t gb = (size_t)(col0 + row) * K * 2 + kb + ch * 16;
        cp_async16(st + 8192 + tile_off(row, ch), B + gb);
    }
}

__global__ __launch_bounds__(256, 1) void mma_gemm_kernel(
    const __half* __restrict__ A, const __half* __restrict__ B,
    int M, int N, int K,
    float* __restrict__ Cf, const float* __restrict__ bias,
    const float* __restrict__ residual,
    __half* __restrict__ Ch,
    float* __restrict__ kOut, float* __restrict__ vOut, int mode)
{
    extern __shared__ char smem[];
    uint32_t sbase = smem_u32(smem);

    int tid = threadIdx.x;
    int wid = tid >> 5, l = tid & 31;
    int wr = wid >> 2, wc = wid & 3;   // 2x4 warp grid: 64x64 per warp
    int row0 = blockIdx.y * 128;
    int col0 = blockIdx.x * 256;
    int CH = K >> 5;

    const char* pA = (const char*)A;
    const char* pB = (const char*)B;

    float acc[4][8][4];
    #pragma unroll
    for (int i = 0; i < 4; i++)
        #pragma unroll
        for (int j = 0; j < 8; j++)
            #pragma unroll
            for (int t = 0; t < 4; t++) acc[i][j][t] = 0.f;

    // per-lane ldmatrix geometry
    int aRow = wr * 64 + (l & 15);
    int aHalf = (l >> 4) & 1;
    int bRowL = (l & 7) + ((l >> 4) & 1) * 8;
    int bHalf = (l >> 3) & 1;

    // prologue: stages 0..2
    load_stage(sbase,                   pA, pB, K, row0, col0, 0, tid);
    cp_commit();
    load_stage(sbase + STAGE_BYTES,     pA, pB, K, row0, col0, 1, tid);
    cp_commit();
    load_stage(sbase + 2 * STAGE_BYTES, pA, pB, K, row0, col0, 2, tid);
    cp_commit();

    for (int c = 0; c < CH; c++) {
        cp_wait<2>();
        __syncthreads();
        // tail-clamped prefetch: always one group per iteration
        int nc = c + 3 < CH ? c + 3 : CH - 1;
        load_stage(sbase + ((c + 3) & (NSTAGE - 1)) * STAGE_BYTES,
                   pA, pB, K, row0, col0, nc, tid);
        cp_commit();

        uint32_t st = sbase + (c & (NSTAGE - 1)) * STAGE_BYTES;
        #pragma unroll
        for (int ks = 0; ks < 2; ks++) {
            uint32_t af[4][4];
            #pragma unroll
            for (int mt = 0; mt < 4; mt++) {
                uint32_t off = tile_off(aRow + mt * 16, ks * 2 + aHalf);
                ldsm4(af[mt][0], af[mt][1], af[mt][2], af[mt][3], st + off);
            }
            uint32_t bf[8][2];
            #pragma unroll
            for (int p = 0; p < 4; p++) {
                uint32_t off = tile_off(wc * 64 + p * 16 + bRowL, ks * 2 + bHalf);
                ldsm4(bf[2*p][0], bf[2*p][1], bf[2*p+1][0], bf[2*p+1][1],
                      st + 8192 + off);
            }
            #pragma unroll
            for (int mt = 0; mt < 4; mt++)
                #pragma unroll
                for (int nt = 0; nt < 8; nt++)
                    mma16816(acc[mt][nt], af[mt], bf[nt][0], bf[nt][1]);
        }
    }

    // epilogue
    int rb = row0 + wr * 64 + (l >> 2);
    int cb = col0 + wc * 64 + (l & 3) * 2;

    if (mode == 3) {
        int seg = col0 >> 10;                 // tile fully inside one segment
        float* dst = (seg == 0) ? Cf : ((seg == 1) ? kOut : vOut);
        int csub = seg << 10;
        bool dorelu = (seg < 2);
        #pragma unroll
        for (int mt = 0; mt < 4; mt++)
            #pragma unroll
            for (int half = 0; half < 2; half++) {
                int r = rb + mt * 16 + half * 8;
                #pragma unroll
                for (int nt = 0; nt < 8; nt++) {
                    int ccol = cb + nt * 8 - csub;
                    float v0 = acc[mt][nt][half * 2];
                    float v1 = acc[mt][nt][half * 2 + 1];
                    if (dorelu) {
                        v0 = fmaxf(v0, 0.f) + 1e-6f;
                        v1 = fmaxf(v1, 0.f) + 1e-6f;
                    }
                    float2 o; o.x = v0; o.y = v1;
                    *reinterpret_cast<float2*>(dst + (size_t)r * 1024 + ccol) = o;
                }
            }
        return;
    }

    #pragma unroll
    for (int mt = 0; mt < 4; mt++) {
        #pragma unroll
        for (int half = 0; half < 2; half++) {
            int r = rb + mt * 16 + half * 8;
            #pragma unroll
            for (int nt = 0; nt < 8; nt++) {
                int ccol = cb + nt * 8;
                float v0 = acc[mt][nt][half * 2];
                float v1 = acc[mt][nt][half * 2 + 1];
                if (mode == 2) {
                    v0 += bias[ccol];
                    v1 += bias[ccol + 1];
                    v0 = 0.5f * v0 * (1.0f + erff(v0 * 0.70710678118654752f));
                    v1 = 0.5f * v1 * (1.0f + erff(v1 * 0.70710678118654752f));
                    *reinterpret_cast<__half2*>(Ch + (size_t)r * N + ccol) =
                        __halves2half2(__float2half_rn(v0), __float2half_rn(v1));
                } else {
                    if (mode == 1) {
                        v0 += bias[ccol];
                        v1 += bias[ccol + 1];
                        const float2 rr = *reinterpret_cast<const float2*>(
                            residual + (size_t)r * N + ccol);
                        v0 += rr.x; v1 += rr.y;
                    }
                    float2 o; o.x = v0; o.y = v1;
                    *reinterpret_cast<float2*>(Cf + (size_t)r * N + ccol) = o;
                }
            }
        }
    }
}

// ---------------------------------------------------------------------------
// kv partials + reduce
// ---------------------------------------------------------------------------
__global__ __launch_bounds__(256) void kv_kernel(const float* __restrict__ kf,
                                                 const float* __restrict__ vv,
                                                 float* __restrict__ kvp,
                                                 float* __restrict__ ksp)
{
    int bh = blockIdx.x;
    int b = bh >> 4, h = bh & 15;
    int chunk = blockIdx.y;

    __shared__ float ks[16][64];
    __shared__ float vs[16][64];
    int tid = threadIdx.x;
    int fq = tid >> 4, dq = tid & 15;
    int ln = tid >> 4, lc = (tid & 15) * 4;

    float acc[4][4];
    #pragma unroll
    for (int i = 0; i < 4; i++)
        #pragma unroll
        for (int j = 0; j < 4; j++) acc[i][j] = 0.f;
    float ksacc = 0.f;

    size_t base = (size_t)b * SS * DD + (size_t)h * 64;
    int nstart = chunk * 512;
    for (int n0 = nstart; n0 < nstart + 512; n0 += 16) {
        const float* kp = kf + base + (size_t)(n0 + ln) * DD + lc;
        const float* vp = vv + base + (size_t)(n0 + ln) * DD + lc;
        *reinterpret_cast<float4*>(&ks[ln][lc]) = *reinterpret_cast<const float4*>(kp);
        *reinterpret_cast<float4*>(&vs[ln][lc]) = *reinterpret_cast<const float4*>(vp);
        __syncthreads();
        #pragma unroll
        for (int nn = 0; nn < 16; nn++) {
            float rk[4], rv[4];
            #pragma unroll
            for (int i = 0; i < 4; i++) rk[i] = ks[nn][fq * 4 + i];
            #pragma unroll
            for (int j = 0; j < 4; j++) rv[j] = vs[nn][dq * 4 + j];
            #pragma unroll
            for (int i = 0; i < 4; i++)
                #pragma unroll
                for (int j = 0; j < 4; j++)
                    acc[i][j] = fmaf(rk[i], rv[j], acc[i][j]);
        }
        if (tid < 64) {
            #pragma unroll
            for (int nn = 0; nn < 16; nn++) ksacc += ks[nn][tid];
        }
        __syncthreads();
    }

    float* dst = kvp + (size_t)chunk * 64 * 4096 + (size_t)bh * 4096;
    #pragma unroll
    for (int i = 0; i < 4; i++)
        #pragma unroll
        for (int j = 0; j < 4; j++)
            dst[(fq * 4 + i) * 64 + dq * 4 + j] = acc[i][j];
    if (tid < 64)
        ksp[(size_t)chunk * 64 * 64 + bh * 64 + tid] = ksacc;
}

__global__ __launch_bounds__(256) void kv_reduce_kernel(const float* __restrict__ kvp,
                                                        const float* __restrict__ ksp,
                                                        float* __restrict__ kv,
                                                        float* __restrict__ ksum)
{
    int i = blockIdx.x * 256 + threadIdx.x;
    if (i < 64 * 4096) {
        float s = 0.f;
        #pragma unroll
        for (int c = 0; c < 8; c++) s += kvp[(size_t)c * 64 * 4096 + i];
        kv[i] = s;
    }
    if (i < 64 * 64) {
        float s = 0.f;
        #pragma unroll
        for (int c = 0; c < 8; c++) s += ksp[(size_t)c * 64 * 64 + i];
        ksum[i] = s;
    }
}

// ---------------------------------------------------------------------------
// attn: row -> (row @ kv[bh]) / (row . ksum[bh] + eps), written as fp16
// ---------------------------------------------------------------------------
__global__ __launch_bounds__(256) void attn_kernel(const float* __restrict__ qf,
                                                   const float* __restrict__ kv,
                                                   const float* __restrict__ ksum,
                                                   __half* __restrict__ o)
{
    __shared__ float kvS[64 * 64];
    __shared__ float ks[64];
    __shared__ float rowbuf[8][64];

    int bh = blockIdx.x;
    int b = bh >> 4, h = bh & 15;
    int tid = threadIdx.x, w = tid >> 5, l = tid & 31;

    for (int i = tid; i < 64 * 64; i += 256) kvS[i] = kv[(size_t)bh * 4096 + i];
    if (tid < 64) ks[tid] = ksum[bh * 64 + tid];
    __syncthreads();

    size_t base = (size_t)b * SS * DD + (size_t)h * 64;
    int n0 = blockIdx.y * 64 + w * 8;
    for (int r = 0; r < 8; r++) {
        const float* p = qf + base + (size_t)(n0 + r) * DD;
        rowbuf[w][l]      = p[l];
        rowbuf[w][l + 32] = p[l + 32];
        __syncwarp();
        float dsum = rowbuf[w][l] * ks[l] + rowbuf[w][l + 32] * ks[l + 32];
        #pragma unroll
        for (int off = 16; off > 0; off >>= 1)
            dsum += __shfl_xor_sync(0xffffffffu, dsum, off);
        float inv = 1.0f / (dsum + 1e-6f);
        float a0 = 0.f, a1 = 0.f;
        #pragma unroll
        for (int f = 0; f < 64; f++) {
            float qv = rowbuf[w][f];
            a0 = fmaf(qv, kvS[f * 64 + l],      a0);
            a1 = fmaf(qv, kvS[f * 64 + l + 32], a1);
        }
        __syncwarp();
        size_t i0 = base + (size_t)(n0 + r) * DD;
        o[i0 + l]      = __float2half_rn(a0 * inv);
        o[i0 + l + 32] = __float2half_rn(a1 * inv);
    }
}

// ---------------------------------------------------------------------------
// Launch
// ---------------------------------------------------------------------------
extern "C" void kernel_launch(void* const* d_in, const int* in_sizes, int n_in,
                              void* d_out, int out_size)
{
    const float* x     = (const float*)d_in[0];
    const float* ln1_g = (const float*)d_in[1];
    const float* ln1_b = (const float*)d_in[2];
    const float* wq    = (const float*)d_in[3];
    const float* wk    = (const float*)d_in[4];
    const float* wv    = (const float*)d_in[5];
    const float* proj  = (const float*)d_in[6];
    const float* wo    = (const float*)d_in[7];
    const float* bo    = (const float*)d_in[8];
    const float* ln2_g = (const float*)d_in[9];
    const float* ln2_b = (const float*)d_in[10];
    const float* w1    = (const float*)d_in[11];
    const float* b1    = (const float*)d_in[12];
    const float* w2    = (const float*)d_in[13];
    const float* b2    = (const float*)d_in[14];
    float* out = (float*)d_out;

    float *q, *k, *v, *kvp, *ksp, *kv, *ksum;
    __half *h, *at, *ffn, *wqkvT, *woT, *w1T, *w2T;
    cudaGetSymbolAddress((void**)&q, g_q);
    cudaGetSymbolAddress((void**)&k, g_k);
    cudaGetSymbolAddress((void**)&v, g_v);
    cudaGetSymbolAddress((void**)&kvp, g_kvp);
    cudaGetSymbolAddress((void**)&ksp, g_ksp);
    cudaGetSymbolAddress((void**)&kv, g_kv);
    cudaGetSymbolAddress((void**)&ksum, g_ksum);
    cudaGetSymbolAddress((void**)&h, g_h);
    cudaGetSymbolAddress((void**)&at, g_at);
    cudaGetSymbolAddress((void**)&ffn, g_ffn);
    cudaGetSymbolAddress((void**)&wqkvT, g_wqkvT);
    cudaGetSymbolAddress((void**)&woT, g_woT);
    cudaGetSymbolAddress((void**)&w1T, g_w1T);
    cudaGetSymbolAddress((void**)&w2T, g_w2T);

    cudaFuncSetAttribute(mma_gemm_kernel,
                         cudaFuncAttributeMaxDynamicSharedMemorySize, GEMM_SMEM);

    // --- weight prep ---
    float* tmp0 = q;                 // [1024*1024] fp32 temps, consumed pre-QKV
    float* tmp1 = q + 1024 * 1024;
    fold_kernel<<<dim3(DD / 64, HH), 256>>>(wq, proj, tmp0);
    fold_kernel<<<dim3(DD / 64, HH), 256>>>(wk, proj, tmp1);
    ts_kernel<<<dim3(DD / 32, DD / 32), 256>>>(tmp0, wqkvT,               DD, DD);
    ts_kernel<<<dim3(DD / 32, DD / 32), 256>>>(tmp1, wqkvT + 1024 * 1024, DD, DD);
    ts_kernel<<<dim3(DD / 32, DD / 32), 256>>>(wv,   wqkvT + 2048 * 1024, DD, DD);
    ts_kernel<<<dim3(DD / 32, DD / 32), 256>>>(wo, woT, DD, DD);
    ts_kernel<<<dim3(DFF / 32, DD / 32), 256>>>(w1, w1T, DD, DFF);
    ts_kernel<<<dim3(DD / 32, DFF / 32), 256>>>(w2, w2T, DFF, DD);

    // LN1 -> h (fp16)
    ln_kernel<<<NTOK, 256>>>(x, ln1_g, ln1_b, h);

    // Fused QKV GEMM: N=3072 -> q (relu+eps), k (relu+eps), v
    dim3 gQKV(3072 / 256, NTOK / 128);
    mma_gemm_kernel<<<gQKV, 256, GEMM_SMEM>>>(h, wqkvT,
        NTOK, 3072, DD, q, nullptr, nullptr, nullptr, k, v, 3);

    // kv / ksum
    kv_kernel<<<dim3(64, 8), 256>>>(k, v, kvp, ksp);
    kv_reduce_kernel<<<(64 * 4096 + 255) / 256, 256>>>(kvp, ksp, kv, ksum);

    // attn -> fp16
    attn_kernel<<<dim3(64, 64), 256>>>(q, kv, ksum, at);

    // x2 = x + attn @ wo + bo -> out (fp32)
    dim3 gD(DD / 256, NTOK / 128);
    mma_gemm_kernel<<<gD, 256, GEMM_SMEM>>>(at, woT,
        NTOK, DD, DD, out, bo, x, nullptr, nullptr, nullptr, 1);

    // LN2 -> h (fp16)
    ln_kernel<<<NTOK, 256>>>(out, ln2_g, ln2_b, h);

    // ffn = gelu(h2 @ w1 + b1) -> fp16
    dim3 gF1(DFF / 256, NTOK / 128);
    mma_gemm_kernel<<<gF1, 256, GEMM_SMEM>>>(h, w1T,
        NTOK, DFF, DD, nullptr, b1, nullptr, ffn, nullptr, nullptr, 2);

    // out = x2 + ffn @ w2 + b2 (in-place residual)
    mma_gemm_kernel<<<gD, 256, GEMM_SMEM>>>(ffn, w2T,
        NTOK, DD, DFF, out, b2, out, nullptr, nullptr, nullptr, 1);
}

// round 7
// speedup vs baseline: 6.5675x; 1.0622x over previous
#include <cuda_runtime.h>
#include <cuda_fp16.h>
#include <math.h>
#include <stdint.h>

// ---------------------------------------------------------------------------
// Problem constants
// ---------------------------------------------------------------------------
#define BB 4
#define SS 4096
#define DD 1024
#define HH 16
#define DH 64
#define FF 64
#define DFF 4096
#define NTOK (BB * SS)            // 16384 tokens

// ---------------------------------------------------------------------------
// Scratch (static device globals)
// ---------------------------------------------------------------------------
// g_q is float-typed for the weight-prep temps; q/k/v data itself is fp16
// (reinterpret-cast), written by the QKV GEMM epilogue.
__device__ float g_q[(size_t)NTOK * DD];
__device__ __half g_kbuf[(size_t)NTOK * DD];
__device__ __half g_vbuf[(size_t)NTOK * DD];
__device__ __half g_h[(size_t)NTOK * DD];      // LN out (A operand), fp16
__device__ __half g_at[(size_t)NTOK * DD];     // attn out (A of wo), fp16
__device__ __half g_ffn[(size_t)NTOK * DFF];   // gelu out (A of w2), fp16
// Transposed single-fp16 weights, [N, K]
__device__ __half g_wqkvT[3 * DD * DD];    // folded q, folded k, v
__device__ __half g_woT[DD * DD];
__device__ __half g_w1T[(size_t)DFF * DD];
__device__ __half g_w2T[(size_t)DD * DFF];
// linear-attention small tensors
__device__ float g_kvp[8 * 64 * FF * DH];
__device__ float g_ksp[8 * 64 * FF];
__device__ float g_kv[64 * FF * DH];
__device__ float g_ksum[64 * FF];

// ---------------------------------------------------------------------------
// PTX helpers (baseline PTX only — no 'a'-suffix features)
// ---------------------------------------------------------------------------
__device__ __forceinline__ uint32_t smem_u32(const void* p) {
    uint32_t a;
    asm("{ .reg .u64 t; cvta.to.shared.u64 t, %1; cvt.u32.u64 %0, t; }"
        : "=r"(a) : "l"(p));
    return a;
}
__device__ __forceinline__ void cp_async16(uint32_t dst, const void* src) {
    asm volatile("cp.async.cg.shared.global [%0], [%1], 16;\n" :: "r"(dst), "l"(src));
}
__device__ __forceinline__ void cp_commit() {
    asm volatile("cp.async.commit_group;\n" ::: "memory");
}
template <int N>
__device__ __forceinline__ void cp_wait() {
    asm volatile("cp.async.wait_group %0;\n" :: "n"(N) : "memory");
}
__device__ __forceinline__ void ldsm4(uint32_t& r0, uint32_t& r1, uint32_t& r2,
                                      uint32_t& r3, uint32_t addr) {
    asm volatile("ldmatrix.sync.aligned.m8n8.x4.shared.b16 {%0,%1,%2,%3}, [%4];"
                 : "=r"(r0), "=r"(r1), "=r"(r2), "=r"(r3) : "r"(addr));
}
__device__ __forceinline__ void mma16816(float* c, const uint32_t* a,
                                         uint32_t b0, uint32_t b1) {
    asm volatile(
        "mma.sync.aligned.m16n8k16.row.col.f32.f16.f16.f32 "
        "{%0,%1,%2,%3}, {%4,%5,%6,%7}, {%8,%9}, {%0,%1,%2,%3};"
        : "+f"(c[0]), "+f"(c[1]), "+f"(c[2]), "+f"(c[3])
        : "r"(a[0]), "r"(a[1]), "r"(a[2]), "r"(a[3]), "r"(b0), "r"(b1));
}

// ---------------------------------------------------------------------------
// Fold proj into a QK weight: out[d, h*64+f] = sum_dh W[d, h*64+dh]*proj[dh,f]
// ---------------------------------------------------------------------------
__global__ __launch_bounds__(256) void fold_kernel(const float* __restrict__ W,
                                                   const float* __restrict__ proj,
                                                   float* __restrict__ outW)
{
    __shared__ float projS[64][64];
    __shared__ float wS[64][65];
    int d0 = blockIdx.x * 64, h = blockIdx.y;
    int tid = threadIdx.x;
    for (int i = tid; i < 64 * 64; i += 256)
        projS[i >> 6][i & 63] = proj[i];
    for (int i = tid; i < 64 * 64; i += 256)
        wS[i >> 6][i & 63] = W[(size_t)(d0 + (i >> 6)) * (HH * DH) + h * 64 + (i & 63)];
    __syncthreads();
    int r = tid >> 2;
    int fb = (tid & 3) * 16;
    float acc[16];
    #pragma unroll
    for (int i = 0; i < 16; i++) acc[i] = 0.f;
    #pragma unroll 8
    for (int c = 0; c < 64; c++) {
        float w = wS[r][c];
        #pragma unroll
        for (int i = 0; i < 16; i++)
            acc[i] = fmaf(w, projS[c][fb + i], acc[i]);
    }
    for (int i = 0; i < 16; i++)
        outW[(size_t)(d0 + r) * (HH * FF) + h * 64 + fb + i] = acc[i];
}

// ---------------------------------------------------------------------------
// Weight transpose + fp16 convert:  W[K,N] -> Wt[N,K]
// ---------------------------------------------------------------------------
__global__ __launch_bounds__(256) void ts_kernel(const float* __restrict__ W,
                                                 __half* __restrict__ o,
                                                 int K, int N)
{
    __shared__ float t[32][33];
    int n0 = blockIdx.x * 32, k0 = blockIdx.y * 32;
    int tx = threadIdx.x & 31, ty = threadIdx.x >> 5;
    for (int r = ty; r < 32; r += 8)
        t[r][tx] = W[(size_t)(k0 + r) * N + n0 + tx];
    __syncthreads();
    for (int r = ty; r < 32; r += 8)
        o[(size_t)(n0 + r) * K + k0 + tx] = __float2half_rn(t[tx][r]);
}

// ---------------------------------------------------------------------------
// LayerNorm -> fp16. One block (256 thr) per row of 1024.
// ---------------------------------------------------------------------------
__global__ __launch_bounds__(256) void ln_kernel(const float* __restrict__ x,
                                                 const float* __restrict__ g,
                                                 const float* __restrict__ b,
                                                 __half* __restrict__ o)
{
    int row = blockIdx.x;
    int t = threadIdx.x;
    const float4* xr = reinterpret_cast<const float4*>(x + (size_t)row * DD);
    float4 xv = xr[t];

    float s  = xv.x + xv.y + xv.z + xv.w;
    float s2 = xv.x*xv.x + xv.y*xv.y + xv.z*xv.z + xv.w*xv.w;

    __shared__ float red[2][8];
    #pragma unroll
    for (int off = 16; off > 0; off >>= 1) {
        s  += __shfl_xor_sync(0xffffffffu, s,  off);
        s2 += __shfl_xor_sync(0xffffffffu, s2, off);
    }
    int w = t >> 5, l = t & 31;
    if (l == 0) { red[0][w] = s; red[1][w] = s2; }
    __syncthreads();
    __shared__ float smu, srstd;
    if (t == 0) {
        float ts = 0.f, ts2 = 0.f;
        #pragma unroll
        for (int i = 0; i < 8; i++) { ts += red[0][i]; ts2 += red[1][i]; }
        float mu = ts * (1.0f / DD);
        float var = ts2 * (1.0f / DD) - mu * mu;
        smu = mu;
        srstd = rsqrtf(var + 1e-5f);
    }
    __syncthreads();
    float mu = smu, rstd = srstd;

    const float4 gv = reinterpret_cast<const float4*>(g)[t];
    const float4 bv = reinterpret_cast<const float4*>(b)[t];
    float o0 = (xv.x - mu) * rstd * gv.x + bv.x;
    float o1 = (xv.y - mu) * rstd * gv.y + bv.y;
    float o2 = (xv.z - mu) * rstd * gv.z + bv.z;
    float o3 = (xv.w - mu) * rstd * gv.w + bv.w;
    size_t idx = (size_t)row * DD + t * 4;
    __half2 p0 = __halves2half2(__float2half_rn(o0), __float2half_rn(o1));
    __half2 p1 = __halves2half2(__float2half_rn(o2), __float2half_rn(o3));
    *reinterpret_cast<__half2*>(o + idx)     = p0;
    *reinterpret_cast<__half2*>(o + idx + 2) = p1;
}

// ---------------------------------------------------------------------------
// HMMA GEMM: C[M,N] = A @ B^T, fp16 inputs, fp32 accum.
// Tile 128x256, BK=32, 4-stage cp.async pipeline, 512 threads,
// 16 warps in 2x8 grid, warp tile 64x32 (better SMSP latency hiding).
// mode 0: Cf = val
// mode 1: Cf = val + bias + residual
// mode 2: Ch = fp16(gelu(val + bias))
// mode 3: fused qkv (fp16 outs): seg0 relu+eps->qOut, seg1 relu+eps->kOut,
//         seg2 ->vOut  (out stride 1024)
// ---------------------------------------------------------------------------
#define STAGE_BYTES 24576
#define NSTAGE 4
#define GEMM_SMEM (NSTAGE * STAGE_BYTES)
#define GTHREADS 512

// swizzled 16B-chunk offset within an Rx32 fp16 tile (64B rows)
__device__ __forceinline__ uint32_t tile_off(int row, int chunk) {
    int sw = chunk ^ (row & 3) ^ ((row >> 2) & 1);
    return (uint32_t)(row * 64 + (sw << 4));
}

__device__ __forceinline__ void load_stage(
    uint32_t st, const char* A, const char* B,
    int K, int row0, int col0, int kc, int tid)
{
    size_t kb = (size_t)kc * 64;  // byte offset of 32-elem chunk within a row
    // A: 128 rows x 4 chunks = 512 chunks, 1/thread
    {
        int row = tid >> 2, ch = tid & 3;
        size_t ga = (size_t)(row0 + row) * K * 2 + kb + ch * 16;
        cp_async16(st + tile_off(row, ch), A + ga);
    }
    // B: 256 rows x 4 chunks = 1024 chunks, 2/thread
    #pragma unroll
    for (int i = 0; i < 2; i++) {
        int id = tid + GTHREADS * i;
        int row = id >> 2, ch = id & 3;
        size_t gb = (size_t)(col0 + row) * K * 2 + kb + ch * 16;
        cp_async16(st + 8192 + tile_off(row, ch), B + gb);
    }
}

__global__ __launch_bounds__(GTHREADS, 1) void mma_gemm_kernel(
    const __half* __restrict__ A, const __half* __restrict__ B,
    int M, int N, int K,
    float* __restrict__ Cf, const float* __restrict__ bias,
    const float* __restrict__ residual,
    __half* __restrict__ Ch,
    __half* __restrict__ kOut, __half* __restrict__ vOut, int mode)
{
    extern __shared__ char smem[];
    uint32_t sbase = smem_u32(smem);

    int tid = threadIdx.x;
    int wid = tid >> 5, l = tid & 31;
    int wr = wid >> 3, wc = wid & 7;   // 2x8 warp grid: 64x32 per warp
    int row0 = blockIdx.y * 128;
    int col0 = blockIdx.x * 256;
    int CH = K >> 5;

    const char* pA = (const char*)A;
    const char* pB = (const char*)B;

    float acc[4][4][4];
    #pragma unroll
    for (int i = 0; i < 4; i++)
        #pragma unroll
        for (int j = 0; j < 4; j++)
            #pragma unroll
            for (int t = 0; t < 4; t++) acc[i][j][t] = 0.f;

    // per-lane ldmatrix geometry
    int aRow = wr * 64 + (l & 15);
    int aHalf = (l >> 4) & 1;
    int bRowL = (l & 7) + ((l >> 4) & 1) * 8;
    int bHalf = (l >> 3) & 1;

    // prologue: stages 0..2
    load_stage(sbase,                   pA, pB, K, row0, col0, 0, tid);
    cp_commit();
    load_stage(sbase + STAGE_BYTES,     pA, pB, K, row0, col0, 1, tid);
    cp_commit();
    load_stage(sbase + 2 * STAGE_BYTES, pA, pB, K, row0, col0, 2, tid);
    cp_commit();

    for (int c = 0; c < CH; c++) {
        cp_wait<2>();
        __syncthreads();
        // tail-clamped prefetch: always one group per iteration
        int nc = c + 3 < CH ? c + 3 : CH - 1;
        load_stage(sbase + ((c + 3) & (NSTAGE - 1)) * STAGE_BYTES,
                   pA, pB, K, row0, col0, nc, tid);
        cp_commit();

        uint32_t st = sbase + (c & (NSTAGE - 1)) * STAGE_BYTES;
        #pragma unroll
        for (int ks = 0; ks < 2; ks++) {
            uint32_t af[4][4];
            #pragma unroll
            for (int mt = 0; mt < 4; mt++) {
                uint32_t off = tile_off(aRow + mt * 16, ks * 2 + aHalf);
                ldsm4(af[mt][0], af[mt][1], af[mt][2], af[mt][3], st + off);
            }
            uint32_t bf[4][2];
            #pragma unroll
            for (int p = 0; p < 2; p++) {
                uint32_t off = tile_off(wc * 32 + p * 16 + bRowL, ks * 2 + bHalf);
                ldsm4(bf[2*p][0], bf[2*p][1], bf[2*p+1][0], bf[2*p+1][1],
                      st + 8192 + off);
            }
            #pragma unroll
            for (int mt = 0; mt < 4; mt++)
                #pragma unroll
                for (int nt = 0; nt < 4; nt++)
                    mma16816(acc[mt][nt], af[mt], bf[nt][0], bf[nt][1]);
        }
    }

    // epilogue
    int rb = row0 + wr * 64 + (l >> 2);
    int cb = col0 + wc * 32 + (l & 3) * 2;

    if (mode == 3) {
        int seg = col0 >> 10;                 // tile fully inside one segment
        __half* dst = (seg == 0) ? Ch : ((seg == 1) ? kOut : vOut);
        int csub = seg << 10;
        bool dorelu = (seg < 2);
        #pragma unroll
        for (int mt = 0; mt < 4; mt++)
            #pragma unroll
            for (int half = 0; half < 2; half++) {
                int r = rb + mt * 16 + half * 8;
                #pragma unroll
                for (int nt = 0; nt < 4; nt++) {
                    int ccol = cb + nt * 8 - csub;
                    float v0 = acc[mt][nt][half * 2];
                    float v1 = acc[mt][nt][half * 2 + 1];
                    if (dorelu) {
                        v0 = fmaxf(v0, 0.f) + 1e-6f;
                        v1 = fmaxf(v1, 0.f) + 1e-6f;
                    }
                    *reinterpret_cast<__half2*>(dst + (size_t)r * 1024 + ccol) =
                        __halves2half2(__float2half_rn(v0), __float2half_rn(v1));
                }
            }
        return;
    }

    #pragma unroll
    for (int mt = 0; mt < 4; mt++) {
        #pragma unroll
        for (int half = 0; half < 2; half++) {
            int r = rb + mt * 16 + half * 8;
            #pragma unroll
            for (int nt = 0; nt < 4; nt++) {
                int ccol = cb + nt * 8;
                float v0 = acc[mt][nt][half * 2];
                float v1 = acc[mt][nt][half * 2 + 1];
                if (mode == 2) {
                    v0 += bias[ccol];
                    v1 += bias[ccol + 1];
                    v0 = 0.5f * v0 * (1.0f + erff(v0 * 0.70710678118654752f));
                    v1 = 0.5f * v1 * (1.0f + erff(v1 * 0.70710678118654752f));
                    *reinterpret_cast<__half2*>(Ch + (size_t)r * N + ccol) =
                        __halves2half2(__float2half_rn(v0), __float2half_rn(v1));
                } else {
                    if (mode == 1) {
                        v0 += bias[ccol];
                        v1 += bias[ccol + 1];
                        const float2 rr = *reinterpret_cast<const float2*>(
                            residual + (size_t)r * N + ccol);
                        v0 += rr.x; v1 += rr.y;
                    }
                    float2 o; o.x = v0; o.y = v1;
                    *reinterpret_cast<float2*>(Cf + (size_t)r * N + ccol) = o;
                }
            }
        }
    }
}

// ---------------------------------------------------------------------------
// kv partials + reduce (fp16 inputs, fp32 accum)
// ---------------------------------------------------------------------------
__global__ __launch_bounds__(256) void kv_kernel(const __half* __restrict__ kf,
                                                 const __half* __restrict__ vv,
                                                 float* __restrict__ kvp,
                                                 float* __restrict__ ksp)
{
    int bh = blockIdx.x;
    int b = bh >> 4, h = bh & 15;
    int chunk = blockIdx.y;

    __shared__ float ks[16][64];
    __shared__ float vs[16][64];
    int tid = threadIdx.x;
    int fq = tid >> 4, dq = tid & 15;
    int ln = tid >> 4, lc = (tid & 15) * 4;

    float acc[4][4];
    #pragma unroll
    for (int i = 0; i < 4; i++)
        #pragma unroll
        for (int j = 0; j < 4; j++) acc[i][j] = 0.f;
    float ksacc = 0.f;

    size_t base = (size_t)b * SS * DD + (size_t)h * 64;
    int nstart = chunk * 512;
    for (int n0 = nstart; n0 < nstart + 512; n0 += 16) {
        const __half* kp = kf + base + (size_t)(n0 + ln) * DD + lc;
        const __half* vp = vv + base + (size_t)(n0 + ln) * DD + lc;
        __half2 k01 = *reinterpret_cast<const __half2*>(kp);
        __half2 k23 = *reinterpret_cast<const __half2*>(kp + 2);
        __half2 v01 = *reinterpret_cast<const __half2*>(vp);
        __half2 v23 = *reinterpret_cast<const __half2*>(vp + 2);
        float2 kf01 = __half22float2(k01), kf23 = __half22float2(k23);
        float2 vf01 = __half22float2(v01), vf23 = __half22float2(v23);
        ks[ln][lc] = kf01.x; ks[ln][lc+1] = kf01.y; ks[ln][lc+2] = kf23.x; ks[ln][lc+3] = kf23.y;
        vs[ln][lc] = vf01.x; vs[ln][lc+1] = vf01.y; vs[ln][lc+2] = vf23.x; vs[ln][lc+3] = vf23.y;
        __syncthreads();
        #pragma unroll
        for (int nn = 0; nn < 16; nn++) {
            float rk[4], rv[4];
            #pragma unroll
            for (int i = 0; i < 4; i++) rk[i] = ks[nn][fq * 4 + i];
            #pragma unroll
            for (int j = 0; j < 4; j++) rv[j] = vs[nn][dq * 4 + j];
            #pragma unroll
            for (int i = 0; i < 4; i++)
                #pragma unroll
                for (int j = 0; j < 4; j++)
                    acc[i][j] = fmaf(rk[i], rv[j], acc[i][j]);
        }
        if (tid < 64) {
            #pragma unroll
            for (int nn = 0; nn < 16; nn++) ksacc += ks[nn][tid];
        }
        __syncthreads();
    }

    float* dst = kvp + (size_t)chunk * 64 * 4096 + (size_t)bh * 4096;
    #pragma unroll
    for (int i = 0; i < 4; i++)
        #pragma unroll
        for (int j = 0; j < 4; j++)
            dst[(fq * 4 + i) * 64 + dq * 4 + j] = acc[i][j];
    if (tid < 64)
        ksp[(size_t)chunk * 64 * 64 + bh * 64 + tid] = ksacc;
}

__global__ __launch_bounds__(256) void kv_reduce_kernel(const float* __restrict__ kvp,
                                                        const float* __restrict__ ksp,
                                                        float* __restrict__ kv,
                                                        float* __restrict__ ksum)
{
    int i = blockIdx.x * 256 + threadIdx.x;
    if (i < 64 * 4096) {
        float s = 0.f;
        #pragma unroll
        for (int c = 0; c < 8; c++) s += kvp[(size_t)c * 64 * 4096 + i];
        kv[i] = s;
    }
    if (i < 64 * 64) {
        float s = 0.f;
        #pragma unroll
        for (int c = 0; c < 8; c++) s += ksp[(size_t)c * 64 * 64 + i];
        ksum[i] = s;
    }
}

// ---------------------------------------------------------------------------
// attn: row -> (row @ kv[bh]) / (row . ksum[bh] + eps), fp16 in, fp16 out
// ---------------------------------------------------------------------------
__global__ __launch_bounds__(256) void attn_kernel(const __half* __restrict__ qf,
                                                   const float* __restrict__ kv,
                                                   const float* __restrict__ ksum,
                                                   __half* __restrict__ o)
{
    __shared__ float kvS[64 * 64];
    __shared__ float ks[64];
    __shared__ float rowbuf[8][64];

    int bh = blockIdx.x;
    int b = bh >> 4, h = bh & 15;
    int tid = threadIdx.x, w = tid >> 5, l = tid & 31;

    for (int i = tid; i < 64 * 64; i += 256) kvS[i] = kv[(size_t)bh * 4096 + i];
    if (tid < 64) ks[tid] = ksum[bh * 64 + tid];
    __syncthreads();

    size_t base = (size_t)b * SS * DD + (size_t)h * 64;
    int n0 = blockIdx.y * 64 + w * 8;
    for (int r = 0; r < 8; r++) {
        const __half* p = qf + base + (size_t)(n0 + r) * DD;
        rowbuf[w][l]      = __half2float(p[l]);
        rowbuf[w][l + 32] = __half2float(p[l + 32]);
        __syncwarp();
        float dsum = rowbuf[w][l] * ks[l] + rowbuf[w][l + 32] * ks[l + 32];
        #pragma unroll
        for (int off = 16; off > 0; off >>= 1)
            dsum += __shfl_xor_sync(0xffffffffu, dsum, off);
        float inv = 1.0f / (dsum + 1e-6f);
        float a0 = 0.f, a1 = 0.f;
        #pragma unroll
        for (int f = 0; f < 64; f++) {
            float qv = rowbuf[w][f];
            a0 = fmaf(qv, kvS[f * 64 + l],      a0);
            a1 = fmaf(qv, kvS[f * 64 + l + 32], a1);
        }
        __syncwarp();
        size_t i0 = base + (size_t)(n0 + r) * DD;
        o[i0 + l]      = __float2half_rn(a0 * inv);
        o[i0 + l + 32] = __float2half_rn(a1 * inv);
    }
}

// ---------------------------------------------------------------------------
// Launch
// ---------------------------------------------------------------------------
extern "C" void kernel_launch(void* const* d_in, const int* in_sizes, int n_in,
                              void* d_out, int out_size)
{
    const float* x     = (const float*)d_in[0];
    const float* ln1_g = (const float*)d_in[1];
    const float* ln1_b = (const float*)d_in[2];
    const float* wq    = (const float*)d_in[3];
    const float* wk    = (const float*)d_in[4];
    const float* wv    = (const float*)d_in[5];
    const float* proj  = (const float*)d_in[6];
    const float* wo    = (const float*)d_in[7];
    const float* bo    = (const float*)d_in[8];
    const float* ln2_g = (const float*)d_in[9];
    const float* ln2_b = (const float*)d_in[10];
    const float* w1    = (const float*)d_in[11];
    const float* b1    = (const float*)d_in[12];
    const float* w2    = (const float*)d_in[13];
    const float* b2    = (const float*)d_in[14];
    float* out = (float*)d_out;

    float *qraw, *kvp, *ksp, *kv, *ksum;
    __half *kbuf, *vbuf, *h, *at, *ffn, *wqkvT, *woT, *w1T, *w2T;
    cudaGetSymbolAddress((void**)&qraw, g_q);
    cudaGetSymbolAddress((void**)&kbuf, g_kbuf);
    cudaGetSymbolAddress((void**)&vbuf, g_vbuf);
    cudaGetSymbolAddress((void**)&kvp, g_kvp);
    cudaGetSymbolAddress((void**)&ksp, g_ksp);
    cudaGetSymbolAddress((void**)&kv, g_kv);
    cudaGetSymbolAddress((void**)&ksum, g_ksum);
    cudaGetSymbolAddress((void**)&h, g_h);
    cudaGetSymbolAddress((void**)&at, g_at);
    cudaGetSymbolAddress((void**)&ffn, g_ffn);
    cudaGetSymbolAddress((void**)&wqkvT, g_wqkvT);
    cudaGetSymbolAddress((void**)&woT, g_woT);
    cudaGetSymbolAddress((void**)&w1T, g_w1T);
    cudaGetSymbolAddress((void**)&w2T, g_w2T);
    __half* qbuf = (__half*)qraw;   // fp16 q view (64MB float buffer, 32MB used)

    cudaFuncSetAttribute(mma_gemm_kernel,
                         cudaFuncAttributeMaxDynamicSharedMemorySize, GEMM_SMEM);

    // --- weight prep ---
    // fp32 temps live in the BACK half of g_q (front 32MB is the fp16 q view)
    float* tmp0 = qraw + 8 * 1024 * 1024;   // [1024*1024]
    float* tmp1 = qraw + 9 * 1024 * 1024;   // [1024*1024]
    fold_kernel<<<dim3(DD / 64, HH), 256>>>(wq, proj, tmp0);
    fold_kernel<<<dim3(DD / 64, HH), 256>>>(wk, proj, tmp1);
    ts_kernel<<<dim3(DD / 32, DD / 32), 256>>>(tmp0, wqkvT,               DD, DD);
    ts_kernel<<<dim3(DD / 32, DD / 32), 256>>>(tmp1, wqkvT + 1024 * 1024, DD, DD);
    ts_kernel<<<dim3(DD / 32, DD / 32), 256>>>(wv,   wqkvT + 2048 * 1024, DD, DD);
    ts_kernel<<<dim3(DD / 32, DD / 32), 256>>>(wo, woT, DD, DD);
    ts_kernel<<<dim3(DFF / 32, DD / 32), 256>>>(w1, w1T, DD, DFF);
    ts_kernel<<<dim3(DD / 32, DFF / 32), 256>>>(w2, w2T, DFF, DD);

    // LN1 -> h (fp16)
    ln_kernel<<<NTOK, 256>>>(x, ln1_g, ln1_b, h);

    // Fused QKV GEMM: N=3072 -> q (relu+eps), k (relu+eps), v  (all fp16)
    dim3 gQKV(3072 / 256, NTOK / 128);
    mma_gemm_kernel<<<gQKV, GTHREADS, GEMM_SMEM>>>(h, wqkvT,
        NTOK, 3072, DD, nullptr, nullptr, nullptr, qbuf, kbuf, vbuf, 3);

    // kv / ksum
    kv_kernel<<<dim3(64, 8), 256>>>(kbuf, vbuf, kvp, ksp);
    kv_reduce_kernel<<<(64 * 4096 + 255) / 256, 256>>>(kvp, ksp, kv, ksum);

    // attn -> fp16
    attn_kernel<<<dim3(64, 64), 256>>>(qbuf, kv, ksum, at);

    // x2 = x + attn @ wo + bo -> out (fp32)
    dim3 gD(DD / 256, NTOK / 128);
    mma_gemm_kernel<<<gD, GTHREADS, GEMM_SMEM>>>(at, woT,
        NTOK, DD, DD, out, bo, x, nullptr, nullptr, nullptr, 1);

    // LN2 -> h (fp16)
    ln_kernel<<<NTOK, 256>>>(out, ln2_g, ln2_b, h);

    // ffn = gelu(h2 @ w1 + b1) -> fp16
    dim3 gF1(DFF / 256, NTOK / 128);
    mma_gemm_kernel<<<gF1, GTHREADS, GEMM_SMEM>>>(h, w1T,
        NTOK, DFF, DD, nullptr, b1, nullptr, ffn, nullptr, nullptr, 2);

    // out = x2 + ffn @ w2 + b2 (in-place residual)
    mma_gemm_kernel<<<gD, GTHREADS, GEMM_SMEM>>>(ffn, w2T,
        NTOK, DD, DFF, out, b2, out, nullptr, nullptr, nullptr, 1);
}

// round 8
// speedup vs baseline: 6.9040x; 1.0512x over previous
#include <cuda_runtime.h>
#include <cuda_fp16.h>
#include <math.h>
#include <stdint.h>

// ---------------------------------------------------------------------------
// Problem constants
// ---------------------------------------------------------------------------
#define BB 4
#define SS 4096
#define DD 1024
#define HH 16
#define DH 64
#define FF 64
#define DFF 4096
#define NTOK (BB * SS)            // 16384 tokens

// ---------------------------------------------------------------------------
// Scratch (static device globals)
// ---------------------------------------------------------------------------
__device__ float g_q[(size_t)NTOK * DD];       // fp16 q view + fp32 prep temps
__device__ __half g_kbuf[(size_t)NTOK * DD];
__device__ __half g_vbuf[(size_t)NTOK * DD];
__device__ __half g_h[(size_t)NTOK * DD];      // LN out (A operand), fp16
__device__ __half g_at[(size_t)NTOK * DD];     // attn out (A of wo), fp16
__device__ __half g_ffn[(size_t)NTOK * DFF];   // gelu out (A of w2), fp16
// Transposed single-fp16 weights, [N, K]
__device__ __half g_wqkvT[3 * DD * DD];    // folded q, folded k, v
__device__ __half g_woT[DD * DD];
__device__ __half g_w1T[(size_t)DFF * DD];
__device__ __half g_w2T[(size_t)DD * DFF];
// linear-attention small tensors
__device__ float g_kvp[8 * 64 * FF * DH];
__device__ float g_ksp[8 * 64 * FF];
__device__ float g_kv[64 * FF * DH];
__device__ float g_ksum[64 * FF];

// ---------------------------------------------------------------------------
// PTX helpers (baseline PTX only — no 'a'-suffix features)
// ---------------------------------------------------------------------------
__device__ __forceinline__ uint32_t smem_u32(const void* p) {
    uint32_t a;
    asm("{ .reg .u64 t; cvta.to.shared.u64 t, %1; cvt.u32.u64 %0, t; }"
        : "=r"(a) : "l"(p));
    return a;
}
__device__ __forceinline__ void cp_async16(uint32_t dst, const void* src) {
    asm volatile("cp.async.cg.shared.global [%0], [%1], 16;\n" :: "r"(dst), "l"(src));
}
__device__ __forceinline__ void cp_commit() {
    asm volatile("cp.async.commit_group;\n" ::: "memory");
}
template <int N>
__device__ __forceinline__ void cp_wait() {
    asm volatile("cp.async.wait_group %0;\n" :: "n"(N) : "memory");
}
__device__ __forceinline__ void ldsm4(uint32_t& r0, uint32_t& r1, uint32_t& r2,
                                      uint32_t& r3, uint32_t addr) {
    asm volatile("ldmatrix.sync.aligned.m8n8.x4.shared.b16 {%0,%1,%2,%3}, [%4];"
                 : "=r"(r0), "=r"(r1), "=r"(r2), "=r"(r3) : "r"(addr));
}
__device__ __forceinline__ void mma16816(float* c, const uint32_t* a,
                                         uint32_t b0, uint32_t b1) {
    asm volatile(
        "mma.sync.aligned.m16n8k16.row.col.f32.f16.f16.f32 "
        "{%0,%1,%2,%3}, {%4,%5,%6,%7}, {%8,%9}, {%0,%1,%2,%3};"
        : "+f"(c[0]), "+f"(c[1]), "+f"(c[2]), "+f"(c[3])
        : "r"(a[0]), "r"(a[1]), "r"(a[2]), "r"(a[3]), "r"(b0), "r"(b1));
}

// ---------------------------------------------------------------------------
// Fold proj into a QK weight: out[d, h*64+f] = sum_dh W[d, h*64+dh]*proj[dh,f]
// ---------------------------------------------------------------------------
__global__ __launch_bounds__(256) void fold_kernel(const float* __restrict__ W,
                                                   const float* __restrict__ proj,
                                                   float* __restrict__ outW)
{
    __shared__ float projS[64][64];
    __shared__ float wS[64][65];
    int d0 = blockIdx.x * 64, h = blockIdx.y;
    int tid = threadIdx.x;
    for (int i = tid; i < 64 * 64; i += 256)
        projS[i >> 6][i & 63] = proj[i];
    for (int i = tid; i < 64 * 64; i += 256)
        wS[i >> 6][i & 63] = W[(size_t)(d0 + (i >> 6)) * (HH * DH) + h * 64 + (i & 63)];
    __syncthreads();
    int r = tid >> 2;
    int fb = (tid & 3) * 16;
    float acc[16];
    #pragma unroll
    for (int i = 0; i < 16; i++) acc[i] = 0.f;
    #pragma unroll 8
    for (int c = 0; c < 64; c++) {
        float w = wS[r][c];
        #pragma unroll
        for (int i = 0; i < 16; i++)
            acc[i] = fmaf(w, projS[c][fb + i], acc[i]);
    }
    for (int i = 0; i < 16; i++)
        outW[(size_t)(d0 + r) * (HH * FF) + h * 64 + fb + i] = acc[i];
}

// ---------------------------------------------------------------------------
// Weight transpose + fp16 convert:  W[K,N] -> Wt[N,K]
// ---------------------------------------------------------------------------
__global__ __launch_bounds__(256) void ts_kernel(const float* __restrict__ W,
                                                 __half* __restrict__ o,
                                                 int K, int N)
{
    __shared__ float t[32][33];
    int n0 = blockIdx.x * 32, k0 = blockIdx.y * 32;
    int tx = threadIdx.x & 31, ty = threadIdx.x >> 5;
    for (int r = ty; r < 32; r += 8)
        t[r][tx] = W[(size_t)(k0 + r) * N + n0 + tx];
    __syncthreads();
    for (int r = ty; r < 32; r += 8)
        o[(size_t)(n0 + r) * K + k0 + tx] = __float2half_rn(t[tx][r]);
}

// ---------------------------------------------------------------------------
// LayerNorm -> fp16. One block (256 thr) per row of 1024.
// ---------------------------------------------------------------------------
__global__ __launch_bounds__(256) void ln_kernel(const float* __restrict__ x,
                                                 const float* __restrict__ g,
                                                 const float* __restrict__ b,
                                                 __half* __restrict__ o)
{
    int row = blockIdx.x;
    int t = threadIdx.x;
    const float4* xr = reinterpret_cast<const float4*>(x + (size_t)row * DD);
    float4 xv = xr[t];

    float s  = xv.x + xv.y + xv.z + xv.w;
    float s2 = xv.x*xv.x + xv.y*xv.y + xv.z*xv.z + xv.w*xv.w;

    __shared__ float red[2][8];
    #pragma unroll
    for (int off = 16; off > 0; off >>= 1) {
        s  += __shfl_xor_sync(0xffffffffu, s,  off);
        s2 += __shfl_xor_sync(0xffffffffu, s2, off);
    }
    int w = t >> 5, l = t & 31;
    if (l == 0) { red[0][w] = s; red[1][w] = s2; }
    __syncthreads();
    __shared__ float smu, srstd;
    if (t == 0) {
        float ts = 0.f, ts2 = 0.f;
        #pragma unroll
        for (int i = 0; i < 8; i++) { ts += red[0][i]; ts2 += red[1][i]; }
        float mu = ts * (1.0f / DD);
        float var = ts2 * (1.0f / DD) - mu * mu;
        smu = mu;
        srstd = rsqrtf(var + 1e-5f);
    }
    __syncthreads();
    float mu = smu, rstd = srstd;

    const float4 gv = reinterpret_cast<const float4*>(g)[t];
    const float4 bv = reinterpret_cast<const float4*>(b)[t];
    float o0 = (xv.x - mu) * rstd * gv.x + bv.x;
    float o1 = (xv.y - mu) * rstd * gv.y + bv.y;
    float o2 = (xv.z - mu) * rstd * gv.z + bv.z;
    float o3 = (xv.w - mu) * rstd * gv.w + bv.w;
    size_t idx = (size_t)row * DD + t * 4;
    __half2 p0 = __halves2half2(__float2half_rn(o0), __float2half_rn(o1));
    __half2 p1 = __halves2half2(__float2half_rn(o2), __float2half_rn(o3));
    *reinterpret_cast<__half2*>(o + idx)     = p0;
    *reinterpret_cast<__half2*>(o + idx + 2) = p1;
}

// ---------------------------------------------------------------------------
// HMMA GEMM: C[M,N] = A @ B^T, fp16 inputs, fp32 accum.
// Tile 128x256, BK=64, 4-stage cp.async pipeline, 256 threads,
// 8 warps in 2x4 grid, warp tile 64x64 (min smem traffic for 8 warps).
// mode 0: Cf = val
// mode 1: Cf = val + bias + residual
// mode 2: Ch = fp16(gelu(val + bias))
// mode 3: fused qkv (fp16 outs): seg0 relu+eps->qOut, seg1 relu+eps->kOut,
//         seg2 ->vOut  (out stride 1024)
// ---------------------------------------------------------------------------
#define STAGE_BYTES 49152
#define NSTAGE 4
#define GEMM_SMEM (NSTAGE * STAGE_BYTES)
#define GTHREADS 256

// swizzled 16B-chunk offset within an Rx64 fp16 tile (128B rows, 8-phase XOR)
__device__ __forceinline__ uint32_t tile_off(int row, int ch) {
    return (uint32_t)(row * 128 + ((ch ^ (row & 7)) << 4));
}

__device__ __forceinline__ void load_stage(
    uint32_t st, const char* A, const char* B,
    int K, int row0, int col0, int kc, int tid)
{
    size_t kb = (size_t)kc * 128;  // byte offset of 64-elem chunk within a row
    // A: 128 rows x 8 chunks = 1024 chunks, 4/thread
    #pragma unroll
    for (int i = 0; i < 4; i++) {
        int id = tid + GTHREADS * i;
        int row = id >> 3, ch = id & 7;
        size_t ga = (size_t)(row0 + row) * K * 2 + kb + ch * 16;
        cp_async16(st + tile_off(row, ch), A + ga);
    }
    // B: 256 rows x 8 chunks = 2048 chunks, 8/thread
    #pragma unroll
    for (int i = 0; i < 8; i++) {
        int id = tid + GTHREADS * i;
        int row = id >> 3, ch = id & 7;
        size_t gb = (size_t)(col0 + row) * K * 2 + kb + ch * 16;
        cp_async16(st + 16384 + tile_off(row, ch), B + gb);
    }
}

__global__ __launch_bounds__(GTHREADS, 1) void mma_gemm_kernel(
    const __half* __restrict__ A, const __half* __restrict__ B,
    int M, int N, int K,
    float* __restrict__ Cf, const float* __restrict__ bias,
    const float* __restrict__ residual,
    __half* __restrict__ Ch,
    __half* __restrict__ kOut, __half* __restrict__ vOut, int mode)
{
    extern __shared__ char smem[];
    uint32_t sbase = smem_u32(smem);

    int tid = threadIdx.x;
    int wid = tid >> 5, l = tid & 31;
    int wr = wid >> 2, wc = wid & 3;   // 2x4 warp grid: 64x64 per warp
    int row0 = blockIdx.y * 128;
    int col0 = blockIdx.x * 256;
    int CH = K >> 6;

    const char* pA = (const char*)A;
    const char* pB = (const char*)B;

    float acc[4][8][4];
    #pragma unroll
    for (int i = 0; i < 4; i++)
        #pragma unroll
        for (int j = 0; j < 8; j++)
            #pragma unroll
            for (int t = 0; t < 4; t++) acc[i][j][t] = 0.f;

    // per-lane ldmatrix geometry
    int aRow = wr * 64 + (l & 15);
    int aHalf = (l >> 4) & 1;
    int bRowL = (l & 7) + ((l >> 4) & 1) * 8;
    int bHalf = (l >> 3) & 1;

    // prologue: stages 0..2
    load_stage(sbase,                   pA, pB, K, row0, col0, 0, tid);
    cp_commit();
    load_stage(sbase + STAGE_BYTES,     pA, pB, K, row0, col0, 1, tid);
    cp_commit();
    load_stage(sbase + 2 * STAGE_BYTES, pA, pB, K, row0, col0, 2, tid);
    cp_commit();

    for (int c = 0; c < CH; c++) {
        cp_wait<2>();
        __syncthreads();
        // tail-clamped prefetch: always one group per iteration
        int nc = c + 3 < CH ? c + 3 : CH - 1;
        load_stage(sbase + ((c + 3) & (NSTAGE - 1)) * STAGE_BYTES,
                   pA, pB, K, row0, col0, nc, tid);
        cp_commit();

        uint32_t st = sbase + (c & (NSTAGE - 1)) * STAGE_BYTES;
        #pragma unroll
        for (int ks = 0; ks < 4; ks++) {
            uint32_t af[4][4];
            #pragma unroll
            for (int mt = 0; mt < 4; mt++) {
                uint32_t off = tile_off(aRow + mt * 16, ks * 2 + aHalf);
                ldsm4(af[mt][0], af[mt][1], af[mt][2], af[mt][3], st + off);
            }
            uint32_t bf[8][2];
            #pragma unroll
            for (int p = 0; p < 4; p++) {
                uint32_t off = tile_off(wc * 64 + p * 16 + bRowL, ks * 2 + bHalf);
                ldsm4(bf[2*p][0], bf[2*p][1], bf[2*p+1][0], bf[2*p+1][1],
                      st + 16384 + off);
            }
            #pragma unroll
            for (int mt = 0; mt < 4; mt++)
                #pragma unroll
                for (int nt = 0; nt < 8; nt++)
                    mma16816(acc[mt][nt], af[mt], bf[nt][0], bf[nt][1]);
        }
    }

    // epilogue
    int rb = row0 + wr * 64 + (l >> 2);
    int cb = col0 + wc * 64 + (l & 3) * 2;

    if (mode == 3) {
        int seg = col0 >> 10;                 // tile fully inside one segment
        __half* dst = (seg == 0) ? Ch : ((seg == 1) ? kOut : vOut);
        int csub = seg << 10;
        bool dorelu = (seg < 2);
        #pragma unroll
        for (int mt = 0; mt < 4; mt++)
            #pragma unroll
            for (int half = 0; half < 2; half++) {
                int r = rb + mt * 16 + half * 8;
                #pragma unroll
                for (int nt = 0; nt < 8; nt++) {
                    int ccol = cb + nt * 8 - csub;
                    float v0 = acc[mt][nt][half * 2];
                    float v1 = acc[mt][nt][half * 2 + 1];
                    if (dorelu) {
                        v0 = fmaxf(v0, 0.f) + 1e-6f;
                        v1 = fmaxf(v1, 0.f) + 1e-6f;
                    }
                    *reinterpret_cast<__half2*>(dst + (size_t)r * 1024 + ccol) =
                        __halves2half2(__float2half_rn(v0), __float2half_rn(v1));
                }
            }
        return;
    }

    #pragma unroll
    for (int mt = 0; mt < 4; mt++) {
        #pragma unroll
        for (int half = 0; half < 2; half++) {
            int r = rb + mt * 16 + half * 8;
            #pragma unroll
            for (int nt = 0; nt < 8; nt++) {
                int ccol = cb + nt * 8;
                float v0 = acc[mt][nt][half * 2];
                float v1 = acc[mt][nt][half * 2 + 1];
                if (mode == 2) {
                    v0 += bias[ccol];
                    v1 += bias[ccol + 1];
                    v0 = 0.5f * v0 * (1.0f + erff(v0 * 0.70710678118654752f));
                    v1 = 0.5f * v1 * (1.0f + erff(v1 * 0.70710678118654752f));
                    *reinterpret_cast<__half2*>(Ch + (size_t)r * N + ccol) =
                        __halves2half2(__float2half_rn(v0), __float2half_rn(v1));
                } else {
                    if (mode == 1) {
                        v0 += bias[ccol];
                        v1 += bias[ccol + 1];
                        const float2 rr = *reinterpret_cast<const float2*>(
                            residual + (size_t)r * N + ccol);
                        v0 += rr.x; v1 += rr.y;
                    }
                    float2 o; o.x = v0; o.y = v1;
                    *reinterpret_cast<float2*>(Cf + (size_t)r * N + ccol) = o;
                }
            }
        }
    }
}

// ---------------------------------------------------------------------------
// kv partials + reduce (fp16 inputs, fp32 accum)
// ---------------------------------------------------------------------------
__global__ __launch_bounds__(256) void kv_kernel(const __half* __restrict__ kf,
                                                 const __half* __restrict__ vv,
                                                 float* __restrict__ kvp,
                                                 float* __restrict__ ksp)
{
    int bh = blockIdx.x;
    int b = bh >> 4, h = bh & 15;
    int chunk = blockIdx.y;

    __shared__ float ks[16][64];
    __shared__ float vs[16][64];
    int tid = threadIdx.x;
    int fq = tid >> 4, dq = tid & 15;
    int ln = tid >> 4, lc = (tid & 15) * 4;

    float acc[4][4];
    #pragma unroll
    for (int i = 0; i < 4; i++)
        #pragma unroll
        for (int j = 0; j < 4; j++) acc[i][j] = 0.f;
    float ksacc = 0.f;

    size_t base = (size_t)b * SS * DD + (size_t)h * 64;
    int nstart = chunk * 512;
    for (int n0 = nstart; n0 < nstart + 512; n0 += 16) {
        const __half* kp = kf + base + (size_t)(n0 + ln) * DD + lc;
        const __half* vp = vv + base + (size_t)(n0 + ln) * DD + lc;
        __half2 k01 = *reinterpret_cast<const __half2*>(kp);
        __half2 k23 = *reinterpret_cast<const __half2*>(kp + 2);
        __half2 v01 = *reinterpret_cast<const __half2*>(vp);
        __half2 v23 = *reinterpret_cast<const __half2*>(vp + 2);
        float2 kf01 = __half22float2(k01), kf23 = __half22float2(k23);
        float2 vf01 = __half22float2(v01), vf23 = __half22float2(v23);
        ks[ln][lc] = kf01.x; ks[ln][lc+1] = kf01.y; ks[ln][lc+2] = kf23.x; ks[ln][lc+3] = kf23.y;
        vs[ln][lc] = vf01.x; vs[ln][lc+1] = vf01.y; vs[ln][lc+2] = vf23.x; vs[ln][lc+3] = vf23.y;
        __syncthreads();
        #pragma unroll
        for (int nn = 0; nn < 16; nn++) {
            float rk[4], rv[4];
            #pragma unroll
            for (int i = 0; i < 4; i++) rk[i] = ks[nn][fq * 4 + i];
            #pragma unroll
            for (int j = 0; j < 4; j++) rv[j] = vs[nn][dq * 4 + j];
            #pragma unroll
            for (int i = 0; i < 4; i++)
                #pragma unroll
                for (int j = 0; j < 4; j++)
                    acc[i][j] = fmaf(rk[i], rv[j], acc[i][j]);
        }
        if (tid < 64) {
            #pragma unroll
            for (int nn = 0; nn < 16; nn++) ksacc += ks[nn][tid];
        }
        __syncthreads();
    }

    float* dst = kvp + (size_t)chunk * 64 * 4096 + (size_t)bh * 4096;
    #pragma unroll
    for (int i = 0; i < 4; i++)
        #pragma unroll
        for (int j = 0; j < 4; j++)
            dst[(fq * 4 + i) * 64 + dq * 4 + j] = acc[i][j];
    if (tid < 64)
        ksp[(size_t)chunk * 64 * 64 + bh * 64 + tid] = ksacc;
}

__global__ __launch_bounds__(256) void kv_reduce_kernel(const float* __restrict__ kvp,
                                                        const float* __restrict__ ksp,
                                                        float* __restrict__ kv,
                                                        float* __restrict__ ksum)
{
    int i = blockIdx.x * 256 + threadIdx.x;
    if (i < 64 * 4096) {
        float s = 0.f;
        #pragma unroll
        for (int c = 0; c < 8; c++) s += kvp[(size_t)c * 64 * 4096 + i];
        kv[i] = s;
    }
    if (i < 64 * 64) {
        float s = 0.f;
        #pragma unroll
        for (int c = 0; c < 8; c++) s += ksp[(size_t)c * 64 * 64 + i];
        ksum[i] = s;
    }
}

// ---------------------------------------------------------------------------
// attn: row -> (row @ kv[bh]) / (row . ksum[bh] + eps), fp16 in, fp16 out
// ---------------------------------------------------------------------------
__global__ __launch_bounds__(256) void attn_kernel(const __half* __restrict__ qf,
                                                   const float* __restrict__ kv,
                                                   const float* __restrict__ ksum,
                                                   __half* __restrict__ o)
{
    __shared__ float kvS[64 * 64];
    __shared__ float ks[64];
    __shared__ float rowbuf[8][64];

    int bh = blockIdx.x;
    int b = bh >> 4, h = bh & 15;
    int tid = threadIdx.x, w = tid >> 5, l = tid & 31;

    for (int i = tid; i < 64 * 64; i += 256) kvS[i] = kv[(size_t)bh * 4096 + i];
    if (tid < 64) ks[tid] = ksum[bh * 64 + tid];
    __syncthreads();

    size_t base = (size_t)b * SS * DD + (size_t)h * 64;
    int n0 = blockIdx.y * 64 + w * 8;
    for (int r = 0; r < 8; r++) {
        const __half* p = qf + base + (size_t)(n0 + r) * DD;
        rowbuf[w][l]      = __half2float(p[l]);
        rowbuf[w][l + 32] = __half2float(p[l + 32]);
        __syncwarp();
        float dsum = rowbuf[w][l] * ks[l] + rowbuf[w][l + 32] * ks[l + 32];
        #pragma unroll
        for (int off = 16; off > 0; off >>= 1)
            dsum += __shfl_xor_sync(0xffffffffu, dsum, off);
        float inv = 1.0f / (dsum + 1e-6f);
        float a0 = 0.f, a1 = 0.f;
        #pragma unroll
        for (int f = 0; f < 64; f++) {
            float qv = rowbuf[w][f];
            a0 = fmaf(qv, kvS[f * 64 + l],      a0);
            a1 = fmaf(qv, kvS[f * 64 + l + 32], a1);
        }
        __syncwarp();
        size_t i0 = base + (size_t)(n0 + r) * DD;
        o[i0 + l]      = __float2half_rn(a0 * inv);
        o[i0 + l + 32] = __float2half_rn(a1 * inv);
    }
}

// ---------------------------------------------------------------------------
// Launch
// ---------------------------------------------------------------------------
extern "C" void kernel_launch(void* const* d_in, const int* in_sizes, int n_in,
                              void* d_out, int out_size)
{
    const float* x     = (const float*)d_in[0];
    const float* ln1_g = (const float*)d_in[1];
    const float* ln1_b = (const float*)d_in[2];
    const float* wq    = (const float*)d_in[3];
    const float* wk    = (const float*)d_in[4];
    const float* wv    = (const float*)d_in[5];
    const float* proj  = (const float*)d_in[6];
    const float* wo    = (const float*)d_in[7];
    const float* bo    = (const float*)d_in[8];
    const float* ln2_g = (const float*)d_in[9];
    const float* ln2_b = (const float*)d_in[10];
    const float* w1    = (const float*)d_in[11];
    const float* b1    = (const float*)d_in[12];
    const float* w2    = (const float*)d_in[13];
    const float* b2    = (const float*)d_in[14];
    float* out = (float*)d_out;

    float *qraw, *kvp, *ksp, *kv, *ksum;
    __half *kbuf, *vbuf, *h, *at, *ffn, *wqkvT, *woT, *w1T, *w2T;
    cudaGetSymbolAddress((void**)&qraw, g_q);
    cudaGetSymbolAddress((void**)&kbuf, g_kbuf);
    cudaGetSymbolAddress((void**)&vbuf, g_vbuf);
    cudaGetSymbolAddress((void**)&kvp, g_kvp);
    cudaGetSymbolAddress((void**)&ksp, g_ksp);
    cudaGetSymbolAddress((void**)&kv, g_kv);
    cudaGetSymbolAddress((void**)&ksum, g_ksum);
    cudaGetSymbolAddress((void**)&h, g_h);
    cudaGetSymbolAddress((void**)&at, g_at);
    cudaGetSymbolAddress((void**)&ffn, g_ffn);
    cudaGetSymbolAddress((void**)&wqkvT, g_wqkvT);
    cudaGetSymbolAddress((void**)&woT, g_woT);
    cudaGetSymbolAddress((void**)&w1T, g_w1T);
    cudaGetSymbolAddress((void**)&w2T, g_w2T);
    __half* qbuf = (__half*)qraw;   // fp16 q view (front 32MB of 64MB buffer)

    cudaFuncSetAttribute(mma_gemm_kernel,
                         cudaFuncAttributeMaxDynamicSharedMemorySize, GEMM_SMEM);

    // --- weight prep ---
    // fp32 temps live in the BACK half of g_q (front 32MB is the fp16 q view)
    float* tmp0 = qraw + 8 * 1024 * 1024;   // [1024*1024]
    float* tmp1 = qraw + 9 * 1024 * 1024;   // [1024*1024]
    fold_kernel<<<dim3(DD / 64, HH), 256>>>(wq, proj, tmp0);
    fold_kernel<<<dim3(DD / 64, HH), 256>>>(wk, proj, tmp1);
    ts_kernel<<<dim3(DD / 32, DD / 32), 256>>>(tmp0, wqkvT,               DD, DD);
    ts_kernel<<<dim3(DD / 32, DD / 32), 256>>>(tmp1, wqkvT + 1024 * 1024, DD, DD);
    ts_kernel<<<dim3(DD / 32, DD / 32), 256>>>(wv,   wqkvT + 2048 * 1024, DD, DD);
    ts_kernel<<<dim3(DD / 32, DD / 32), 256>>>(wo, woT, DD, DD);
    ts_kernel<<<dim3(DFF / 32, DD / 32), 256>>>(w1, w1T, DD, DFF);
    ts_kernel<<<dim3(DD / 32, DFF / 32), 256>>>(w2, w2T, DFF, DD);

    // LN1 -> h (fp16)
    ln_kernel<<<NTOK, 256>>>(x, ln1_g, ln1_b, h);

    // Fused QKV GEMM: N=3072 -> q (relu+eps), k (relu+eps), v  (all fp16)
    dim3 gQKV(3072 / 256, NTOK / 128);
    mma_gemm_kernel<<<gQKV, GTHREADS, GEMM_SMEM>>>(h, wqkvT,
        NTOK, 3072, DD, nullptr, nullptr, nullptr, qbuf, kbuf, vbuf, 3);

    // kv / ksum
    kv_kernel<<<dim3(64, 8), 256>>>(kbuf, vbuf, kvp, ksp);
    kv_reduce_kernel<<<(64 * 4096 + 255) / 256, 256>>>(kvp, ksp, kv, ksum);

    // attn -> fp16
    attn_kernel<<<dim3(64, 64), 256>>>(qbuf, kv, ksum, at);

    // x2 = x + attn @ wo + bo -> out (fp32)
    dim3 gD(DD / 256, NTOK / 128);
    mma_gemm_kernel<<<gD, GTHREADS, GEMM_SMEM>>>(at, woT,
        NTOK, DD, DD, out, bo, x, nullptr, nullptr, nullptr, 1);

    // LN2 -> h (fp16)
    ln_kernel<<<NTOK, 256>>>(out, ln2_g, ln2_b, h);

    // ffn = gelu(h2 @ w1 + b1) -> fp16
    dim3 gF1(DFF / 256, NTOK / 128);
    mma_gemm_kernel<<<gF1, GTHREADS, GEMM_SMEM>>>(h, w1T,
        NTOK, DFF, DD, nullptr, b1, nullptr, ffn, nullptr, nullptr, 2);

    // out = x2 + ffn @ w2 + b2 (in-place residual)
    mma_gemm_kernel<<<gD, GTHREADS, GEMM_SMEM>>>(ffn, w2T,
        NTOK, DD, DFF, out, b2, out, nullptr, nullptr, nullptr, 1);
}

// round 9
// speedup vs baseline: 6.9739x; 1.0101x over previous
#include <cuda_runtime.h>
#include <cuda_fp16.h>
#include <math.h>
#include <stdint.h>

// ---------------------------------------------------------------------------
// Problem constants
// ---------------------------------------------------------------------------
#define BB 4
#define SS 4096
#define DD 1024
#define HH 16
#define DH 64
#define FF 64
#define DFF 4096
#define NTOK (BB * SS)            // 16384 tokens

// ---------------------------------------------------------------------------
// Scratch (static device globals)
// ---------------------------------------------------------------------------
__device__ float g_q[(size_t)NTOK * DD];       // fp16 q view + fp32 prep temps
__device__ __half g_kbuf[(size_t)NTOK * DD];
__device__ __half g_vbuf[(size_t)NTOK * DD];
__device__ __half g_h[(size_t)NTOK * DD];      // LN out (A operand), fp16
__device__ __half g_at[(size_t)NTOK * DD];     // attn out (A of wo), fp16
__device__ __half g_ffn[(size_t)NTOK * DFF];   // gelu out (A of w2), fp16
// Transposed single-fp16 weights, [N, K]
__device__ __half g_wqkvT[3 * DD * DD];    // folded q, folded k, v
__device__ __half g_woT[DD * DD];
__device__ __half g_w1T[(size_t)DFF * DD];
__device__ __half g_w2T[(size_t)DD * DFF];
// linear-attention small tensors
__device__ float g_kvp[8 * 64 * FF * DH];
__device__ float g_ksp[8 * 64 * FF];
__device__ float g_kv[64 * FF * DH];
__device__ float g_ksum[64 * FF];

// ---------------------------------------------------------------------------
// PTX helpers (baseline PTX only — no 'a'-suffix features)
// ---------------------------------------------------------------------------
__device__ __forceinline__ uint32_t smem_u32(const void* p) {
    uint32_t a;
    asm("{ .reg .u64 t; cvta.to.shared.u64 t, %1; cvt.u32.u64 %0, t; }"
        : "=r"(a) : "l"(p));
    return a;
}
__device__ __forceinline__ void cp_async16(uint32_t dst, const void* src) {
    asm volatile("cp.async.cg.shared.global [%0], [%1], 16;\n" :: "r"(dst), "l"(src));
}
__device__ __forceinline__ void cp_commit() {
    asm volatile("cp.async.commit_group;\n" ::: "memory");
}
template <int N>
__device__ __forceinline__ void cp_wait() {
    asm volatile("cp.async.wait_group %0;\n" :: "n"(N) : "memory");
}
__device__ __forceinline__ void ldsm4(uint32_t& r0, uint32_t& r1, uint32_t& r2,
                                      uint32_t& r3, uint32_t addr) {
    asm volatile("ldmatrix.sync.aligned.m8n8.x4.shared.b16 {%0,%1,%2,%3}, [%4];"
                 : "=r"(r0), "=r"(r1), "=r"(r2), "=r"(r3) : "r"(addr));
}
__device__ __forceinline__ void mma16816(float* c, const uint32_t* a,
                                         uint32_t b0, uint32_t b1) {
    asm volatile(
        "mma.sync.aligned.m16n8k16.row.col.f32.f16.f16.f32 "
        "{%0,%1,%2,%3}, {%4,%5,%6,%7}, {%8,%9}, {%0,%1,%2,%3};"
        : "+f"(c[0]), "+f"(c[1]), "+f"(c[2]), "+f"(c[3])
        : "r"(a[0]), "r"(a[1]), "r"(a[2]), "r"(a[3]), "r"(b0), "r"(b1));
}

// ---------------------------------------------------------------------------
// Fold proj into a QK weight: out[d, h*64+f] = sum_dh W[d, h*64+dh]*proj[dh,f]
// ---------------------------------------------------------------------------
__global__ __launch_bounds__(256) void fold_kernel(const float* __restrict__ W,
                                                   const float* __restrict__ proj,
                                                   float* __restrict__ outW)
{
    __shared__ float projS[64][64];
    __shared__ float wS[64][65];
    int d0 = blockIdx.x * 64, h = blockIdx.y;
    int tid = threadIdx.x;
    for (int i = tid; i < 64 * 64; i += 256)
        projS[i >> 6][i & 63] = proj[i];
    for (int i = tid; i < 64 * 64; i += 256)
        wS[i >> 6][i & 63] = W[(size_t)(d0 + (i >> 6)) * (HH * DH) + h * 64 + (i & 63)];
    __syncthreads();
    int r = tid >> 2;
    int fb = (tid & 3) * 16;
    float acc[16];
    #pragma unroll
    for (int i = 0; i < 16; i++) acc[i] = 0.f;
    #pragma unroll 8
    for (int c = 0; c < 64; c++) {
        float w = wS[r][c];
        #pragma unroll
        for (int i = 0; i < 16; i++)
            acc[i] = fmaf(w, projS[c][fb + i], acc[i]);
    }
    for (int i = 0; i < 16; i++)
        outW[(size_t)(d0 + r) * (HH * FF) + h * 64 + fb + i] = acc[i];
}

// ---------------------------------------------------------------------------
// Weight transpose + fp16 convert:  W[K,N] -> Wt[N,K]
// ---------------------------------------------------------------------------
__global__ __launch_bounds__(256) void ts_kernel(const float* __restrict__ W,
                                                 __half* __restrict__ o,
                                                 int K, int N)
{
    __shared__ float t[32][33];
    int n0 = blockIdx.x * 32, k0 = blockIdx.y * 32;
    int tx = threadIdx.x & 31, ty = threadIdx.x >> 5;
    for (int r = ty; r < 32; r += 8)
        t[r][tx] = W[(size_t)(k0 + r) * N + n0 + tx];
    __syncthreads();
    for (int r = ty; r < 32; r += 8)
        o[(size_t)(n0 + r) * K + k0 + tx] = __float2half_rn(t[tx][r]);
}

// ---------------------------------------------------------------------------
// LayerNorm -> fp16. One block (256 thr) per row of 1024.
// ---------------------------------------------------------------------------
__global__ __launch_bounds__(256) void ln_kernel(const float* __restrict__ x,
                                                 const float* __restrict__ g,
                                                 const float* __restrict__ b,
                                                 __half* __restrict__ o)
{
    int row = blockIdx.x;
    int t = threadIdx.x;
    const float4* xr = reinterpret_cast<const float4*>(x + (size_t)row * DD);
    float4 xv = xr[t];

    float s  = xv.x + xv.y + xv.z + xv.w;
    float s2 = xv.x*xv.x + xv.y*xv.y + xv.z*xv.z + xv.w*xv.w;

    __shared__ float red[2][8];
    #pragma unroll
    for (int off = 16; off > 0; off >>= 1) {
        s  += __shfl_xor_sync(0xffffffffu, s,  off);
        s2 += __shfl_xor_sync(0xffffffffu, s2, off);
    }
    int w = t >> 5, l = t & 31;
    if (l == 0) { red[0][w] = s; red[1][w] = s2; }
    __syncthreads();
    __shared__ float smu, srstd;
    if (t == 0) {
        float ts = 0.f, ts2 = 0.f;
        #pragma unroll
        for (int i = 0; i < 8; i++) { ts += red[0][i]; ts2 += red[1][i]; }
        float mu = ts * (1.0f / DD);
        float var = ts2 * (1.0f / DD) - mu * mu;
        smu = mu;
        srstd = rsqrtf(var + 1e-5f);
    }
    __syncthreads();
    float mu = smu, rstd = srstd;

    const float4 gv = reinterpret_cast<const float4*>(g)[t];
    const float4 bv = reinterpret_cast<const float4*>(b)[t];
    float o0 = (xv.x - mu) * rstd * gv.x + bv.x;
    float o1 = (xv.y - mu) * rstd * gv.y + bv.y;
    float o2 = (xv.z - mu) * rstd * gv.z + bv.z;
    float o3 = (xv.w - mu) * rstd * gv.w + bv.w;
    size_t idx = (size_t)row * DD + t * 4;
    __half2 p0 = __halves2half2(__float2half_rn(o0), __float2half_rn(o1));
    __half2 p1 = __halves2half2(__float2half_rn(o2), __float2half_rn(o3));
    *reinterpret_cast<__half2*>(o + idx)     = p0;
    *reinterpret_cast<__half2*>(o + idx + 2) = p1;
}

// ---------------------------------------------------------------------------
// HMMA GEMM: C[M,N] = A @ B^T, fp16 inputs, fp32 accum.
// Tile 128x256, BK=64, 4-stage cp.async pipeline, 256 threads,
// 8 warps in 2x4 grid, warp tile 64x64, fragment double-buffering.
// mode 0: Cf = val
// mode 1: Cf = val + bias + residual
// mode 2: Ch = fp16(gelu(val + bias))
// mode 3: fused qkv (fp16 outs): seg0 relu+eps->qOut, seg1 relu+eps->kOut,
//         seg2 ->vOut  (out stride 1024)
// ---------------------------------------------------------------------------
#define STAGE_BYTES 49152
#define NSTAGE 4
#define GEMM_SMEM (NSTAGE * STAGE_BYTES)
#define GTHREADS 256

// swizzled 16B-chunk offset within an Rx64 fp16 tile (128B rows, 8-phase XOR)
__device__ __forceinline__ uint32_t tile_off(int row, int ch) {
    return (uint32_t)(row * 128 + ((ch ^ (row & 7)) << 4));
}

__device__ __forceinline__ void load_stage(
    uint32_t st, const char* A, const char* B,
    int K, int row0, int col0, int kc, int tid)
{
    size_t kb = (size_t)kc * 128;  // byte offset of 64-elem chunk within a row
    // A: 128 rows x 8 chunks = 1024 chunks, 4/thread
    #pragma unroll
    for (int i = 0; i < 4; i++) {
        int id = tid + GTHREADS * i;
        int row = id >> 3, ch = id & 7;
        size_t ga = (size_t)(row0 + row) * K * 2 + kb + ch * 16;
        cp_async16(st + tile_off(row, ch), A + ga);
    }
    // B: 256 rows x 8 chunks = 2048 chunks, 8/thread
    #pragma unroll
    for (int i = 0; i < 8; i++) {
        int id = tid + GTHREADS * i;
        int row = id >> 3, ch = id & 7;
        size_t gb = (size_t)(col0 + row) * K * 2 + kb + ch * 16;
        cp_async16(st + 16384 + tile_off(row, ch), B + gb);
    }
}

// load one ks-step's register fragments
__device__ __forceinline__ void ld_frags(
    uint32_t st, int ks, int aRow, int aHalf, int wc, int bRowL, int bHalf,
    uint32_t fa[4][4], uint32_t fb[8][2])
{
    #pragma unroll
    for (int mt = 0; mt < 4; mt++) {
        uint32_t off = tile_off(aRow + mt * 16, ks * 2 + aHalf);
        ldsm4(fa[mt][0], fa[mt][1], fa[mt][2], fa[mt][3], st + off);
    }
    #pragma unroll
    for (int p = 0; p < 4; p++) {
        uint32_t off = tile_off(wc * 64 + p * 16 + bRowL, ks * 2 + bHalf);
        ldsm4(fb[2*p][0], fb[2*p][1], fb[2*p+1][0], fb[2*p+1][1],
              st + 16384 + off);
    }
}

__global__ __launch_bounds__(GTHREADS, 1) void mma_gemm_kernel(
    const __half* __restrict__ A, const __half* __restrict__ B,
    int M, int N, int K,
    float* __restrict__ Cf, const float* __restrict__ bias,
    const float* __restrict__ residual,
    __half* __restrict__ Ch,
    __half* __restrict__ kOut, __half* __restrict__ vOut, int mode)
{
    extern __shared__ char smem[];
    uint32_t sbase = smem_u32(smem);

    int tid = threadIdx.x;
    int wid = tid >> 5, l = tid & 31;
    int wr = wid >> 2, wc = wid & 3;   // 2x4 warp grid: 64x64 per warp
    int row0 = blockIdx.y * 128;
    int col0 = blockIdx.x * 256;
    int CH = K >> 6;

    const char* pA = (const char*)A;
    const char* pB = (const char*)B;

    float acc[4][8][4];
    #pragma unroll
    for (int i = 0; i < 4; i++)
        #pragma unroll
        for (int j = 0; j < 8; j++)
            #pragma unroll
            for (int t = 0; t < 4; t++) acc[i][j][t] = 0.f;

    // per-lane ldmatrix geometry
    int aRow = wr * 64 + (l & 15);
    int aHalf = (l >> 4) & 1;
    int bRowL = (l & 7) + ((l >> 4) & 1) * 8;
    int bHalf = (l >> 3) & 1;

    // prologue: stages 0..2
    load_stage(sbase,                   pA, pB, K, row0, col0, 0, tid);
    cp_commit();
    load_stage(sbase + STAGE_BYTES,     pA, pB, K, row0, col0, 1, tid);
    cp_commit();
    load_stage(sbase + 2 * STAGE_BYTES, pA, pB, K, row0, col0, 2, tid);
    cp_commit();

    uint32_t fa[2][4][4], fb[2][8][2];

    for (int c = 0; c < CH; c++) {
        cp_wait<2>();
        __syncthreads();
        // tail-clamped prefetch: always one group per iteration
        int nc = c + 3 < CH ? c + 3 : CH - 1;
        load_stage(sbase + ((c + 3) & (NSTAGE - 1)) * STAGE_BYTES,
                   pA, pB, K, row0, col0, nc, tid);
        cp_commit();

        uint32_t st = sbase + (c & (NSTAGE - 1)) * STAGE_BYTES;
        // preload ks=0 fragments
        ld_frags(st, 0, aRow, aHalf, wc, bRowL, bHalf, fa[0], fb[0]);
        #pragma unroll
        for (int ks = 0; ks < 4; ks++) {
            int cur = ks & 1;
            if (ks < 3)
                ld_frags(st, ks + 1, aRow, aHalf, wc, bRowL, bHalf,
                         fa[cur ^ 1], fb[cur ^ 1]);
            #pragma unroll
            for (int mt = 0; mt < 4; mt++)
                #pragma unroll
                for (int nt = 0; nt < 8; nt++)
                    mma16816(acc[mt][nt], fa[cur][mt], fb[cur][nt][0], fb[cur][nt][1]);
        }
    }

    // epilogue
    int rb = row0 + wr * 64 + (l >> 2);
    int cb = col0 + wc * 64 + (l & 3) * 2;

    if (mode == 3) {
        int seg = col0 >> 10;                 // tile fully inside one segment
        __half* dst = (seg == 0) ? Ch : ((seg == 1) ? kOut : vOut);
        int csub = seg << 10;
        bool dorelu = (seg < 2);
        #pragma unroll
        for (int mt = 0; mt < 4; mt++)
            #pragma unroll
            for (int half = 0; half < 2; half++) {
                int r = rb + mt * 16 + half * 8;
                #pragma unroll
                for (int nt = 0; nt < 8; nt++) {
                    int ccol = cb + nt * 8 - csub;
                    float v0 = acc[mt][nt][half * 2];
                    float v1 = acc[mt][nt][half * 2 + 1];
                    if (dorelu) {
                        v0 = fmaxf(v0, 0.f) + 1e-6f;
                        v1 = fmaxf(v1, 0.f) + 1e-6f;
                    }
                    *reinterpret_cast<__half2*>(dst + (size_t)r * 1024 + ccol) =
                        __halves2half2(__float2half_rn(v0), __float2half_rn(v1));
                }
            }
        return;
    }

    #pragma unroll
    for (int mt = 0; mt < 4; mt++) {
        #pragma unroll
        for (int half = 0; half < 2; half++) {
            int r = rb + mt * 16 + half * 8;
            #pragma unroll
            for (int nt = 0; nt < 8; nt++) {
                int ccol = cb + nt * 8;
                float v0 = acc[mt][nt][half * 2];
                float v1 = acc[mt][nt][half * 2 + 1];
                if (mode == 2) {
                    v0 += bias[ccol];
                    v1 += bias[ccol + 1];
                    v0 = 0.5f * v0 * (1.0f + erff(v0 * 0.70710678118654752f));
                    v1 = 0.5f * v1 * (1.0f + erff(v1 * 0.70710678118654752f));
                    *reinterpret_cast<__half2*>(Ch + (size_t)r * N + ccol) =
                        __halves2half2(__float2half_rn(v0), __float2half_rn(v1));
                } else {
                    if (mode == 1) {
                        v0 += bias[ccol];
                        v1 += bias[ccol + 1];
                        const float2 rr = *reinterpret_cast<const float2*>(
                            residual + (size_t)r * N + ccol);
                        v0 += rr.x; v1 += rr.y;
                    }
                    float2 o; o.x = v0; o.y = v1;
                    *reinterpret_cast<float2*>(Cf + (size_t)r * N + ccol) = o;
                }
            }
        }
    }
}

// ---------------------------------------------------------------------------
// kv partials + reduce (fp16 inputs, fp32 accum)
// ---------------------------------------------------------------------------
__global__ __launch_bounds__(256) void kv_kernel(const __half* __restrict__ kf,
                                                 const __half* __restrict__ vv,
                                                 float* __restrict__ kvp,
                                                 float* __restrict__ ksp)
{
    int bh = blockIdx.x;
    int b = bh >> 4, h = bh & 15;
    int chunk = blockIdx.y;

    __shared__ float ks[16][64];
    __shared__ float vs[16][64];
    int tid = threadIdx.x;
    int fq = tid >> 4, dq = tid & 15;
    int ln = tid >> 4, lc = (tid & 15) * 4;

    float acc[4][4];
    #pragma unroll
    for (int i = 0; i < 4; i++)
        #pragma unroll
        for (int j = 0; j < 4; j++) acc[i][j] = 0.f;
    float ksacc = 0.f;

    size_t base = (size_t)b * SS * DD + (size_t)h * 64;
    int nstart = chunk * 512;
    for (int n0 = nstart; n0 < nstart + 512; n0 += 16) {
        const __half* kp = kf + base + (size_t)(n0 + ln) * DD + lc;
        const __half* vp = vv + base + (size_t)(n0 + ln) * DD + lc;
        __half2 k01 = *reinterpret_cast<const __half2*>(kp);
        __half2 k23 = *reinterpret_cast<const __half2*>(kp + 2);
        __half2 v01 = *reinterpret_cast<const __half2*>(vp);
        __half2 v23 = *reinterpret_cast<const __half2*>(vp + 2);
        float2 kf01 = __half22float2(k01), kf23 = __half22float2(k23);
        float2 vf01 = __half22float2(v01), vf23 = __half22float2(v23);
        ks[ln][lc] = kf01.x; ks[ln][lc+1] = kf01.y; ks[ln][lc+2] = kf23.x; ks[ln][lc+3] = kf23.y;
        vs[ln][lc] = vf01.x; vs[ln][lc+1] = vf01.y; vs[ln][lc+2] = vf23.x; vs[ln][lc+3] = vf23.y;
        __syncthreads();
        #pragma unroll
        for (int nn = 0; nn < 16; nn++) {
            float rk[4], rv[4];
            #pragma unroll
            for (int i = 0; i < 4; i++) rk[i] = ks[nn][fq * 4 + i];
            #pragma unroll
            for (int j = 0; j < 4; j++) rv[j] = vs[nn][dq * 4 + j];
            #pragma unroll
            for (int i = 0; i < 4; i++)
                #pragma unroll
                for (int j = 0; j < 4; j++)
                    acc[i][j] = fmaf(rk[i], rv[j], acc[i][j]);
        }
        if (tid < 64) {
            #pragma unroll
            for (int nn = 0; nn < 16; nn++) ksacc += ks[nn][tid];
        }
        __syncthreads();
    }

    float* dst = kvp + (size_t)chunk * 64 * 4096 + (size_t)bh * 4096;
    #pragma unroll
    for (int i = 0; i < 4; i++)
        #pragma unroll
        for (int j = 0; j < 4; j++)
            dst[(fq * 4 + i) * 64 + dq * 4 + j] = acc[i][j];
    if (tid < 64)
        ksp[(size_t)chunk * 64 * 64 + bh * 64 + tid] = ksacc;
}

__global__ __launch_bounds__(256) void kv_reduce_kernel(const float* __restrict__ kvp,
                                                        const float* __restrict__ ksp,
                                                        float* __restrict__ kv,
                                                        float* __restrict__ ksum)
{
    int i = blockIdx.x * 256 + threadIdx.x;
    if (i < 64 * 4096) {
        float s = 0.f;
        #pragma unroll
        for (int c = 0; c < 8; c++) s += kvp[(size_t)c * 64 * 4096 + i];
        kv[i] = s;
    }
    if (i < 64 * 64) {
        float s = 0.f;
        #pragma unroll
        for (int c = 0; c < 8; c++) s += ksp[(size_t)c * 64 * 64 + i];
        ksum[i] = s;
    }
}

// ---------------------------------------------------------------------------
// attn: row -> (row @ kv[bh]) / (row . ksum[bh] + eps), fp16 in, fp16 out
// ---------------------------------------------------------------------------
__global__ __launch_bounds__(256) void attn_kernel(const __half* __restrict__ qf,
                                                   const float* __restrict__ kv,
                                                   const float* __restrict__ ksum,
                                                   __half* __restrict__ o)
{
    __shared__ float kvS[64 * 64];
    __shared__ float ks[64];
    __shared__ float rowbuf[8][64];

    int bh = blockIdx.x;
    int b = bh >> 4, h = bh & 15;
    int tid = threadIdx.x, w = tid >> 5, l = tid & 31;

    for (int i = tid; i < 64 * 64; i += 256) kvS[i] = kv[(size_t)bh * 4096 + i];
    if (tid < 64) ks[tid] = ksum[bh * 64 + tid];
    __syncthreads();

    size_t base = (size_t)b * SS * DD + (size_t)h * 64;
    int n0 = blockIdx.y * 64 + w * 8;
    for (int r = 0; r < 8; r++) {
        const __half* p = qf + base + (size_t)(n0 + r) * DD;
        rowbuf[w][l]      = __half2float(p[l]);
        rowbuf[w][l + 32] = __half2float(p[l + 32]);
        __syncwarp();
        float dsum = rowbuf[w][l] * ks[l] + rowbuf[w][l + 32] * ks[l + 32];
        #pragma unroll
        for (int off = 16; off > 0; off >>= 1)
            dsum += __shfl_xor_sync(0xffffffffu, dsum, off);
        float inv = 1.0f / (dsum + 1e-6f);
        float a0 = 0.f, a1 = 0.f;
        #pragma unroll
        for (int f = 0; f < 64; f++) {
            float qv = rowbuf[w][f];
            a0 = fmaf(qv, kvS[f * 64 + l],      a0);
            a1 = fmaf(qv, kvS[f * 64 + l + 32], a1);
        }
        __syncwarp();
        size_t i0 = base + (size_t)(n0 + r) * DD;
        o[i0 + l]      = __float2half_rn(a0 * inv);
        o[i0 + l + 32] = __float2half_rn(a1 * inv);
    }
}

// ---------------------------------------------------------------------------
// Launch
// ---------------------------------------------------------------------------
extern "C" void kernel_launch(void* const* d_in, const int* in_sizes, int n_in,
                              void* d_out, int out_size)
{
    const float* x     = (const float*)d_in[0];
    const float* ln1_g = (const float*)d_in[1];
    const float* ln1_b = (const float*)d_in[2];
    const float* wq    = (const float*)d_in[3];
    const float* wk    = (const float*)d_in[4];
    const float* wv    = (const float*)d_in[5];
    const float* proj  = (const float*)d_in[6];
    const float* wo    = (const float*)d_in[7];
    const float* bo    = (const float*)d_in[8];
    const float* ln2_g = (const float*)d_in[9];
    const float* ln2_b = (const float*)d_in[10];
    const float* w1    = (const float*)d_in[11];
    const float* b1    = (const float*)d_in[12];
    const float* w2    = (const float*)d_in[13];
    const float* b2    = (const float*)d_in[14];
    float* out = (float*)d_out;

    float *qraw, *kvp, *ksp, *kv, *ksum;
    __half *kbuf, *vbuf, *h, *at, *ffn, *wqkvT, *woT, *w1T, *w2T;
    cudaGetSymbolAddress((void**)&qraw, g_q);
    cudaGetSymbolAddress((void**)&kbuf, g_kbuf);
    cudaGetSymbolAddress((void**)&vbuf, g_vbuf);
    cudaGetSymbolAddress((void**)&kvp, g_kvp);
    cudaGetSymbolAddress((void**)&ksp, g_ksp);
    cudaGetSymbolAddress((void**)&kv, g_kv);
    cudaGetSymbolAddress((void**)&ksum, g_ksum);
    cudaGetSymbolAddress((void**)&h, g_h);
    cudaGetSymbolAddress((void**)&at, g_at);
    cudaGetSymbolAddress((void**)&ffn, g_ffn);
    cudaGetSymbolAddress((void**)&wqkvT, g_wqkvT);
    cudaGetSymbolAddress((void**)&woT, g_woT);
    cudaGetSymbolAddress((void**)&w1T, g_w1T);
    cudaGetSymbolAddress((void**)&w2T, g_w2T);
    __half* qbuf = (__half*)qraw;   // fp16 q view (front 32MB of 64MB buffer)

    cudaFuncSetAttribute(mma_gemm_kernel,
                         cudaFuncAttributeMaxDynamicSharedMemorySize, GEMM_SMEM);

    // --- weight prep ---
    // fp32 temps live in the BACK half of g_q (front 32MB is the fp16 q view)
    float* tmp0 = qraw + 8 * 1024 * 1024;   // [1024*1024]
    float* tmp1 = qraw + 9 * 1024 * 1024;   // [1024*1024]
    fold_kernel<<<dim3(DD / 64, HH), 256>>>(wq, proj, tmp0);
    fold_kernel<<<dim3(DD / 64, HH), 256>>>(wk, proj, tmp1);
    ts_kernel<<<dim3(DD / 32, DD / 32), 256>>>(tmp0, wqkvT,               DD, DD);
    ts_kernel<<<dim3(DD / 32, DD / 32), 256>>>(tmp1, wqkvT + 1024 * 1024, DD, DD);
    ts_kernel<<<dim3(DD / 32, DD / 32), 256>>>(wv,   wqkvT + 2048 * 1024, DD, DD);
    ts_kernel<<<dim3(DD / 32, DD / 32), 256>>>(wo, woT, DD, DD);
    ts_kernel<<<dim3(DFF / 32, DD / 32), 256>>>(w1, w1T, DD, DFF);
    ts_kernel<<<dim3(DD / 32, DFF / 32), 256>>>(w2, w2T, DFF, DD);

    // LN1 -> h (fp16)
    ln_kernel<<<NTOK, 256>>>(x, ln1_g, ln1_b, h);

    // Fused QKV GEMM: N=3072 -> q (relu+eps), k (relu+eps), v  (all fp16)
    dim3 gQKV(3072 / 256, NTOK / 128);
    mma_gemm_kernel<<<gQKV, GTHREADS, GEMM_SMEM>>>(h, wqkvT,
        NTOK, 3072, DD, nullptr, nullptr, nullptr, qbuf, kbuf, vbuf, 3);

    // kv / ksum
    kv_kernel<<<dim3(64, 8), 256>>>(kbuf, vbuf, kvp, ksp);
    kv_reduce_kernel<<<(64 * 4096 + 255) / 256, 256>>>(kvp, ksp, kv, ksum);

    // attn -> fp16
    attn_kernel<<<dim3(64, 64), 256>>>(qbuf, kv, ksum, at);

    // x2 = x + attn @ wo + bo -> out (fp32)
    dim3 gD(DD / 256, NTOK / 128);
    mma_gemm_kernel<<<gD, GTHREADS, GEMM_SMEM>>>(at, woT,
        NTOK, DD, DD, out, bo, x, nullptr, nullptr, nullptr, 1);

    // LN2 -> h (fp16)
    ln_kernel<<<NTOK, 256>>>(out, ln2_g, ln2_b, h);

    // ffn = gelu(h2 @ w1 + b1) -> fp16
    dim3 gF1(DFF / 256, NTOK / 128);
    mma_gemm_kernel<<<gF1, GTHREADS, GEMM_SMEM>>>(h, w1T,
        NTOK, DFF, DD, nullptr, b1, nullptr, ffn, nullptr, nullptr, 2);

    // out = x2 + ffn @ w2 + b2 (in-place residual)
    mma_gemm_kernel<<<gD, GTHREADS, GEMM_SMEM>>>(ffn, w2T,
        NTOK, DD, DFF, out, b2, out, nullptr, nullptr, nullptr, 1);
}

// round 13
// speedup vs baseline: 7.7682x; 1.1139x over previous
#include <cuda_runtime.h>
#include <cuda_fp16.h>
#include <math.h>
#include <stdint.h>

// ---------------------------------------------------------------------------
// Problem constants
// ---------------------------------------------------------------------------
#define BB 4
#define SS 4096
#define DD 1024
#define HH 16
#define DH 64
#define FF 64
#define DFF 4096
#define NTOK (BB * SS)            // 16384 tokens

// ---------------------------------------------------------------------------
// Scratch (static device globals)
// ---------------------------------------------------------------------------
__device__ float g_q[(size_t)NTOK * DD];       // fp16 q view + fp32 prep temps
__device__ __half g_kbuf[(size_t)NTOK * DD];
__device__ __half g_vbuf[(size_t)NTOK * DD];
__device__ __half g_h[(size_t)NTOK * DD];      // LN out (A operand), fp16
__device__ __half g_at[(size_t)NTOK * DD];     // attn out (A of wo), fp16
__device__ __half g_ffn[(size_t)NTOK * DFF];   // gelu out (A of w2), fp16
// Transposed single-fp16 weights, [N, K]
__device__ __half g_wqkvT[3 * DD * DD];    // folded q, folded k, v
__device__ __half g_woT[DD * DD];
__device__ __half g_w1T[(size_t)DFF * DD];
__device__ __half g_w2T[(size_t)DD * DFF];
// linear-attention small tensors
__device__ __half g_kvT[64 * FF * DH];     // [bh][d][f] fp16 (B^T for attn mma)
__device__ float g_ksum[64 * FF];

// ---------------------------------------------------------------------------
// PTX helpers (baseline PTX only — no 'a'-suffix features)
// ---------------------------------------------------------------------------
__device__ __forceinline__ uint32_t smem_u32(const void* p) {
    uint32_t a;
    asm("{ .reg .u64 t; cvta.to.shared.u64 t, %1; cvt.u32.u64 %0, t; }"
        : "=r"(a) : "l"(p));
    return a;
}
__device__ __forceinline__ void cp_async16(uint32_t dst, const void* src) {
    asm volatile("cp.async.cg.shared.global [%0], [%1], 16;\n" :: "r"(dst), "l"(src));
}
__device__ __forceinline__ void cp_commit() {
    asm volatile("cp.async.commit_group;\n" ::: "memory");
}
template <int N>
__device__ __forceinline__ void cp_wait() {
    asm volatile("cp.async.wait_group %0;\n" :: "n"(N) : "memory");
}
__device__ __forceinline__ void ldsm4(uint32_t& r0, uint32_t& r1, uint32_t& r2,
                                      uint32_t& r3, uint32_t addr) {
    asm volatile("ldmatrix.sync.aligned.m8n8.x4.shared.b16 {%0,%1,%2,%3}, [%4];"
                 : "=r"(r0), "=r"(r1), "=r"(r2), "=r"(r3) : "r"(addr));
}
__device__ __forceinline__ void ldsm4t(uint32_t& r0, uint32_t& r1, uint32_t& r2,
                                       uint32_t& r3, uint32_t addr) {
    asm volatile("ldmatrix.sync.aligned.m8n8.x4.trans.shared.b16 {%0,%1,%2,%3}, [%4];"
                 : "=r"(r0), "=r"(r1), "=r"(r2), "=r"(r3) : "r"(addr));
}
__device__ __forceinline__ void mma16816(float* c, const uint32_t* a,
                                         uint32_t b0, uint32_t b1) {
    asm volatile(
        "mma.sync.aligned.m16n8k16.row.col.f32.f16.f16.f32 "
        "{%0,%1,%2,%3}, {%4,%5,%6,%7}, {%8,%9}, {%0,%1,%2,%3};"
        : "+f"(c[0]), "+f"(c[1]), "+f"(c[2]), "+f"(c[3])
        : "r"(a[0]), "r"(a[1]), "r"(a[2]), "r"(a[3]), "r"(b0), "r"(b1));
}

// swizzled 16B-chunk offset within an Rx64 fp16 tile (128B rows, 8-phase XOR)
__device__ __forceinline__ uint32_t tile_off(int row, int ch) {
    return (uint32_t)(row * 128 + ((ch ^ (row & 7)) << 4));
}

// ---------------------------------------------------------------------------
// Fold proj into a QK weight: out[d, h*64+f] = sum_dh W[d, h*64+dh]*proj[dh,f]
// ---------------------------------------------------------------------------
__global__ __launch_bounds__(256) void fold_kernel(const float* __restrict__ W,
                                                   const float* __restrict__ proj,
                                                   float* __restrict__ outW)
{
    __shared__ float projS[64][64];
    __shared__ float wS[64][65];
    int d0 = blockIdx.x * 64, h = blockIdx.y;
    int tid = threadIdx.x;
    for (int i = tid; i < 64 * 64; i += 256)
        projS[i >> 6][i & 63] = proj[i];
    for (int i = tid; i < 64 * 64; i += 256)
        wS[i >> 6][i & 63] = W[(size_t)(d0 + (i >> 6)) * (HH * DH) + h * 64 + (i & 63)];
    __syncthreads();
    int r = tid >> 2;
    int fb = (tid & 3) * 16;
    float acc[16];
    #pragma unroll
    for (int i = 0; i < 16; i++) acc[i] = 0.f;
    #pragma unroll 8
    for (int c = 0; c < 64; c++) {
        float w = wS[r][c];
        #pragma unroll
        for (int i = 0; i < 16; i++)
            acc[i] = fmaf(w, projS[c][fb + i], acc[i]);
    }
    for (int i = 0; i < 16; i++)
        outW[(size_t)(d0 + r) * (HH * FF) + h * 64 + fb + i] = acc[i];
}

// ---------------------------------------------------------------------------
// Weight transpose + fp16 convert:  W[K,N] -> Wt[N,K]
// ---------------------------------------------------------------------------
__global__ __launch_bounds__(256) void ts_kernel(const float* __restrict__ W,
                                                 __half* __restrict__ o,
                                                 int K, int N)
{
    __shared__ float t[32][33];
    int n0 = blockIdx.x * 32, k0 = blockIdx.y * 32;
    int tx = threadIdx.x & 31, ty = threadIdx.x >> 5;
    for (int r = ty; r < 32; r += 8)
        t[r][tx] = W[(size_t)(k0 + r) * N + n0 + tx];
    __syncthreads();
    for (int r = ty; r < 32; r += 8)
        o[(size_t)(n0 + r) * K + k0 + tx] = __float2half_rn(t[tx][r]);
}

// ---------------------------------------------------------------------------
// LayerNorm -> fp16. One block (256 thr) per row of 1024.
// ---------------------------------------------------------------------------
__global__ __launch_bounds__(256) void ln_kernel(const float* __restrict__ x,
                                                 const float* __restrict__ g,
                                                 const float* __restrict__ b,
                                                 __half* __restrict__ o)
{
    int row = blockIdx.x;
    int t = threadIdx.x;
    const float4* xr = reinterpret_cast<const float4*>(x + (size_t)row * DD);
    float4 xv = xr[t];

    float s  = xv.x + xv.y + xv.z + xv.w;
    float s2 = xv.x*xv.x + xv.y*xv.y + xv.z*xv.z + xv.w*xv.w;

    __shared__ float red[2][8];
    #pragma unroll
    for (int off = 16; off > 0; off >>= 1) {
        s  += __shfl_xor_sync(0xffffffffu, s,  off);
        s2 += __shfl_xor_sync(0xffffffffu, s2, off);
    }
    int w = t >> 5, l = t & 31;
    if (l == 0) { red[0][w] = s; red[1][w] = s2; }
    __syncthreads();
    __shared__ float smu, srstd;
    if (t == 0) {
        float ts = 0.f, ts2 = 0.f;
        #pragma unroll
        for (int i = 0; i < 8; i++) { ts += red[0][i]; ts2 += red[1][i]; }
        float mu = ts * (1.0f / DD);
        float var = ts2 * (1.0f / DD) - mu * mu;
        smu = mu;
        srstd = rsqrtf(var + 1e-5f);
    }
    __syncthreads();
    float mu = smu, rstd = srstd;

    const float4 gv = reinterpret_cast<const float4*>(g)[t];
    const float4 bv = reinterpret_cast<const float4*>(b)[t];
    float o0 = (xv.x - mu) * rstd * gv.x + bv.x;
    float o1 = (xv.y - mu) * rstd * gv.y + bv.y;
    float o2 = (xv.z - mu) * rstd * gv.z + bv.z;
    float o3 = (xv.w - mu) * rstd * gv.w + bv.w;
    size_t idx = (size_t)row * DD + t * 4;
    __half2 p0 = __halves2half2(__float2half_rn(o0), __float2half_rn(o1));
    __half2 p1 = __halves2half2(__float2half_rn(o2), __float2half_rn(o3));
    *reinterpret_cast<__half2*>(o + idx)     = p0;
    *reinterpret_cast<__half2*>(o + idx + 2) = p1;
}

// ---------------------------------------------------------------------------
// HMMA GEMM: 128x256 tile, BK=64, 4-stage, 2x4 warps, frag double-buffer.
// ---------------------------------------------------------------------------
#define STAGE_BYTES 49152
#define NSTAGE 4
#define GEMM_SMEM (NSTAGE * STAGE_BYTES)
#define GTHREADS 256

__device__ __forceinline__ void load_stage(
    uint32_t st, const char* A, const char* B,
    int K, int row0, int col0, int kc, int tid)
{
    size_t kb = (size_t)kc * 128;
    #pragma unroll
    for (int i = 0; i < 4; i++) {
        int id = tid + GTHREADS * i;
        int row = id >> 3, ch = id & 7;
        size_t ga = (size_t)(row0 + row) * K * 2 + kb + ch * 16;
        cp_async16(st + tile_off(row, ch), A + ga);
    }
    #pragma unroll
    for (int i = 0; i < 8; i++) {
        int id = tid + GTHREADS * i;
        int row = id >> 3, ch = id & 7;
        size_t gb = (size_t)(col0 + row) * K * 2 + kb + ch * 16;
        cp_async16(st + 16384 + tile_off(row, ch), B + gb);
    }
}

__device__ __forceinline__ void ld_frags(
    uint32_t st, int ks, int aRow, int aHalf, int wc, int bRowL, int bHalf,
    uint32_t fa[4][4], uint32_t fb[8][2])
{
    #pragma unroll
    for (int mt = 0; mt < 4; mt++) {
        uint32_t off = tile_off(aRow + mt * 16, ks * 2 + aHalf);
        ldsm4(fa[mt][0], fa[mt][1], fa[mt][2], fa[mt][3], st + off);
    }
    #pragma unroll
    for (int p = 0; p < 4; p++) {
        uint32_t off = tile_off(wc * 64 + p * 16 + bRowL, ks * 2 + bHalf);
        ldsm4(fb[2*p][0], fb[2*p][1], fb[2*p+1][0], fb[2*p+1][1],
              st + 16384 + off);
    }
}

__global__ __launch_bounds__(GTHREADS, 1) void mma_gemm_kernel(
    const __half* __restrict__ A, const __half* __restrict__ B,
    int M, int N, int K,
    float* __restrict__ Cf, const float* __restrict__ bias,
    const float* __restrict__ residual,
    __half* __restrict__ Ch,
    __half* __restrict__ kOut, __half* __restrict__ vOut, int mode)
{
    extern __shared__ char smem[];
    uint32_t sbase = smem_u32(smem);

    int tid = threadIdx.x;
    int wid = tid >> 5, l = tid & 31;
    int wr = wid >> 2, wc = wid & 3;
    int row0 = blockIdx.y * 128;
    int col0 = blockIdx.x * 256;
    int CH = K >> 6;

    const char* pA = (const char*)A;
    const char* pB = (const char*)B;

    float acc[4][8][4];
    #pragma unroll
    for (int i = 0; i < 4; i++)
        #pragma unroll
        for (int j = 0; j < 8; j++)
            #pragma unroll
            for (int t = 0; t < 4; t++) acc[i][j][t] = 0.f;

    int aRow = wr * 64 + (l & 15);
    int aHalf = (l >> 4) & 1;
    int bRowL = (l & 7) + ((l >> 4) & 1) * 8;
    int bHalf = (l >> 3) & 1;

    load_stage(sbase,                   pA, pB, K, row0, col0, 0, tid);
    cp_commit();
    load_stage(sbase + STAGE_BYTES,     pA, pB, K, row0, col0, 1, tid);
    cp_commit();
    load_stage(sbase + 2 * STAGE_BYTES, pA, pB, K, row0, col0, 2, tid);
    cp_commit();

    uint32_t fa[2][4][4], fb[2][8][2];

    for (int c = 0; c < CH; c++) {
        cp_wait<2>();
        __syncthreads();
        int nc = c + 3 < CH ? c + 3 : CH - 1;
        load_stage(sbase + ((c + 3) & (NSTAGE - 1)) * STAGE_BYTES,
                   pA, pB, K, row0, col0, nc, tid);
        cp_commit();

        uint32_t st = sbase + (c & (NSTAGE - 1)) * STAGE_BYTES;
        ld_frags(st, 0, aRow, aHalf, wc, bRowL, bHalf, fa[0], fb[0]);
        #pragma unroll
        for (int ks = 0; ks < 4; ks++) {
            int cur = ks & 1;
            if (ks < 3)
                ld_frags(st, ks + 1, aRow, aHalf, wc, bRowL, bHalf,
                         fa[cur ^ 1], fb[cur ^ 1]);
            #pragma unroll
            for (int mt = 0; mt < 4; mt++)
                #pragma unroll
                for (int nt = 0; nt < 8; nt++)
                    mma16816(acc[mt][nt], fa[cur][mt], fb[cur][nt][0], fb[cur][nt][1]);
        }
    }

    int rb = row0 + wr * 64 + (l >> 2);
    int cb = col0 + wc * 64 + (l & 3) * 2;

    if (mode == 3) {
        int seg = col0 >> 10;
        __half* dst = (seg == 0) ? Ch : ((seg == 1) ? kOut : vOut);
        int csub = seg << 10;
        bool dorelu = (seg < 2);
        #pragma unroll
        for (int mt = 0; mt < 4; mt++)
            #pragma unroll
            for (int half = 0; half < 2; half++) {
                int r = rb + mt * 16 + half * 8;
                #pragma unroll
                for (int nt = 0; nt < 8; nt++) {
                    int ccol = cb + nt * 8 - csub;
                    float v0 = acc[mt][nt][half * 2];
                    float v1 = acc[mt][nt][half * 2 + 1];
                    if (dorelu) {
                        v0 = fmaxf(v0, 0.f) + 1e-6f;
                        v1 = fmaxf(v1, 0.f) + 1e-6f;
                    }
                    *reinterpret_cast<__half2*>(dst + (size_t)r * 1024 + ccol) =
                        __halves2half2(__float2half_rn(v0), __float2half_rn(v1));
                }
            }
        return;
    }

    #pragma unroll
    for (int mt = 0; mt < 4; mt++) {
        #pragma unroll
        for (int half = 0; half < 2; half++) {
            int r = rb + mt * 16 + half * 8;
            #pragma unroll
            for (int nt = 0; nt < 8; nt++) {
                int ccol = cb + nt * 8;
                float v0 = acc[mt][nt][half * 2];
                float v1 = acc[mt][nt][half * 2 + 1];
                if (mode == 2) {
                    v0 += bias[ccol];
                    v1 += bias[ccol + 1];
                    v0 = 0.5f * v0 * (1.0f + erff(v0 * 0.70710678118654752f));
                    v1 = 0.5f * v1 * (1.0f + erff(v1 * 0.70710678118654752f));
                    *reinterpret_cast<__half2*>(Ch + (size_t)r * N + ccol) =
                        __halves2half2(__float2half_rn(v0), __float2half_rn(v1));
                } else {
                    if (mode == 1) {
                        v0 += bias[ccol];
                        v1 += bias[ccol + 1];
                        const float2 rr = *reinterpret_cast<const float2*>(
                            residual + (size_t)r * N + ccol);
                        v0 += rr.x; v1 += rr.y;
                    }
                    float2 o; o.x = v0; o.y = v1;
                    *reinterpret_cast<float2*>(Cf + (size_t)r * N + ccol) = o;
                }
            }
        }
    }
}

// ---------------------------------------------------------------------------
// kv via tensor cores: per bh, C[f][d] = sum_t k[t][f] * v[t][d]  (K=4096)
// Block 128 thr (4 warps, K-split), grid 64. Writes kvT fp16 [bh][d][f].
// ---------------------------------------------------------------------------
#define KV_SMEM 65536
__global__ __launch_bounds__(128, 1) void kv_mma_kernel(
    const __half* __restrict__ kf, const __half* __restrict__ vv,
    __half* __restrict__ kvT)
{
    extern __shared__ char smem[];
    uint32_t sb = smem_u32(smem);
    int bh = blockIdx.x;
    int b = bh >> 4, h = bh & 15;
    int tid = threadIdx.x, w = tid >> 5, l = tid & 31;
    size_t gbase = (size_t)b * SS * DD + (size_t)h * 64;   // halfs

    float acc[4][8][4];
    #pragma unroll
    for (int i = 0; i < 4; i++)
        #pragma unroll
        for (int j = 0; j < 8; j++)
            #pragma unroll
            for (int t = 0; t < 4; t++) acc[i][j][t] = 0.f;

    // per-lane trans-ldmatrix geometry
    int aTrow = ((l >> 4) & 1) * 8 + (l & 7);   // A: t-offset row
    int aFoff = ((l >> 3) & 1) * 8;             // A: f-offset
    int bTrow = ((l >> 3) & 1) * 8 + (l & 7);   // B: t-offset row
    int bDoff = ((l >> 4) & 1) * 8;             // B: d-offset

    auto load_tile = [&](int it) {
        uint32_t st = sb + (it & 1) * 16384;
        int t0 = it * 64;
        #pragma unroll
        for (int i = 0; i < 4; i++) {
            int id = tid + 128 * i;
            int row = id >> 3, ch = id & 7;
            size_t go = gbase + (size_t)(t0 + row) * DD + ch * 8;
            cp_async16(st + tile_off(row, ch),        (const char*)(kf + go));
            cp_async16(st + 8192 + tile_off(row, ch), (const char*)(vv + go));
        }
    };

    load_tile(0);
    cp_commit();

    for (int it = 0; it < 64; it++) {
        if (it < 63) { load_tile(it + 1); cp_commit(); cp_wait<1>(); }
        else cp_wait<0>();
        __syncthreads();
        uint32_t st = sb + (it & 1) * 16384;
        int t0w = w * 16;
        uint32_t af[4][4], bf[8][2];
        #pragma unroll
        for (int mt = 0; mt < 4; mt++) {
            int f0 = mt * 16 + aFoff;
            ldsm4t(af[mt][0], af[mt][1], af[mt][2], af[mt][3],
                   st + tile_off(t0w + aTrow, f0 >> 3));
        }
        #pragma unroll
        for (int p = 0; p < 4; p++) {
            int d0 = p * 16 + bDoff;
            uint32_t r0, r1, r2, r3;
            ldsm4t(r0, r1, r2, r3, st + 8192 + tile_off(t0w + bTrow, d0 >> 3));
            bf[2*p][0] = r0; bf[2*p][1] = r1;
            bf[2*p+1][0] = r2; bf[2*p+1][1] = r3;
        }
        #pragma unroll
        for (int mt = 0; mt < 4; mt++)
            #pragma unroll
            for (int nt = 0; nt < 8; nt++)
                mma16816(acc[mt][nt], af[mt], bf[nt][0], bf[nt][1]);
        __syncthreads();
    }

    // cross-warp reduce via smem: red[w][f][d]
    float* red = (float*)smem;
    #pragma unroll
    for (int mt = 0; mt < 4; mt++)
        #pragma unroll
        for (int half = 0; half < 2; half++) {
            int f = mt * 16 + half * 8 + (l >> 2);
            #pragma unroll
            for (int nt = 0; nt < 8; nt++) {
                int d = nt * 8 + (l & 3) * 2;
                red[w * 4096 + f * 64 + d]     = acc[mt][nt][half * 2];
                red[w * 4096 + f * 64 + d + 1] = acc[mt][nt][half * 2 + 1];
            }
        }
    __syncthreads();
    for (int j = tid; j < 4096; j += 128) {
        int d = j >> 6, f = j & 63;
        int s = f * 64 + d;
        float v = red[s] + red[4096 + s] + red[8192 + s] + red[12288 + s];
        kvT[(size_t)bh * 4096 + j] = __float2half_rn(v);
    }
}

// ---------------------------------------------------------------------------
// ksum[bh][f] = sum_t k[t][bh*64+f]   (grid 64, block 256: 4 token-slices)
// ---------------------------------------------------------------------------
__global__ __launch_bounds__(256) void ksum_kernel(const __half* __restrict__ kf,
                                                   float* __restrict__ ksum)
{
    __shared__ float part[4][64];
    int bh = blockIdx.x;
    int b = bh >> 4, h = bh & 15;
    int tid = threadIdx.x;
    int f = tid & 63, s = tid >> 6;
    size_t gbase = (size_t)b * SS * DD + (size_t)h * 64 + f;
    float acc = 0.f;
    for (int t = s * 1024; t < (s + 1) * 1024; t++)
        acc += __half2float(kf[gbase + (size_t)t * DD]);
    part[s][f] = acc;
    __syncthreads();
    if (tid < 64)
        ksum[bh * 64 + tid] = part[0][tid] + part[1][tid] + part[2][tid] + part[3][tid];
}

// ---------------------------------------------------------------------------
// attn via tensor cores: per (bh, 128-token tile):
//   num = q[128x64] @ kvT^T, den = q . ksum;  at = num/den (fp16)
// ---------------------------------------------------------------------------
__global__ __launch_bounds__(128) void attn_mma_kernel(
    const __half* __restrict__ qf, const __half* __restrict__ kvT,
    const float* __restrict__ ksum, __half* __restrict__ o)
{
    __shared__ __align__(16) char qs[128 * 128];
    __shared__ __align__(16) char kvs[64 * 128];
    __shared__ float sksum[64];
    __shared__ float sinv[128];

    int bh = blockIdx.x;
    int b = bh >> 4, h = bh & 15;
    int t0 = blockIdx.y * 128;
    int tid = threadIdx.x, w = tid >> 5, l = tid & 31;
    uint32_t qsb = smem_u32(qs), kvsb = smem_u32(kvs);
    size_t gbase = (size_t)b * SS * DD + (size_t)h * 64;

    #pragma unroll
    for (int i = 0; i < 8; i++) {
        int id = tid + 128 * i;
        int row = id >> 3, ch = id & 7;
        cp_async16(qsb + tile_off(row, ch),
                   (const char*)(qf + gbase + (size_t)(t0 + row) * DD + ch * 8));
    }
    #pragma unroll
    for (int i = 0; i < 4; i++) {
        int id = tid + 128 * i;
        int row = id >> 3, ch = id & 7;
        cp_async16(kvsb + tile_off(row, ch),
                   (const char*)(kvT + (size_t)bh * 4096 + row * 64 + ch * 8));
    }
    cp_commit();
    if (tid < 64) sksum[tid] = ksum[bh * 64 + tid];
    cp_wait<0>();
    __syncthreads();

    {
        float den = 0.f;
        #pragma unroll 8
        for (int f = 0; f < 64; f++) {
            __half qv = *reinterpret_cast<const __half*>(
                qs + tile_off(tid, f >> 3) + (f & 7) * 2);
            den = fmaf(__half2float(qv), sksum[f], den);
        }
        sinv[tid] = 1.0f / (den + 1e-6f);
    }
    __syncthreads();

    float acc[2][8][4];
    #pragma unroll
    for (int i = 0; i < 2; i++)
        #pragma unroll
        for (int j = 0; j < 8; j++)
            #pragma unroll
            for (int t = 0; t < 4; t++) acc[i][j][t] = 0.f;

    int aRow = w * 32 + (l & 15);
    int aHalf = (l >> 4) & 1;
    int bRowL = (l & 7) + ((l >> 4) & 1) * 8;
    int bHalf = (l >> 3) & 1;

    #pragma unroll
    for (int ks = 0; ks < 4; ks++) {
        uint32_t af[2][4], bf[8][2];
        #pragma unroll
        for (int mt = 0; mt < 2; mt++)
            ldsm4(af[mt][0], af[mt][1], af[mt][2], af[mt][3],
                  qsb + tile_off(aRow + mt * 16, ks * 2 + aHalf));
        #pragma unroll
        for (int p = 0; p < 4; p++)
            ldsm4(bf[2*p][0], bf[2*p][1], bf[2*p+1][0], bf[2*p+1][1],
                  kvsb + tile_off(p * 16 + bRowL, ks * 2 + bHalf));
        #pragma unroll
        for (int mt = 0; mt < 2; mt++)
            #pragma unroll
            for (int nt = 0; nt < 8; nt++)
                mma16816(acc[mt][nt], af[mt], bf[nt][0], bf[nt][1]);
    }

    #pragma unroll
    for (int mt = 0; mt < 2; mt++)
        #pragma unroll
        for (int half = 0; half < 2; half++) {
            int row = w * 32 + mt * 16 + half * 8 + (l >> 2);
            float inv = sinv[row];
            size_t obase = gbase + (size_t)(t0 + row) * DD;
            #pragma unroll
            for (int nt = 0; nt < 8; nt++) {
                int d = nt * 8 + (l & 3) * 2;
                float v0 = acc[mt][nt][half * 2] * inv;
                float v1 = acc[mt][nt][half * 2 + 1] * inv;
                *reinterpret_cast<__half2*>(o + obase + d) =
                    __halves2half2(__float2half_rn(v0), __float2half_rn(v1));
            }
        }
}

// ---------------------------------------------------------------------------
// Launch
// ---------------------------------------------------------------------------
extern "C" void kernel_launch(void* const* d_in, const int* in_sizes, int n_in,
                              void* d_out, int out_size)
{
    const float* x     = (const float*)d_in[0];
    const float* ln1_g = (const float*)d_in[1];
    const float* ln1_b = (const float*)d_in[2];
    const float* wq    = (const float*)d_in[3];
    const float* wk    = (const float*)d_in[4];
    const float* wv    = (const float*)d_in[5];
    const float* proj  = (const float*)d_in[6];
    const float* wo    = (const float*)d_in[7];
    const float* bo    = (const float*)d_in[8];
    const float* ln2_g = (const float*)d_in[9];
    const float* ln2_b = (const float*)d_in[10];
    const float* w1    = (const float*)d_in[11];
    const float* b1    = (const float*)d_in[12];
    const float* w2    = (const float*)d_in[13];
    const float* b2    = (const float*)d_in[14];
    float* out = (float*)d_out;

    float *qraw, *ksum;
    __half *kbuf, *vbuf, *h, *at, *ffn, *wqkvT, *woT, *w1T, *w2T, *kvT;
    cudaGetSymbolAddress((void**)&qraw, g_q);
    cudaGetSymbolAddress((void**)&kbuf, g_kbuf);
    cudaGetSymbolAddress((void**)&vbuf, g_vbuf);
    cudaGetSymbolAddress((void**)&kvT, g_kvT);
    cudaGetSymbolAddress((void**)&ksum, g_ksum);
    cudaGetSymbolAddress((void**)&h, g_h);
    cudaGetSymbolAddress((void**)&at, g_at);
    cudaGetSymbolAddress((void**)&ffn, g_ffn);
    cudaGetSymbolAddress((void**)&wqkvT, g_wqkvT);
    cudaGetSymbolAddress((void**)&woT, g_woT);
    cudaGetSymbolAddress((void**)&w1T, g_w1T);
    cudaGetSymbolAddress((void**)&w2T, g_w2T);
    __half* qbuf = (__half*)qraw;   // fp16 q view (front 32MB of 64MB buffer)

    cudaFuncSetAttribute(mma_gemm_kernel,
                         cudaFuncAttributeMaxDynamicSharedMemorySize, GEMM_SMEM);
    cudaFuncSetAttribute(kv_mma_kernel,
                         cudaFuncAttributeMaxDynamicSharedMemorySize, KV_SMEM);

    // --- weight prep ---
    float* tmp0 = qraw + 8 * 1024 * 1024;   // fp32 temps (back half of g_q)
    float* tmp1 = qraw + 9 * 1024 * 1024;
    fold_kernel<<<dim3(DD / 64, HH), 256>>>(wq, proj, tmp0);
    fold_kernel<<<dim3(DD / 64, HH), 256>>>(wk, proj, tmp1);
    ts_kernel<<<dim3(DD / 32, DD / 32), 256>>>(tmp0, wqkvT,               DD, DD);
    ts_kernel<<<dim3(DD / 32, DD / 32), 256>>>(tmp1, wqkvT + 1024 * 1024, DD, DD);
    ts_kernel<<<dim3(DD / 32, DD / 32), 256>>>(wv,   wqkvT + 2048 * 1024, DD, DD);
    ts_kernel<<<dim3(DD / 32, DD / 32), 256>>>(wo, woT, DD, DD);
    ts_kernel<<<dim3(DFF / 32, DD / 32), 256>>>(w1, w1T, DD, DFF);
    ts_kernel<<<dim3(DD / 32, DFF / 32), 256>>>(w2, w2T, DFF, DD);

    // LN1 -> h (fp16)
    ln_kernel<<<NTOK, 256>>>(x, ln1_g, ln1_b, h);

    // Fused QKV GEMM: N=3072 -> q (relu+eps), k (relu+eps), v  (all fp16)
    dim3 gQKV(3072 / 256, NTOK / 128);
    mma_gemm_kernel<<<gQKV, GTHREADS, GEMM_SMEM>>>(h, wqkvT,
        NTOK, 3072, DD, nullptr, nullptr, nullptr, qbuf, kbuf, vbuf, 3);

    // kv (tensor cores) + ksum
    kv_mma_kernel<<<64, 128, KV_SMEM>>>(kbuf, vbuf, kvT);
    ksum_kernel<<<64, 256>>>(kbuf, ksum);

    // attn (tensor cores) -> fp16
    attn_mma_kernel<<<dim3(64, SS / 128), 128>>>(qbuf, kvT, ksum, at);

    // x2 = x + attn @ wo + bo -> out (fp32)
    dim3 gD(DD / 256, NTOK / 128);
    mma_gemm_kernel<<<gD, GTHREADS, GEMM_SMEM>>>(at, woT,
        NTOK, DD, DD, out, bo, x, nullptr, nullptr, nullptr, 1);

    // LN2 -> h (fp16)
    ln_kernel<<<NTOK, 256>>>(out, ln2_g, ln2_b, h);

    // ffn = gelu(h2 @ w1 + b1) -> fp16
    dim3 gF1(DFF / 256, NTOK / 128);
    mma_gemm_kernel<<<gF1, GTHREADS, GEMM_SMEM>>>(h, w1T,
        NTOK, DFF, DD, nullptr, b1, nullptr, ffn, nullptr, nullptr, 2);

    // out = x2 + ffn @ w2 + b2 (in-place residual)
    mma_gemm_kernel<<<gD, GTHREADS, GEMM_SMEM>>>(ffn, w2T,
        NTOK, DD, DFF, out, b2, out, nullptr, nullptr, nullptr, 1);
}

// round 14
// speedup vs baseline: 8.4956x; 1.0936x over previous
#include <cuda_runtime.h>
#include <cuda_fp16.h>
#include <math.h>
#include <stdint.h>

// ---------------------------------------------------------------------------
// Problem constants
// ---------------------------------------------------------------------------
#define BB 4
#define SS 4096
#define DD 1024
#define HH 16
#define DH 64
#define FF 64
#define DFF 4096
#define NTOK (BB * SS)            // 16384 tokens

// ---------------------------------------------------------------------------
// Scratch (static device globals)
// ---------------------------------------------------------------------------
__device__ float g_q[(size_t)NTOK * DD];       // fp16 q view + fp32 prep temps
__device__ __half g_kbuf[(size_t)NTOK * DD];
__device__ __half g_vbuf[(size_t)NTOK * DD];
__device__ __half g_h[(size_t)NTOK * DD];      // LN out (A operand), fp16
__device__ __half g_at[(size_t)NTOK * DD];     // attn out (A of wo), fp16
__device__ __half g_ffn[(size_t)NTOK * DFF];   // gelu out (A of w2), fp16
// Transposed single-fp16 weights, [N, K]
__device__ __half g_wqkvT[3 * DD * DD];    // folded q, folded k, v
__device__ __half g_woT[DD * DD];
__device__ __half g_w1T[(size_t)DFF * DD];
__device__ __half g_w2T[(size_t)DD * DFF];
// linear-attention small tensors
__device__ __half g_kvT[64 * FF * DH];     // [bh][d][f] fp16 (B^T for attn mma)
__device__ float g_ksum[64 * FF];

// ---------------------------------------------------------------------------
// PTX helpers (baseline PTX only — no 'a'-suffix features)
// ---------------------------------------------------------------------------
__device__ __forceinline__ uint32_t smem_u32(const void* p) {
    uint32_t a;
    asm("{ .reg .u64 t; cvta.to.shared.u64 t, %1; cvt.u32.u64 %0, t; }"
        : "=r"(a) : "l"(p));
    return a;
}
__device__ __forceinline__ void cp_async16(uint32_t dst, const void* src) {
    asm volatile("cp.async.cg.shared.global [%0], [%1], 16;\n" :: "r"(dst), "l"(src));
}
__device__ __forceinline__ void cp_commit() {
    asm volatile("cp.async.commit_group;\n" ::: "memory");
}
template <int N>
__device__ __forceinline__ void cp_wait() {
    asm volatile("cp.async.wait_group %0;\n" :: "n"(N) : "memory");
}
__device__ __forceinline__ void ldsm4(uint32_t& r0, uint32_t& r1, uint32_t& r2,
                                      uint32_t& r3, uint32_t addr) {
    asm volatile("ldmatrix.sync.aligned.m8n8.x4.shared.b16 {%0,%1,%2,%3}, [%4];"
                 : "=r"(r0), "=r"(r1), "=r"(r2), "=r"(r3) : "r"(addr));
}
__device__ __forceinline__ void ldsm4t(uint32_t& r0, uint32_t& r1, uint32_t& r2,
                                       uint32_t& r3, uint32_t addr) {
    asm volatile("ldmatrix.sync.aligned.m8n8.x4.trans.shared.b16 {%0,%1,%2,%3}, [%4];"
                 : "=r"(r0), "=r"(r1), "=r"(r2), "=r"(r3) : "r"(addr));
}
__device__ __forceinline__ void mma16816(float* c, const uint32_t* a,
                                         uint32_t b0, uint32_t b1) {
    asm volatile(
        "mma.sync.aligned.m16n8k16.row.col.f32.f16.f16.f32 "
        "{%0,%1,%2,%3}, {%4,%5,%6,%7}, {%8,%9}, {%0,%1,%2,%3};"
        : "+f"(c[0]), "+f"(c[1]), "+f"(c[2]), "+f"(c[3])
        : "r"(a[0]), "r"(a[1]), "r"(a[2]), "r"(a[3]), "r"(b0), "r"(b1));
}

// swizzled 16B-chunk offset within an Rx64 fp16 tile (128B rows, 8-phase XOR)
__device__ __forceinline__ uint32_t tile_off(int row, int ch) {
    return (uint32_t)(row * 128 + ((ch ^ (row & 7)) << 4));
}

// ---------------------------------------------------------------------------
// Fold proj into a QK weight: out[d, h*64+f] = sum_dh W[d, h*64+dh]*proj[dh,f]
// ---------------------------------------------------------------------------
__global__ __launch_bounds__(256) void fold_kernel(const float* __restrict__ W,
                                                   const float* __restrict__ proj,
                                                   float* __restrict__ outW)
{
    __shared__ float projS[64][64];
    __shared__ float wS[64][65];
    int d0 = blockIdx.x * 64, h = blockIdx.y;
    int tid = threadIdx.x;
    for (int i = tid; i < 64 * 64; i += 256)
        projS[i >> 6][i & 63] = proj[i];
    for (int i = tid; i < 64 * 64; i += 256)
        wS[i >> 6][i & 63] = W[(size_t)(d0 + (i >> 6)) * (HH * DH) + h * 64 + (i & 63)];
    __syncthreads();
    int r = tid >> 2;
    int fb = (tid & 3) * 16;
    float acc[16];
    #pragma unroll
    for (int i = 0; i < 16; i++) acc[i] = 0.f;
    #pragma unroll 8
    for (int c = 0; c < 64; c++) {
        float w = wS[r][c];
        #pragma unroll
        for (int i = 0; i < 16; i++)
            acc[i] = fmaf(w, projS[c][fb + i], acc[i]);
    }
    for (int i = 0; i < 16; i++)
        outW[(size_t)(d0 + r) * (HH * FF) + h * 64 + fb + i] = acc[i];
}

// ---------------------------------------------------------------------------
// Weight transpose + fp16 convert:  W[K,N] -> Wt[N,K]
// ---------------------------------------------------------------------------
__global__ __launch_bounds__(256) void ts_kernel(const float* __restrict__ W,
                                                 __half* __restrict__ o,
                                                 int K, int N)
{
    __shared__ float t[32][33];
    int n0 = blockIdx.x * 32, k0 = blockIdx.y * 32;
    int tx = threadIdx.x & 31, ty = threadIdx.x >> 5;
    for (int r = ty; r < 32; r += 8)
        t[r][tx] = W[(size_t)(k0 + r) * N + n0 + tx];
    __syncthreads();
    for (int r = ty; r < 32; r += 8)
        o[(size_t)(n0 + r) * K + k0 + tx] = __float2half_rn(t[tx][r]);
}

// ---------------------------------------------------------------------------
// LayerNorm -> fp16. One block (256 thr) per row of 1024.
// ---------------------------------------------------------------------------
__global__ __launch_bounds__(256) void ln_kernel(const float* __restrict__ x,
                                                 const float* __restrict__ g,
                                                 const float* __restrict__ b,
                                                 __half* __restrict__ o)
{
    int row = blockIdx.x;
    int t = threadIdx.x;
    const float4* xr = reinterpret_cast<const float4*>(x + (size_t)row * DD);
    float4 xv = xr[t];

    float s  = xv.x + xv.y + xv.z + xv.w;
    float s2 = xv.x*xv.x + xv.y*xv.y + xv.z*xv.z + xv.w*xv.w;

    __shared__ float red[2][8];
    #pragma unroll
    for (int off = 16; off > 0; off >>= 1) {
        s  += __shfl_xor_sync(0xffffffffu, s,  off);
        s2 += __shfl_xor_sync(0xffffffffu, s2, off);
    }
    int w = t >> 5, l = t & 31;
    if (l == 0) { red[0][w] = s; red[1][w] = s2; }
    __syncthreads();
    __shared__ float smu, srstd;
    if (t == 0) {
        float ts = 0.f, ts2 = 0.f;
        #pragma unroll
        for (int i = 0; i < 8; i++) { ts += red[0][i]; ts2 += red[1][i]; }
        float mu = ts * (1.0f / DD);
        float var = ts2 * (1.0f / DD) - mu * mu;
        smu = mu;
        srstd = rsqrtf(var + 1e-5f);
    }
    __syncthreads();
    float mu = smu, rstd = srstd;

    const float4 gv = reinterpret_cast<const float4*>(g)[t];
    const float4 bv = reinterpret_cast<const float4*>(b)[t];
    float o0 = (xv.x - mu) * rstd * gv.x + bv.x;
    float o1 = (xv.y - mu) * rstd * gv.y + bv.y;
    float o2 = (xv.z - mu) * rstd * gv.z + bv.z;
    float o3 = (xv.w - mu) * rstd * gv.w + bv.w;
    size_t idx = (size_t)row * DD + t * 4;
    __half2 p0 = __halves2half2(__float2half_rn(o0), __float2half_rn(o1));
    __half2 p1 = __halves2half2(__float2half_rn(o2), __float2half_rn(o3));
    *reinterpret_cast<__half2*>(o + idx)     = p0;
    *reinterpret_cast<__half2*>(o + idx + 2) = p1;
}

// ---------------------------------------------------------------------------
// HMMA GEMM: 128x128 tile, BK=64, 3-stage cp.async pipeline, 256 threads,
// 2 CTAs/SM (96KB smem each), 2x4 warp grid, warp tile 64x32.
// mode 0: Cf = val
// mode 1: Cf = val + bias + residual
// mode 2: Ch = fp16(gelu(val + bias))
// mode 3: fused qkv (fp16 outs): seg0 relu+eps->Ch(q), seg1 relu+eps->kOut,
//         seg2 ->vOut  (out stride 1024)
// ---------------------------------------------------------------------------
#define STAGE_BYTES 32768
#define NSTAGE 3
#define GEMM_SMEM (NSTAGE * STAGE_BYTES)
#define GTHREADS 256

__device__ __forceinline__ void load_stage(
    uint32_t st, const char* A, const char* B,
    int K, int row0, int col0, int kc, int tid)
{
    size_t kb = (size_t)kc * 128;
    // A: 128 rows x 8 chunks = 1024 chunks, 4/thread
    #pragma unroll
    for (int i = 0; i < 4; i++) {
        int id = tid + GTHREADS * i;
        int row = id >> 3, ch = id & 7;
        size_t ga = (size_t)(row0 + row) * K * 2 + kb + ch * 16;
        cp_async16(st + tile_off(row, ch), A + ga);
    }
    // B: 128 rows x 8 chunks = 1024 chunks, 4/thread
    #pragma unroll
    for (int i = 0; i < 4; i++) {
        int id = tid + GTHREADS * i;
        int row = id >> 3, ch = id & 7;
        size_t gb = (size_t)(col0 + row) * K * 2 + kb + ch * 16;
        cp_async16(st + 16384 + tile_off(row, ch), B + gb);
    }
}

__global__ __launch_bounds__(GTHREADS, 2) void mma_gemm_kernel(
    const __half* __restrict__ A, const __half* __restrict__ B,
    int M, int N, int K,
    float* __restrict__ Cf, const float* __restrict__ bias,
    const float* __restrict__ residual,
    __half* __restrict__ Ch,
    __half* __restrict__ kOut, __half* __restrict__ vOut, int mode)
{
    extern __shared__ char smem[];
    uint32_t sbase = smem_u32(smem);

    int tid = threadIdx.x;
    int wid = tid >> 5, l = tid & 31;
    int wr = wid >> 2, wc = wid & 3;   // 2x4 warp grid: 64x32 per warp
    int row0 = blockIdx.y * 128;
    int col0 = blockIdx.x * 128;
    int CH = K >> 6;

    const char* pA = (const char*)A;
    const char* pB = (const char*)B;

    float acc[4][4][4];
    #pragma unroll
    for (int i = 0; i < 4; i++)
        #pragma unroll
        for (int j = 0; j < 4; j++)
            #pragma unroll
            for (int t = 0; t < 4; t++) acc[i][j][t] = 0.f;

    int aRow = wr * 64 + (l & 15);
    int aHalf = (l >> 4) & 1;
    int bRowL = (l & 7) + ((l >> 4) & 1) * 8;
    int bHalf = (l >> 3) & 1;

    load_stage(sbase,               pA, pB, K, row0, col0, 0, tid);
    cp_commit();
    load_stage(sbase + STAGE_BYTES, pA, pB, K, row0, col0, 1, tid);
    cp_commit();

    int sidx = 0;
    for (int c = 0; c < CH; c++) {
        cp_wait<1>();
        __syncthreads();
        // prefetch stage c+2 (tail-clamped)
        int nc = c + 2 < CH ? c + 2 : CH - 1;
        int widx = sidx + 2; if (widx >= NSTAGE) widx -= NSTAGE;
        load_stage(sbase + widx * STAGE_BYTES, pA, pB, K, row0, col0, nc, tid);
        cp_commit();

        uint32_t st = sbase + sidx * STAGE_BYTES;
        #pragma unroll
        for (int ks = 0; ks < 4; ks++) {
            uint32_t af[4][4];
            #pragma unroll
            for (int mt = 0; mt < 4; mt++) {
                uint32_t off = tile_off(aRow + mt * 16, ks * 2 + aHalf);
                ldsm4(af[mt][0], af[mt][1], af[mt][2], af[mt][3], st + off);
            }
            uint32_t bf[4][2];
            #pragma unroll
            for (int p = 0; p < 2; p++) {
                uint32_t off = tile_off(wc * 32 + p * 16 + bRowL, ks * 2 + bHalf);
                ldsm4(bf[2*p][0], bf[2*p][1], bf[2*p+1][0], bf[2*p+1][1],
                      st + 16384 + off);
            }
            #pragma unroll
            for (int mt = 0; mt < 4; mt++)
                #pragma unroll
                for (int nt = 0; nt < 4; nt++)
                    mma16816(acc[mt][nt], af[mt], bf[nt][0], bf[nt][1]);
        }
        if (++sidx == NSTAGE) sidx = 0;
    }

    // epilogue
    int rb = row0 + wr * 64 + (l >> 2);
    int cb = col0 + wc * 32 + (l & 3) * 2;

    if (mode == 3) {
        int seg = col0 >> 10;                 // 128-tile fully inside a segment
        __half* dst = (seg == 0) ? Ch : ((seg == 1) ? kOut : vOut);
        int csub = seg << 10;
        bool dorelu = (seg < 2);
        #pragma unroll
        for (int mt = 0; mt < 4; mt++)
            #pragma unroll
            for (int half = 0; half < 2; half++) {
                int r = rb + mt * 16 + half * 8;
                #pragma unroll
                for (int nt = 0; nt < 4; nt++) {
                    int ccol = cb + nt * 8 - csub;
                    float v0 = acc[mt][nt][half * 2];
                    float v1 = acc[mt][nt][half * 2 + 1];
                    if (dorelu) {
                        v0 = fmaxf(v0, 0.f) + 1e-6f;
                        v1 = fmaxf(v1, 0.f) + 1e-6f;
                    }
                    *reinterpret_cast<__half2*>(dst + (size_t)r * 1024 + ccol) =
                        __halves2half2(__float2half_rn(v0), __float2half_rn(v1));
                }
            }
        return;
    }

    #pragma unroll
    for (int mt = 0; mt < 4; mt++) {
        #pragma unroll
        for (int half = 0; half < 2; half++) {
            int r = rb + mt * 16 + half * 8;
            #pragma unroll
            for (int nt = 0; nt < 4; nt++) {
                int ccol = cb + nt * 8;
                float v0 = acc[mt][nt][half * 2];
                float v1 = acc[mt][nt][half * 2 + 1];
                if (mode == 2) {
                    v0 += bias[ccol];
                    v1 += bias[ccol + 1];
                    v0 = 0.5f * v0 * (1.0f + erff(v0 * 0.70710678118654752f));
                    v1 = 0.5f * v1 * (1.0f + erff(v1 * 0.70710678118654752f));
                    *reinterpret_cast<__half2*>(Ch + (size_t)r * N + ccol) =
                        __halves2half2(__float2half_rn(v0), __float2half_rn(v1));
                } else {
                    if (mode == 1) {
                        v0 += bias[ccol];
                        v1 += bias[ccol + 1];
                        const float2 rr = *reinterpret_cast<const float2*>(
                            residual + (size_t)r * N + ccol);
                        v0 += rr.x; v1 += rr.y;
                    }
                    float2 o; o.x = v0; o.y = v1;
                    *reinterpret_cast<float2*>(Cf + (size_t)r * N + ccol) = o;
                }
            }
        }
    }
}

// ---------------------------------------------------------------------------
// kv via tensor cores: per bh, C[f][d] = sum_t k[t][f] * v[t][d]  (K=4096)
// Block 128 thr (4 warps, K-split), grid 64. Writes kvT fp16 [bh][d][f].
// ---------------------------------------------------------------------------
#define KV_SMEM 65536
__global__ __launch_bounds__(128, 1) void kv_mma_kernel(
    const __half* __restrict__ kf, const __half* __restrict__ vv,
    __half* __restrict__ kvT)
{
    extern __shared__ char smem[];
    uint32_t sb = smem_u32(smem);
    int bh = blockIdx.x;
    int b = bh >> 4, h = bh & 15;
    int tid = threadIdx.x, w = tid >> 5, l = tid & 31;
    size_t gbase = (size_t)b * SS * DD + (size_t)h * 64;   // halfs

    float acc[4][8][4];
    #pragma unroll
    for (int i = 0; i < 4; i++)
        #pragma unroll
        for (int j = 0; j < 8; j++)
            #pragma unroll
            for (int t = 0; t < 4; t++) acc[i][j][t] = 0.f;

    // per-lane trans-ldmatrix geometry
    int aTrow = ((l >> 4) & 1) * 8 + (l & 7);   // A: t-offset row
    int aFoff = ((l >> 3) & 1) * 8;             // A: f-offset
    int bTrow = ((l >> 3) & 1) * 8 + (l & 7);   // B: t-offset row
    int bDoff = ((l >> 4) & 1) * 8;             // B: d-offset

    auto load_tile = [&](int it) {
        uint32_t st = sb + (it & 1) * 16384;
        int t0 = it * 64;
        #pragma unroll
        for (int i = 0; i < 4; i++) {
            int id = tid + 128 * i;
            int row = id >> 3, ch = id & 7;
            size_t go = gbase + (size_t)(t0 + row) * DD + ch * 8;
            cp_async16(st + tile_off(row, ch),        (const char*)(kf + go));
            cp_async16(st + 8192 + tile_off(row, ch), (const char*)(vv + go));
        }
    };

    load_tile(0);
    cp_commit();

    for (int it = 0; it < 64; it++) {
        if (it < 63) { load_tile(it + 1); cp_commit(); cp_wait<1>(); }
        else cp_wait<0>();
        __syncthreads();
        uint32_t st = sb + (it & 1) * 16384;
        int t0w = w * 16;
        uint32_t af[4][4], bf[8][2];
        #pragma unroll
        for (int mt = 0; mt < 4; mt++) {
            int f0 = mt * 16 + aFoff;
            ldsm4t(af[mt][0], af[mt][1], af[mt][2], af[mt][3],
                   st + tile_off(t0w + aTrow, f0 >> 3));
        }
        #pragma unroll
        for (int p = 0; p < 4; p++) {
            int d0 = p * 16 + bDoff;
            uint32_t r0, r1, r2, r3;
            ldsm4t(r0, r1, r2, r3, st + 8192 + tile_off(t0w + bTrow, d0 >> 3));
            bf[2*p][0] = r0; bf[2*p][1] = r1;
            bf[2*p+1][0] = r2; bf[2*p+1][1] = r3;
        }
        #pragma unroll
        for (int mt = 0; mt < 4; mt++)
            #pragma unroll
            for (int nt = 0; nt < 8; nt++)
                mma16816(acc[mt][nt], af[mt], bf[nt][0], bf[nt][1]);
        __syncthreads();
    }

    // cross-warp reduce via smem: red[w][f][d]
    float* red = (float*)smem;
    #pragma unroll
    for (int mt = 0; mt < 4; mt++)
        #pragma unroll
        for (int half = 0; half < 2; half++) {
            int f = mt * 16 + half * 8 + (l >> 2);
            #pragma unroll
            for (int nt = 0; nt < 8; nt++) {
                int d = nt * 8 + (l & 3) * 2;
                red[w * 4096 + f * 64 + d]     = acc[mt][nt][half * 2];
                red[w * 4096 + f * 64 + d + 1] = acc[mt][nt][half * 2 + 1];
            }
        }
    __syncthreads();
    for (int j = tid; j < 4096; j += 128) {
        int d = j >> 6, f = j & 63;
        int s = f * 64 + d;
        float v = red[s] + red[4096 + s] + red[8192 + s] + red[12288 + s];
        kvT[(size_t)bh * 4096 + j] = __float2half_rn(v);
    }
}

// ---------------------------------------------------------------------------
// ksum[bh][f] = sum_t k[t][bh*64+f]   (grid 64, block 256: 4 token-slices)
// ---------------------------------------------------------------------------
__global__ __launch_bounds__(256) void ksum_kernel(const __half* __restrict__ kf,
                                                   float* __restrict__ ksum)
{
    __shared__ float part[4][64];
    int bh = blockIdx.x;
    int b = bh >> 4, h = bh & 15;
    int tid = threadIdx.x;
    int f = tid & 63, s = tid >> 6;
    size_t gbase = (size_t)b * SS * DD + (size_t)h * 64 + f;
    float acc = 0.f;
    for (int t = s * 1024; t < (s + 1) * 1024; t++)
        acc += __half2float(kf[gbase + (size_t)t * DD]);
    part[s][f] = acc;
    __syncthreads();
    if (tid < 64)
        ksum[bh * 64 + tid] = part[0][tid] + part[1][tid] + part[2][tid] + part[3][tid];
}

// ---------------------------------------------------------------------------
// attn via tensor cores: per (bh, 128-token tile):
//   num = q[128x64] @ kvT^T, den = q . ksum;  at = num/den (fp16)
// ---------------------------------------------------------------------------
__global__ __launch_bounds__(128) void attn_mma_kernel(
    const __half* __restrict__ qf, const __half* __restrict__ kvT,
    const float* __restrict__ ksum, __half* __restrict__ o)
{
    __shared__ __align__(16) char qs[128 * 128];
    __shared__ __align__(16) char kvs[64 * 128];
    __shared__ float sksum[64];
    __shared__ float sinv[128];

    int bh = blockIdx.x;
    int b = bh >> 4, h = bh & 15;
    int t0 = blockIdx.y * 128;
    int tid = threadIdx.x, w = tid >> 5, l = tid & 31;
    uint32_t qsb = smem_u32(qs), kvsb = smem_u32(kvs);
    size_t gbase = (size_t)b * SS * DD + (size_t)h * 64;

    #pragma unroll
    for (int i = 0; i < 8; i++) {
        int id = tid + 128 * i;
        int row = id >> 3, ch = id & 7;
        cp_async16(qsb + tile_off(row, ch),
                   (const char*)(qf + gbase + (size_t)(t0 + row) * DD + ch * 8));
    }
    #pragma unroll
    for (int i = 0; i < 4; i++) {
        int id = tid + 128 * i;
        int row = id >> 3, ch = id & 7;
        cp_async16(kvsb + tile_off(row, ch),
                   (const char*)(kvT + (size_t)bh * 4096 + row * 64 + ch * 8));
    }
    cp_commit();
    if (tid < 64) sksum[tid] = ksum[bh * 64 + tid];
    cp_wait<0>();
    __syncthreads();

    {
        float den = 0.f;
        #pragma unroll 8
        for (int f = 0; f < 64; f++) {
            __half qv = *reinterpret_cast<const __half*>(
                qs + tile_off(tid, f >> 3) + (f & 7) * 2);
            den = fmaf(__half2float(qv), sksum[f], den);
        }
        sinv[tid] = 1.0f / (den + 1e-6f);
    }
    __syncthreads();

    float acc[2][8][4];
    #pragma unroll
    for (int i = 0; i < 2; i++)
        #pragma unroll
        for (int j = 0; j < 8; j++)
            #pragma unroll
            for (int t = 0; t < 4; t++) acc[i][j][t] = 0.f;

    int aRow = w * 32 + (l & 15);
    int aHalf = (l >> 4) & 1;
    int bRowL = (l & 7) + ((l >> 4) & 1) * 8;
    int bHalf = (l >> 3) & 1;

    #pragma unroll
    for (int ks = 0; ks < 4; ks++) {
        uint32_t af[2][4], bf[8][2];
        #pragma unroll
        for (int mt = 0; mt < 2; mt++)
            ldsm4(af[mt][0], af[mt][1], af[mt][2], af[mt][3],
                  qsb + tile_off(aRow + mt * 16, ks * 2 + aHalf));
        #pragma unroll
        for (int p = 0; p < 4; p++)
            ldsm4(bf[2*p][0], bf[2*p][1], bf[2*p+1][0], bf[2*p+1][1],
                  kvsb + tile_off(p * 16 + bRowL, ks * 2 + bHalf));
        #pragma unroll
        for (int mt = 0; mt < 2; mt++)
            #pragma unroll
            for (int nt = 0; nt < 8; nt++)
                mma16816(acc[mt][nt], af[mt], bf[nt][0], bf[nt][1]);
    }

    #pragma unroll
    for (int mt = 0; mt < 2; mt++)
        #pragma unroll
        for (int half = 0; half < 2; half++) {
            int row = w * 32 + mt * 16 + half * 8 + (l >> 2);
            float inv = sinv[row];
            size_t obase = gbase + (size_t)(t0 + row) * DD;
            #pragma unroll
            for (int nt = 0; nt < 8; nt++) {
                int d = nt * 8 + (l & 3) * 2;
                float v0 = acc[mt][nt][half * 2] * inv;
                float v1 = acc[mt][nt][half * 2 + 1] * inv;
                *reinterpret_cast<__half2*>(o + obase + d) =
                    __halves2half2(__float2half_rn(v0), __float2half_rn(v1));
            }
        }
}

// ---------------------------------------------------------------------------
// Launch
// ---------------------------------------------------------------------------
extern "C" void kernel_launch(void* const* d_in, const int* in_sizes, int n_in,
                              void* d_out, int out_size)
{
    const float* x     = (const float*)d_in[0];
    const float* ln1_g = (const float*)d_in[1];
    const float* ln1_b = (const float*)d_in[2];
    const float* wq    = (const float*)d_in[3];
    const float* wk    = (const float*)d_in[4];
    const float* wv    = (const float*)d_in[5];
    const float* proj  = (const float*)d_in[6];
    const float* wo    = (const float*)d_in[7];
    const float* bo    = (const float*)d_in[8];
    const float* ln2_g = (const float*)d_in[9];
    const float* ln2_b = (const float*)d_in[10];
    const float* w1    = (const float*)d_in[11];
    const float* b1    = (const float*)d_in[12];
    const float* w2    = (const float*)d_in[13];
    const float* b2    = (const float*)d_in[14];
    float* out = (float*)d_out;

    float *qraw, *ksum;
    __half *kbuf, *vbuf, *h, *at, *ffn, *wqkvT, *woT, *w1T, *w2T, *kvT;
    cudaGetSymbolAddress((void**)&qraw, g_q);
    cudaGetSymbolAddress((void**)&kbuf, g_kbuf);
    cudaGetSymbolAddress((void**)&vbuf, g_vbuf);
    cudaGetSymbolAddress((void**)&kvT, g_kvT);
    cudaGetSymbolAddress((void**)&ksum, g_ksum);
    cudaGetSymbolAddress((void**)&h, g_h);
    cudaGetSymbolAddress((void**)&at, g_at);
    cudaGetSymbolAddress((void**)&ffn, g_ffn);
    cudaGetSymbolAddress((void**)&wqkvT, g_wqkvT);
    cudaGetSymbolAddress((void**)&woT, g_woT);
    cudaGetSymbolAddress((void**)&w1T, g_w1T);
    cudaGetSymbolAddress((void**)&w2T, g_w2T);
    __half* qbuf = (__half*)qraw;   // fp16 q view (front 32MB of 64MB buffer)

    cudaFuncSetAttribute(mma_gemm_kernel,
                         cudaFuncAttributeMaxDynamicSharedMemorySize, GEMM_SMEM);
    cudaFuncSetAttribute(kv_mma_kernel,
                         cudaFuncAttributeMaxDynamicSharedMemorySize, KV_SMEM);

    // --- weight prep ---
    float* tmp0 = qraw + 8 * 1024 * 1024;   // fp32 temps (back half of g_q)
    float* tmp1 = qraw + 9 * 1024 * 1024;
    fold_kernel<<<dim3(DD / 64, HH), 256>>>(wq, proj, tmp0);
    fold_kernel<<<dim3(DD / 64, HH), 256>>>(wk, proj, tmp1);
    ts_kernel<<<dim3(DD / 32, DD / 32), 256>>>(tmp0, wqkvT,               DD, DD);
    ts_kernel<<<dim3(DD / 32, DD / 32), 256>>>(tmp1, wqkvT + 1024 * 1024, DD, DD);
    ts_kernel<<<dim3(DD / 32, DD / 32), 256>>>(wv,   wqkvT + 2048 * 1024, DD, DD);
    ts_kernel<<<dim3(DD / 32, DD / 32), 256>>>(wo, woT, DD, DD);
    ts_kernel<<<dim3(DFF / 32, DD / 32), 256>>>(w1, w1T, DD, DFF);
    ts_kernel<<<dim3(DD / 32, DFF / 32), 256>>>(w2, w2T, DFF, DD);

    // LN1 -> h (fp16)
    ln_kernel<<<NTOK, 256>>>(x, ln1_g, ln1_b, h);

    // Fused QKV GEMM: N=3072 -> q (relu+eps), k (relu+eps), v  (all fp16)
    dim3 gQKV(3072 / 128, NTOK / 128);
    mma_gemm_kernel<<<gQKV, GTHREADS, GEMM_SMEM>>>(h, wqkvT,
        NTOK, 3072, DD, nullptr, nullptr, nullptr, qbuf, kbuf, vbuf, 3);

    // kv (tensor cores) + ksum
    kv_mma_kernel<<<64, 128, KV_SMEM>>>(kbuf, vbuf, kvT);
    ksum_kernel<<<64, 256>>>(kbuf, ksum);

    // attn (tensor cores) -> fp16
    attn_mma_kernel<<<dim3(64, SS / 128), 128>>>(qbuf, kvT, ksum, at);

    // x2 = x + attn @ wo + bo -> out (fp32)
    dim3 gD(DD / 128, NTOK / 128);
    mma_gemm_kernel<<<gD, GTHREADS, GEMM_SMEM>>>(at, woT,
        NTOK, DD, DD, out, bo, x, nullptr, nullptr, nullptr, 1);

    // LN2 -> h (fp16)
    ln_kernel<<<NTOK, 256>>>(out, ln2_g, ln2_b, h);

    // ffn = gelu(h2 @ w1 + b1) -> fp16
    dim3 gF1(DFF / 128, NTOK / 128);
    mma_gemm_kernel<<<gF1, GTHREADS, GEMM_SMEM>>>(h, w1T,
        NTOK, DFF, DD, nullptr, b1, nullptr, ffn, nullptr, nullptr, 2);

    // out = x2 + ffn @ w2 + b2 (in-place residual)
    mma_gemm_kernel<<<gD, GTHREADS, GEMM_SMEM>>>(ffn, w2T,
        NTOK, DD, DFF, out, b2, out, nullptr, nullptr, nullptr, 1);
}

// round 15
// speedup vs baseline: 8.5931x; 1.0115x over previous
#include <cuda_runtime.h>
#include <cuda_fp16.h>
#include <math.h>
#include <stdint.h>

// ---------------------------------------------------------------------------
// Problem constants
// ---------------------------------------------------------------------------
#define BB 4
#define SS 4096
#define DD 1024
#define HH 16
#define DH 64
#define FF 64
#define DFF 4096
#define NTOK (BB * SS)            // 16384 tokens

// ---------------------------------------------------------------------------
// Scratch (static device globals)
// ---------------------------------------------------------------------------
__device__ float g_q[(size_t)NTOK * DD];       // fp16 q view
__device__ __half g_kbuf[(size_t)NTOK * DD];
__device__ __half g_vbuf[(size_t)NTOK * DD];
__device__ __half g_h[(size_t)NTOK * DD];      // LN out (A operand), fp16
__device__ __half g_at[(size_t)NTOK * DD];     // attn out (A of wo), fp16
__device__ __half g_ffn[(size_t)NTOK * DFF];   // gelu out (A of w2), fp16
// Transposed single-fp16 weights, [N, K]
__device__ __half g_wqkvT[3 * DD * DD];    // folded q, folded k, v
__device__ __half g_woT[DD * DD];
__device__ __half g_w1T[(size_t)DFF * DD];
__device__ __half g_w2T[(size_t)DD * DFF];
// linear-attention small tensors
__device__ float g_kvp[2 * 64 * FF * DH];  // kv partials (2 K-chunks)
__device__ __half g_kvT[64 * FF * DH];     // [bh][d][f] fp16 (B^T for attn mma)
__device__ float g_ksum[64 * FF];

// ---------------------------------------------------------------------------
// PTX helpers (baseline PTX only — no 'a'-suffix features)
// ---------------------------------------------------------------------------
__device__ __forceinline__ uint32_t smem_u32(const void* p) {
    uint32_t a;
    asm("{ .reg .u64 t; cvta.to.shared.u64 t, %1; cvt.u32.u64 %0, t; }"
        : "=r"(a) : "l"(p));
    return a;
}
__device__ __forceinline__ void cp_async16(uint32_t dst, const void* src) {
    asm volatile("cp.async.cg.shared.global [%0], [%1], 16;\n" :: "r"(dst), "l"(src));
}
__device__ __forceinline__ void cp_commit() {
    asm volatile("cp.async.commit_group;\n" ::: "memory");
}
template <int N>
__device__ __forceinline__ void cp_wait() {
    asm volatile("cp.async.wait_group %0;\n" :: "n"(N) : "memory");
}
__device__ __forceinline__ void ldsm4(uint32_t& r0, uint32_t& r1, uint32_t& r2,
                                      uint32_t& r3, uint32_t addr) {
    asm volatile("ldmatrix.sync.aligned.m8n8.x4.shared.b16 {%0,%1,%2,%3}, [%4];"
                 : "=r"(r0), "=r"(r1), "=r"(r2), "=r"(r3) : "r"(addr));
}
__device__ __forceinline__ void ldsm4t(uint32_t& r0, uint32_t& r1, uint32_t& r2,
                                       uint32_t& r3, uint32_t addr) {
    asm volatile("ldmatrix.sync.aligned.m8n8.x4.trans.shared.b16 {%0,%1,%2,%3}, [%4];"
                 : "=r"(r0), "=r"(r1), "=r"(r2), "=r"(r3) : "r"(addr));
}
__device__ __forceinline__ void mma16816(float* c, const uint32_t* a,
                                         uint32_t b0, uint32_t b1) {
    asm volatile(
        "mma.sync.aligned.m16n8k16.row.col.f32.f16.f16.f32 "
        "{%0,%1,%2,%3}, {%4,%5,%6,%7}, {%8,%9}, {%0,%1,%2,%3};"
        : "+f"(c[0]), "+f"(c[1]), "+f"(c[2]), "+f"(c[3])
        : "r"(a[0]), "r"(a[1]), "r"(a[2]), "r"(a[3]), "r"(b0), "r"(b1));
}

// swizzled 16B-chunk offset within an Rx64 fp16 tile (128B rows, 8-phase XOR)
__device__ __forceinline__ uint32_t tile_off(int row, int ch) {
    return (uint32_t)(row * 128 + ((ch ^ (row & 7)) << 4));
}

// ---------------------------------------------------------------------------
// Fold proj into a QK weight and write TRANSPOSED fp16 directly:
//   outT[(h*64+f)*DD + d] = fp16( sum_dh W[d, h*64+dh] * proj[dh, f] )
// grid (D/64, H), block 256
// ---------------------------------------------------------------------------
__global__ __launch_bounds__(256) void fold_kernel(const float* __restrict__ W,
                                                   const float* __restrict__ proj,
                                                   __half* __restrict__ outT)
{
    __shared__ float projS[64][64];
    __shared__ float wS[64][65];
    int d0 = blockIdx.x * 64, h = blockIdx.y;
    int tid = threadIdx.x;
    for (int i = tid; i < 64 * 64; i += 256)
        projS[i >> 6][i & 63] = proj[i];
    for (int i = tid; i < 64 * 64; i += 256)
        wS[i >> 6][i & 63] = W[(size_t)(d0 + (i >> 6)) * (HH * DH) + h * 64 + (i & 63)];
    __syncthreads();
    int r = tid >> 2;              // local d
    int fb = (tid & 3) * 16;       // f base
    float acc[16];
    #pragma unroll
    for (int i = 0; i < 16; i++) acc[i] = 0.f;
    #pragma unroll 8
    for (int c = 0; c < 64; c++) {
        float w = wS[r][c];
        #pragma unroll
        for (int i = 0; i < 16; i++)
            acc[i] = fmaf(w, projS[c][fb + i], acc[i]);
    }
    #pragma unroll
    for (int i = 0; i < 16; i++)
        outT[(size_t)(h * 64 + fb + i) * DD + d0 + r] = __float2half_rn(acc[i]);
}

// ---------------------------------------------------------------------------
// Weight transpose + fp16 convert:  W[K,N] -> Wt[N,K]
// ---------------------------------------------------------------------------
__global__ __launch_bounds__(256) void ts_kernel(const float* __restrict__ W,
                                                 __half* __restrict__ o,
                                                 int K, int N)
{
    __shared__ float t[32][33];
    int n0 = blockIdx.x * 32, k0 = blockIdx.y * 32;
    int tx = threadIdx.x & 31, ty = threadIdx.x >> 5;
    for (int r = ty; r < 32; r += 8)
        t[r][tx] = W[(size_t)(k0 + r) * N + n0 + tx];
    __syncthreads();
    for (int r = ty; r < 32; r += 8)
        o[(size_t)(n0 + r) * K + k0 + tx] = __float2half_rn(t[tx][r]);
}

// ---------------------------------------------------------------------------
// LayerNorm -> fp16. One block (256 thr) per row of 1024.
// ---------------------------------------------------------------------------
__global__ __launch_bounds__(256) void ln_kernel(const float* __restrict__ x,
                                                 const float* __restrict__ g,
                                                 const float* __restrict__ b,
                                                 __half* __restrict__ o)
{
    int row = blockIdx.x;
    int t = threadIdx.x;
    const float4* xr = reinterpret_cast<const float4*>(x + (size_t)row * DD);
    float4 xv = xr[t];

    float s  = xv.x + xv.y + xv.z + xv.w;
    float s2 = xv.x*xv.x + xv.y*xv.y + xv.z*xv.z + xv.w*xv.w;

    __shared__ float red[2][8];
    #pragma unroll
    for (int off = 16; off > 0; off >>= 1) {
        s  += __shfl_xor_sync(0xffffffffu, s,  off);
        s2 += __shfl_xor_sync(0xffffffffu, s2, off);
    }
    int w = t >> 5, l = t & 31;
    if (l == 0) { red[0][w] = s; red[1][w] = s2; }
    __syncthreads();
    __shared__ float smu, srstd;
    if (t == 0) {
        float ts = 0.f, ts2 = 0.f;
        #pragma unroll
        for (int i = 0; i < 8; i++) { ts += red[0][i]; ts2 += red[1][i]; }
        float mu = ts * (1.0f / DD);
        float var = ts2 * (1.0f / DD) - mu * mu;
        smu = mu;
        srstd = rsqrtf(var + 1e-5f);
    }
    __syncthreads();
    float mu = smu, rstd = srstd;

    const float4 gv = reinterpret_cast<const float4*>(g)[t];
    const float4 bv = reinterpret_cast<const float4*>(b)[t];
    float o0 = (xv.x - mu) * rstd * gv.x + bv.x;
    float o1 = (xv.y - mu) * rstd * gv.y + bv.y;
    float o2 = (xv.z - mu) * rstd * gv.z + bv.z;
    float o3 = (xv.w - mu) * rstd * gv.w + bv.w;
    size_t idx = (size_t)row * DD + t * 4;
    __half2 p0 = __halves2half2(__float2half_rn(o0), __float2half_rn(o1));
    __half2 p1 = __halves2half2(__float2half_rn(o2), __float2half_rn(o3));
    *reinterpret_cast<__half2*>(o + idx)     = p0;
    *reinterpret_cast<__half2*>(o + idx + 2) = p1;
}

// ---------------------------------------------------------------------------
// HMMA GEMM: 128x128 tile, BK=64, 3-stage cp.async pipeline, 256 threads,
// 2 CTAs/SM (96KB smem each), 2x4 warp grid, warp tile 64x32.
// mode 0: Cf = val
// mode 1: Cf = val + bias + residual
// mode 2: Ch = fp16(gelu(val + bias))
// mode 3: fused qkv (fp16 outs): seg0 relu+eps->Ch(q), seg1 relu+eps->kOut,
//         seg2 ->vOut  (out stride 1024)
// ---------------------------------------------------------------------------
#define STAGE_BYTES 32768
#define NSTAGE 3
#define GEMM_SMEM (NSTAGE * STAGE_BYTES)
#define GTHREADS 256

__device__ __forceinline__ void load_stage(
    uint32_t st, const char* A, const char* B,
    int K, int row0, int col0, int kc, int tid)
{
    size_t kb = (size_t)kc * 128;
    #pragma unroll
    for (int i = 0; i < 4; i++) {
        int id = tid + GTHREADS * i;
        int row = id >> 3, ch = id & 7;
        size_t ga = (size_t)(row0 + row) * K * 2 + kb + ch * 16;
        cp_async16(st + tile_off(row, ch), A + ga);
    }
    #pragma unroll
    for (int i = 0; i < 4; i++) {
        int id = tid + GTHREADS * i;
        int row = id >> 3, ch = id & 7;
        size_t gb = (size_t)(col0 + row) * K * 2 + kb + ch * 16;
        cp_async16(st + 16384 + tile_off(row, ch), B + gb);
    }
}

__global__ __launch_bounds__(GTHREADS, 2) void mma_gemm_kernel(
    const __half* __restrict__ A, const __half* __restrict__ B,
    int M, int N, int K,
    float* __restrict__ Cf, const float* __restrict__ bias,
    const float* __restrict__ residual,
    __half* __restrict__ Ch,
    __half* __restrict__ kOut, __half* __restrict__ vOut, int mode)
{
    extern __shared__ char smem[];
    uint32_t sbase = smem_u32(smem);

    int tid = threadIdx.x;
    int wid = tid >> 5, l = tid & 31;
    int wr = wid >> 2, wc = wid & 3;   // 2x4 warp grid: 64x32 per warp
    int row0 = blockIdx.y * 128;
    int col0 = blockIdx.x * 128;
    int CH = K >> 6;

    const char* pA = (const char*)A;
    const char* pB = (const char*)B;

    float acc[4][4][4];
    #pragma unroll
    for (int i = 0; i < 4; i++)
        #pragma unroll
        for (int j = 0; j < 4; j++)
            #pragma unroll
            for (int t = 0; t < 4; t++) acc[i][j][t] = 0.f;

    int aRow = wr * 64 + (l & 15);
    int aHalf = (l >> 4) & 1;
    int bRowL = (l & 7) + ((l >> 4) & 1) * 8;
    int bHalf = (l >> 3) & 1;

    load_stage(sbase,               pA, pB, K, row0, col0, 0, tid);
    cp_commit();
    load_stage(sbase + STAGE_BYTES, pA, pB, K, row0, col0, 1, tid);
    cp_commit();

    int sidx = 0;
    for (int c = 0; c < CH; c++) {
        cp_wait<1>();
        __syncthreads();
        int nc = c + 2 < CH ? c + 2 : CH - 1;
        int widx = sidx + 2; if (widx >= NSTAGE) widx -= NSTAGE;
        load_stage(sbase + widx * STAGE_BYTES, pA, pB, K, row0, col0, nc, tid);
        cp_commit();

        uint32_t st = sbase + sidx * STAGE_BYTES;
        #pragma unroll
        for (int ks = 0; ks < 4; ks++) {
            uint32_t af[4][4];
            #pragma unroll
            for (int mt = 0; mt < 4; mt++) {
                uint32_t off = tile_off(aRow + mt * 16, ks * 2 + aHalf);
                ldsm4(af[mt][0], af[mt][1], af[mt][2], af[mt][3], st + off);
            }
            uint32_t bf[4][2];
            #pragma unroll
            for (int p = 0; p < 2; p++) {
                uint32_t off = tile_off(wc * 32 + p * 16 + bRowL, ks * 2 + bHalf);
                ldsm4(bf[2*p][0], bf[2*p][1], bf[2*p+1][0], bf[2*p+1][1],
                      st + 16384 + off);
            }
            #pragma unroll
            for (int mt = 0; mt < 4; mt++)
                #pragma unroll
                for (int nt = 0; nt < 4; nt++)
                    mma16816(acc[mt][nt], af[mt], bf[nt][0], bf[nt][1]);
        }
        if (++sidx == NSTAGE) sidx = 0;
    }

    // epilogue
    int rb = row0 + wr * 64 + (l >> 2);
    int cb = col0 + wc * 32 + (l & 3) * 2;

    if (mode == 3) {
        int seg = col0 >> 10;
        __half* dst = (seg == 0) ? Ch : ((seg == 1) ? kOut : vOut);
        int csub = seg << 10;
        bool dorelu = (seg < 2);
        #pragma unroll
        for (int mt = 0; mt < 4; mt++)
            #pragma unroll
            for (int half = 0; half < 2; half++) {
                int r = rb + mt * 16 + half * 8;
                #pragma unroll
                for (int nt = 0; nt < 4; nt++) {
                    int ccol = cb + nt * 8 - csub;
                    float v0 = acc[mt][nt][half * 2];
                    float v1 = acc[mt][nt][half * 2 + 1];
                    if (dorelu) {
                        v0 = fmaxf(v0, 0.f) + 1e-6f;
                        v1 = fmaxf(v1, 0.f) + 1e-6f;
                    }
                    *reinterpret_cast<__half2*>(dst + (size_t)r * 1024 + ccol) =
                        __halves2half2(__float2half_rn(v0), __float2half_rn(v1));
                }
            }
        return;
    }

    #pragma unroll
    for (int mt = 0; mt < 4; mt++) {
        #pragma unroll
        for (int half = 0; half < 2; half++) {
            int r = rb + mt * 16 + half * 8;
            #pragma unroll
            for (int nt = 0; nt < 4; nt++) {
                int ccol = cb + nt * 8;
                float v0 = acc[mt][nt][half * 2];
                float v1 = acc[mt][nt][half * 2 + 1];
                if (mode == 2) {
                    v0 += bias[ccol];
                    v1 += bias[ccol + 1];
                    v0 = 0.5f * v0 * (1.0f + erff(v0 * 0.70710678118654752f));
                    v1 = 0.5f * v1 * (1.0f + erff(v1 * 0.70710678118654752f));
                    *reinterpret_cast<__half2*>(Ch + (size_t)r * N + ccol) =
                        __halves2half2(__float2half_rn(v0), __float2half_rn(v1));
                } else {
                    if (mode == 1) {
                        v0 += bias[ccol];
                        v1 += bias[ccol + 1];
                        const float2 rr = *reinterpret_cast<const float2*>(
                            residual + (size_t)r * N + ccol);
                        v0 += rr.x; v1 += rr.y;
                    }
                    float2 o; o.x = v0; o.y = v1;
                    *reinterpret_cast<float2*>(Cf + (size_t)r * N + ccol) = o;
                }
            }
        }
    }
}

// ---------------------------------------------------------------------------
// kv via tensor cores, K-split: grid (64 bh, 2 chunks of 2048 tokens).
// Writes fp32 partials kvp[chunk][bh][d][f].
// ---------------------------------------------------------------------------
#define KV_SMEM 65536
__global__ __launch_bounds__(128, 1) void kv_mma_kernel(
    const __half* __restrict__ kf, const __half* __restrict__ vv,
    float* __restrict__ kvp)
{
    extern __shared__ char smem[];
    uint32_t sb = smem_u32(smem);
    int bh = blockIdx.x;
    int chunk = blockIdx.y;
    int b = bh >> 4, h = bh & 15;
    int tid = threadIdx.x, w = tid >> 5, l = tid & 31;
    size_t gbase = (size_t)b * SS * DD + (size_t)h * 64
                 + (size_t)chunk * 2048 * DD;   // halfs

    float acc[4][8][4];
    #pragma unroll
    for (int i = 0; i < 4; i++)
        #pragma unroll
        for (int j = 0; j < 8; j++)
            #pragma unroll
            for (int t = 0; t < 4; t++) acc[i][j][t] = 0.f;

    int aTrow = ((l >> 4) & 1) * 8 + (l & 7);
    int aFoff = ((l >> 3) & 1) * 8;
    int bTrow = ((l >> 3) & 1) * 8 + (l & 7);
    int bDoff = ((l >> 4) & 1) * 8;

    auto load_tile = [&](int it) {
        uint32_t st = sb + (it & 1) * 16384;
        int t0 = it * 64;
        #pragma unroll
        for (int i = 0; i < 4; i++) {
            int id = tid + 128 * i;
            int row = id >> 3, ch = id & 7;
            size_t go = gbase + (size_t)(t0 + row) * DD + ch * 8;
            cp_async16(st + tile_off(row, ch),        (const char*)(kf + go));
            cp_async16(st + 8192 + tile_off(row, ch), (const char*)(vv + go));
        }
    };

    load_tile(0);
    cp_commit();

    for (int it = 0; it < 32; it++) {
        if (it < 31) { load_tile(it + 1); cp_commit(); cp_wait<1>(); }
        else cp_wait<0>();
        __syncthreads();
        uint32_t st = sb + (it & 1) * 16384;
        int t0w = w * 16;
        uint32_t af[4][4], bf[8][2];
        #pragma unroll
        for (int mt = 0; mt < 4; mt++) {
            int f0 = mt * 16 + aFoff;
            ldsm4t(af[mt][0], af[mt][1], af[mt][2], af[mt][3],
                   st + tile_off(t0w + aTrow, f0 >> 3));
        }
        #pragma unroll
        for (int p = 0; p < 4; p++) {
            int d0 = p * 16 + bDoff;
            uint32_t r0, r1, r2, r3;
            ldsm4t(r0, r1, r2, r3, st + 8192 + tile_off(t0w + bTrow, d0 >> 3));
            bf[2*p][0] = r0; bf[2*p][1] = r1;
            bf[2*p+1][0] = r2; bf[2*p+1][1] = r3;
        }
        #pragma unroll
        for (int mt = 0; mt < 4; mt++)
            #pragma unroll
            for (int nt = 0; nt < 8; nt++)
                mma16816(acc[mt][nt], af[mt], bf[nt][0], bf[nt][1]);
        __syncthreads();
    }

    // cross-warp reduce via smem: red[w][f][d]
    float* red = (float*)smem;
    #pragma unroll
    for (int mt = 0; mt < 4; mt++)
        #pragma unroll
        for (int half = 0; half < 2; half++) {
            int f = mt * 16 + half * 8 + (l >> 2);
            #pragma unroll
            for (int nt = 0; nt < 8; nt++) {
                int d = nt * 8 + (l & 3) * 2;
                red[w * 4096 + f * 64 + d]     = acc[mt][nt][half * 2];
                red[w * 4096 + f * 64 + d + 1] = acc[mt][nt][half * 2 + 1];
            }
        }
    __syncthreads();
    float* dst = kvp + (size_t)chunk * 64 * 4096 + (size_t)bh * 4096;
    for (int j = tid; j < 4096; j += 128) {
        int d = j >> 6, f = j & 63;
        int s = f * 64 + d;
        dst[j] = red[s] + red[4096 + s] + red[8192 + s] + red[12288 + s];
    }
}

// kvT[bh][j] = fp16(kvp[0][bh][j] + kvp[1][bh][j])
__global__ __launch_bounds__(256) void kv_reduce_kernel(const float* __restrict__ kvp,
                                                        __half* __restrict__ kvT)
{
    int i = blockIdx.x * 256 + threadIdx.x;
    kvT[i] = __float2half_rn(kvp[i] + kvp[64 * 4096 + i]);
}

// ---------------------------------------------------------------------------
// ksum[bh][f] = sum_t k[t][bh*64+f]   (grid 64, block 256: 4 token-slices)
// ---------------------------------------------------------------------------
__global__ __launch_bounds__(256) void ksum_kernel(const __half* __restrict__ kf,
                                                   float* __restrict__ ksum)
{
    __shared__ float part[4][64];
    int bh = blockIdx.x;
    int b = bh >> 4, h = bh & 15;
    int tid = threadIdx.x;
    int f = tid & 63, s = tid >> 6;
    size_t gbase = (size_t)b * SS * DD + (size_t)h * 64 + f;
    float acc = 0.f;
    for (int t = s * 1024; t < (s + 1) * 1024; t++)
        acc += __half2float(kf[gbase + (size_t)t * DD]);
    part[s][f] = acc;
    __syncthreads();
    if (tid < 64)
        ksum[bh * 64 + tid] = part[0][tid] + part[1][tid] + part[2][tid] + part[3][tid];
}

// ---------------------------------------------------------------------------
// attn via tensor cores: per (bh, 128-token tile):
//   num = q[128x64] @ kvT^T, den = q . ksum;  at = num/den (fp16)
// ---------------------------------------------------------------------------
__global__ __launch_bounds__(128) void attn_mma_kernel(
    const __half* __restrict__ qf, const __half* __restrict__ kvT,
    const float* __restrict__ ksum, __half* __restrict__ o)
{
    __shared__ __align__(16) char qs[128 * 128];
    __shared__ __align__(16) char kvs[64 * 128];
    __shared__ float sksum[64];
    __shared__ float sinv[128];

    int bh = blockIdx.x;
    int b = bh >> 4, h = bh & 15;
    int t0 = blockIdx.y * 128;
    int tid = threadIdx.x, w = tid >> 5, l = tid & 31;
    uint32_t qsb = smem_u32(qs), kvsb = smem_u32(kvs);
    size_t gbase = (size_t)b * SS * DD + (size_t)h * 64;

    #pragma unroll
    for (int i = 0; i < 8; i++) {
        int id = tid + 128 * i;
        int row = id >> 3, ch = id & 7;
        cp_async16(qsb + tile_off(row, ch),
                   (const char*)(qf + gbase + (size_t)(t0 + row) * DD + ch * 8));
    }
    #pragma unroll
    for (int i = 0; i < 4; i++) {
        int id = tid + 128 * i;
        int row = id >> 3, ch = id & 7;
        cp_async16(kvsb + tile_off(row, ch),
                   (const char*)(kvT + (size_t)bh * 4096 + row * 64 + ch * 8));
    }
    cp_commit();
    if (tid < 64) sksum[tid] = ksum[bh * 64 + tid];
    cp_wait<0>();
    __syncthreads();

    {
        float den = 0.f;
        #pragma unroll 8
        for (int f = 0; f < 64; f++) {
            __half qv = *reinterpret_cast<const __half*>(
                qs + tile_off(tid, f >> 3) + (f & 7) * 2);
            den = fmaf(__half2float(qv), sksum[f], den);
        }
        sinv[tid] = 1.0f / (den + 1e-6f);
    }
    __syncthreads();

    float acc[2][8][4];
    #pragma unroll
    for (int i = 0; i < 2; i++)
        #pragma unroll
        for (int j = 0; j < 8; j++)
            #pragma unroll
            for (int t = 0; t < 4; t++) acc[i][j][t] = 0.f;

    int aRow = w * 32 + (l & 15);
    int aHalf = (l >> 4) & 1;
    int bRowL = (l & 7) + ((l >> 4) & 1) * 8;
    int bHalf = (l >> 3) & 1;

    #pragma unroll
    for (int ks = 0; ks < 4; ks++) {
        uint32_t af[2][4], bf[8][2];
        #pragma unroll
        for (int mt = 0; mt < 2; mt++)
            ldsm4(af[mt][0], af[mt][1], af[mt][2], af[mt][3],
                  qsb + tile_off(aRow + mt * 16, ks * 2 + aHalf));
        #pragma unroll
        for (int p = 0; p < 4; p++)
            ldsm4(bf[2*p][0], bf[2*p][1], bf[2*p+1][0], bf[2*p+1][1],
                  kvsb + tile_off(p * 16 + bRowL, ks * 2 + bHalf));
        #pragma unroll
        for (int mt = 0; mt < 2; mt++)
            #pragma unroll
            for (int nt = 0; nt < 8; nt++)
                mma16816(acc[mt][nt], af[mt], bf[nt][0], bf[nt][1]);
    }

    #pragma unroll
    for (int mt = 0; mt < 2; mt++)
        #pragma unroll
        for (int half = 0; half < 2; half++) {
            int row = w * 32 + mt * 16 + half * 8 + (l >> 2);
            float inv = sinv[row];
            size_t obase = gbase + (size_t)(t0 + row) * DD;
            #pragma unroll
            for (int nt = 0; nt < 8; nt++) {
                int d = nt * 8 + (l & 3) * 2;
                float v0 = acc[mt][nt][half * 2] * inv;
                float v1 = acc[mt][nt][half * 2 + 1] * inv;
                *reinterpret_cast<__half2*>(o + obase + d) =
                    __halves2half2(__float2half_rn(v0), __float2half_rn(v1));
            }
        }
}

// ---------------------------------------------------------------------------
// Launch
// ---------------------------------------------------------------------------
extern "C" void kernel_launch(void* const* d_in, const int* in_sizes, int n_in,
                              void* d_out, int out_size)
{
    const float* x     = (const float*)d_in[0];
    const float* ln1_g = (const float*)d_in[1];
    const float* ln1_b = (const float*)d_in[2];
    const float* wq    = (const float*)d_in[3];
    const float* wk    = (const float*)d_in[4];
    const float* wv    = (const float*)d_in[5];
    const float* proj  = (const float*)d_in[6];
    const float* wo    = (const float*)d_in[7];
    const float* bo    = (const float*)d_in[8];
    const float* ln2_g = (const float*)d_in[9];
    const float* ln2_b = (const float*)d_in[10];
    const float* w1    = (const float*)d_in[11];
    const float* b1    = (const float*)d_in[12];
    const float* w2    = (const float*)d_in[13];
    const float* b2    = (const float*)d_in[14];
    float* out = (float*)d_out;

    float *qraw, *ksum, *kvp;
    __half *kbuf, *vbuf, *h, *at, *ffn, *wqkvT, *woT, *w1T, *w2T, *kvT;
    cudaGetSymbolAddress((void**)&qraw, g_q);
    cudaGetSymbolAddress((void**)&kbuf, g_kbuf);
    cudaGetSymbolAddress((void**)&vbuf, g_vbuf);
    cudaGetSymbolAddress((void**)&kvp, g_kvp);
    cudaGetSymbolAddress((void**)&kvT, g_kvT);
    cudaGetSymbolAddress((void**)&ksum, g_ksum);
    cudaGetSymbolAddress((void**)&h, g_h);
    cudaGetSymbolAddress((void**)&at, g_at);
    cudaGetSymbolAddress((void**)&ffn, g_ffn);
    cudaGetSymbolAddress((void**)&wqkvT, g_wqkvT);
    cudaGetSymbolAddress((void**)&woT, g_woT);
    cudaGetSymbolAddress((void**)&w1T, g_w1T);
    cudaGetSymbolAddress((void**)&w2T, g_w2T);
    __half* qbuf = (__half*)qraw;   // fp16 q view (front 32MB of 64MB buffer)

    cudaFuncSetAttribute(mma_gemm_kernel,
                         cudaFuncAttributeMaxDynamicSharedMemorySize, GEMM_SMEM);
    cudaFuncSetAttribute(kv_mma_kernel,
                         cudaFuncAttributeMaxDynamicSharedMemorySize, KV_SMEM);

    // --- weight prep (fold writes transposed fp16 directly) ---
    fold_kernel<<<dim3(DD / 64, HH), 256>>>(wq, proj, wqkvT);
    fold_kernel<<<dim3(DD / 64, HH), 256>>>(wk, proj, wqkvT + 1024 * 1024);
    ts_kernel<<<dim3(DD / 32, DD / 32), 256>>>(wv, wqkvT + 2048 * 1024, DD, DD);
    ts_kernel<<<dim3(DD / 32, DD / 32), 256>>>(wo, woT, DD, DD);
    ts_kernel<<<dim3(DFF / 32, DD / 32), 256>>>(w1, w1T, DD, DFF);
    ts_kernel<<<dim3(DD / 32, DFF / 32), 256>>>(w2, w2T, DFF, DD);

    // LN1 -> h (fp16)
    ln_kernel<<<NTOK, 256>>>(x, ln1_g, ln1_b, h);

    // Fused QKV GEMM: N=3072 -> q (relu+eps), k (relu+eps), v  (all fp16)
    dim3 gQKV(3072 / 128, NTOK / 128);
    mma_gemm_kernel<<<gQKV, GTHREADS, GEMM_SMEM>>>(h, wqkvT,
        NTOK, 3072, DD, nullptr, nullptr, nullptr, qbuf, kbuf, vbuf, 3);

    // kv (tensor cores, K-split) + reduce + ksum
    kv_mma_kernel<<<dim3(64, 2), 128, KV_SMEM>>>(kbuf, vbuf, kvp);
    ksum_kernel<<<64, 256>>>(kbuf, ksum);
    kv_reduce_kernel<<<64 * 4096 / 256, 256>>>(kvp, kvT);

    // attn (tensor cores) -> fp16
    attn_mma_kernel<<<dim3(64, SS / 128), 128>>>(qbuf, kvT, ksum, at);

    // x2 = x + attn @ wo + bo -> out (fp32)
    dim3 gD(DD / 128, NTOK / 128);
    mma_gemm_kernel<<<gD, GTHREADS, GEMM_SMEM>>>(at, woT,
        NTOK, DD, DD, out, bo, x, nullptr, nullptr, nullptr, 1);

    // LN2 -> h (fp16)
    ln_kernel<<<NTOK, 256>>>(out, ln2_g, ln2_b, h);

    // ffn = gelu(h2 @ w1 + b1) -> fp16
    dim3 gF1(DFF / 128, NTOK / 128);
    mma_gemm_kernel<<<gF1, GTHREADS, GEMM_SMEM>>>(h, w1T,
        NTOK, DFF, DD, nullptr, b1, nullptr, ffn, nullptr, nullptr, 2);

    // out = x2 + ffn @ w2 + b2 (in-place residual)
    mma_gemm_kernel<<<gD, GTHREADS, GEMM_SMEM>>>(ffn, w2T,
        NTOK, DD, DFF, out, b2, out, nullptr, nullptr, nullptr, 1);
}